// round 3
// baseline (speedup 1.0000x reference)
#include <cuda_runtime.h>
#include <cstdint>

// Problem constants
#define Nn     50000
#define Dd     64
#define Ee     800000
#define Bb     50
#define NMAXx  1000
#define Cc     100

// ---------------------------------------------------------------------------
// Device scratch (no allocations allowed)
// ---------------------------------------------------------------------------
__device__ float g_xa[Nn * Dd];          // x @ W_ma[:64] + b_ma
__device__ float g_acc[Nn * Dd];         // (1+eps1)*x + segment_sum(msg)
__device__ float g_up[Nn * Dd];          // einsum result (flat [B*NMAX, D])
__device__ float g_msgup[Bb * Cc * Dd];  // relu(attr1 @ W_mu + b_mu)

// counting sort by dst
__device__ int g_cnt[Nn];
__device__ int g_off[Nn];
__device__ int g_eid[Ee];                // sorted-order -> original edge id
__device__ int g_src_s[Ee];              // src in sorted order
__device__ int g_dst_s[Ee];              // dst in sorted order

// W_ma[64:128] with每 value duplicated as pairs: g_W2d[k*128 + 2j(+1)] = W_ma[64+k][j]
__device__ float g_W2d[64 * 128];

// ---------------------------------------------------------------------------
// f32x2 packed helpers
// ---------------------------------------------------------------------------
__device__ __forceinline__ void fma2(unsigned long long& d,
                                     unsigned long long a,
                                     unsigned long long b) {
    asm("fma.rn.f32x2 %0, %1, %2, %0;" : "+l"(d) : "l"(a), "l"(b));
}
__device__ __forceinline__ float2 unpack2(unsigned long long v) {
    float2 r;
    asm("mov.b64 {%0, %1}, %2;" : "=f"(r.x), "=f"(r.y) : "l"(v));
    return r;
}

// ---------------------------------------------------------------------------
// Counting sort kernels
// ---------------------------------------------------------------------------
__global__ void k_zero_cnt() {
    int i = blockIdx.x * 256 + threadIdx.x;
    if (i < Nn) g_cnt[i] = 0;
}
__global__ void k_hist(const int* __restrict__ ei) {
    int i = blockIdx.x * 256 + threadIdx.x;
    if (i < Ee) atomicAdd(&g_cnt[ei[Ee + i]], 1);
}
__global__ __launch_bounds__(1024) void k_scan() {
    __shared__ int part[1024];
    const int t = threadIdx.x;
    const int CH = 49;  // 1024*49 = 50176 >= 50000
    int base = t * CH;
    int s = 0;
    for (int i = 0; i < CH; i++) {
        int idx = base + i;
        if (idx < Nn) s += g_cnt[idx];
    }
    part[t] = s;
    __syncthreads();
    for (int off = 1; off < 1024; off <<= 1) {
        int v = (t >= off) ? part[t - off] : 0;
        __syncthreads();
        part[t] += v;
        __syncthreads();
    }
    int run = (t > 0) ? part[t - 1] : 0;
    for (int i = 0; i < CH; i++) {
        int idx = base + i;
        if (idx < Nn) {
            g_off[idx] = run;
            run += g_cnt[idx];
        }
    }
}
__global__ void k_scatter(const int* __restrict__ ei) {
    int i = blockIdx.x * 256 + threadIdx.x;
    if (i < Ee) {
        int s = ei[i];
        int d = ei[Ee + i];
        int pos = atomicAdd(&g_off[d], 1);
        g_eid[pos] = i;
        g_src_s[pos] = s;
        g_dst_s[pos] = d;
    }
}

// ---------------------------------------------------------------------------
// Precompute duplicated W2: g_W2d[k][2j] = g_W2d[k][2j+1] = W_ma[64+k][j]
// ---------------------------------------------------------------------------
__global__ void k_prep_w2(const float* __restrict__ W_ma) {
    int i = blockIdx.x * 256 + threadIdx.x;
    if (i >= 64 * 64) return;
    int k = i >> 6, j = i & 63;
    float w = W_ma[(64 + k) * 64 + j];
    g_W2d[k * 128 + 2 * j]     = w;
    g_W2d[k * 128 + 2 * j + 1] = w;
}

// ---------------------------------------------------------------------------
// Kernel 1: g_xa = x @ W_ma[0:64] + b_ma ;  g_acc = (1+eps1)*x
// ---------------------------------------------------------------------------
__global__ __launch_bounds__(256) void k_node_pre(
    const float* __restrict__ x, const float* __restrict__ W_ma,
    const float* __restrict__ b_ma, const float* __restrict__ eps1)
{
    __shared__ float Xs[64 * 68];
    __shared__ float Ws[64 * 68];
    __shared__ float bs[64];
    const int t = threadIdx.x;
    const int row0 = blockIdx.x * 64;

    for (int i = t; i < 64 * 16; i += 256) {
        int k = i / 16, c = (i % 16) * 4;
        *(float4*)(Ws + k * 68 + c) = *(const float4*)(W_ma + k * 64 + c);
    }
    if (t < 64) bs[t] = b_ma[t];
    for (int i = t; i < 64 * 16; i += 256) {
        int r = i / 16, c = (i % 16) * 4;
        int gr = row0 + r;
        float4 v = make_float4(0.f, 0.f, 0.f, 0.f);
        if (gr < Nn) v = *(const float4*)(x + gr * 64 + c);
        *(float4*)(Xs + r * 68 + c) = v;
    }
    __syncthreads();

    const int r0 = (t / 16) * 4, c0 = (t % 16) * 4;
    float acc[4][4];
#pragma unroll
    for (int i = 0; i < 4; i++)
#pragma unroll
        for (int j = 0; j < 4; j++) acc[i][j] = 0.f;

#pragma unroll
    for (int k = 0; k < 64; k += 4) {
        float4 a4[4];
#pragma unroll
        for (int i = 0; i < 4; i++) a4[i] = *(float4*)(Xs + (r0 + i) * 68 + k);
#pragma unroll
        for (int kk = 0; kk < 4; kk++) {
            float4 b4 = *(float4*)(Ws + (k + kk) * 68 + c0);
#pragma unroll
            for (int i = 0; i < 4; i++) {
                float a = ((const float*)&a4[i])[kk];
                acc[i][0] += a * b4.x; acc[i][1] += a * b4.y;
                acc[i][2] += a * b4.z; acc[i][3] += a * b4.w;
            }
        }
    }

    const float e1 = 1.0f + eps1[0];
#pragma unroll
    for (int i = 0; i < 4; i++) {
        int gr = row0 + r0 + i;
        if (gr < Nn) {
            float4 o;
            o.x = acc[i][0] + bs[c0 + 0];
            o.y = acc[i][1] + bs[c0 + 1];
            o.z = acc[i][2] + bs[c0 + 2];
            o.w = acc[i][3] + bs[c0 + 3];
            *(float4*)(g_xa + gr * 64 + c0) = o;
            float4 xv = *(float4*)(Xs + (r0 + i) * 68 + c0);
            float4 av = make_float4(e1 * xv.x, e1 * xv.y, e1 * xv.z, e1 * xv.w);
            *(float4*)(g_acc + gr * 64 + c0) = av;
        }
    }
}

// ---------------------------------------------------------------------------
// Kernel 2: g_msgup = relu(attr1 @ W_mu + b_mu)
// ---------------------------------------------------------------------------
__global__ __launch_bounds__(256) void k_mlp_up(
    const float* __restrict__ attr1, const float* __restrict__ W_mu,
    const float* __restrict__ b_mu)
{
    __shared__ float As[64 * 68];
    __shared__ float Ws[64 * 68];
    __shared__ float bs[64];
    const int t = threadIdx.x;
    const int row0 = blockIdx.x * 64;
    const int M = Bb * Cc;

    for (int i = t; i < 64 * 16; i += 256) {
        int k = i / 16, c = (i % 16) * 4;
        *(float4*)(Ws + k * 68 + c) = *(const float4*)(W_mu + k * 64 + c);
    }
    if (t < 64) bs[t] = b_mu[t];
    for (int i = t; i < 64 * 16; i += 256) {
        int r = i / 16, c = (i % 16) * 4;
        int gr = row0 + r;
        float4 v = make_float4(0.f, 0.f, 0.f, 0.f);
        if (gr < M) v = *(const float4*)(attr1 + gr * 64 + c);
        *(float4*)(As + r * 68 + c) = v;
    }
    __syncthreads();

    const int r0 = (t / 16) * 4, c0 = (t % 16) * 4;
    float acc[4][4];
#pragma unroll
    for (int i = 0; i < 4; i++)
#pragma unroll
        for (int j = 0; j < 4; j++) acc[i][j] = 0.f;

#pragma unroll
    for (int k = 0; k < 64; k += 4) {
        float4 a4[4];
#pragma unroll
        for (int i = 0; i < 4; i++) a4[i] = *(float4*)(As + (r0 + i) * 68 + k);
#pragma unroll
        for (int kk = 0; kk < 4; kk++) {
            float4 b4 = *(float4*)(Ws + (k + kk) * 68 + c0);
#pragma unroll
            for (int i = 0; i < 4; i++) {
                float a = ((const float*)&a4[i])[kk];
                acc[i][0] += a * b4.x; acc[i][1] += a * b4.y;
                acc[i][2] += a * b4.z; acc[i][3] += a * b4.w;
            }
        }
    }

#pragma unroll
    for (int i = 0; i < 4; i++) {
        int gr = row0 + r0 + i;
        if (gr < M) {
            float4 o;
            o.x = fmaxf(acc[i][0] + bs[c0 + 0], 0.f);
            o.y = fmaxf(acc[i][1] + bs[c0 + 1], 0.f);
            o.z = fmaxf(acc[i][2] + bs[c0 + 2], 0.f);
            o.w = fmaxf(acc[i][3] + bs[c0 + 3], 0.f);
            *(float4*)(g_msgup + gr * 64 + c0) = o;
        }
    }
}

// ---------------------------------------------------------------------------
// Kernel 3: g_up[b,n,:] = sum_c nc1[b,n,c] * g_msgup[b,c,:]
// ---------------------------------------------------------------------------
__global__ __launch_bounds__(256) void k_upagg(const float* __restrict__ nc1)
{
    extern __shared__ float sm[];
    float* Ns = sm;              // 64 x 104
    float* Ms = sm + 64 * 104;   // 100 x 68
    const int t = threadIdx.x;
    const int b = blockIdx.y;
    const int row0 = blockIdx.x * 64;

    for (int i = t; i < 64 * 25; i += 256) {
        int r = i / 25, c = (i % 25) * 4;
        int gr = row0 + r;
        float4 v = make_float4(0.f, 0.f, 0.f, 0.f);
        if (gr < NMAXx)
            v = *(const float4*)(nc1 + ((size_t)b * NMAXx + gr) * Cc + c);
        *(float4*)(Ns + r * 104 + c) = v;
    }
    for (int i = t; i < 100 * 16; i += 256) {
        int r = i / 16, c = (i % 16) * 4;
        *(float4*)(Ms + r * 68 + c) =
            *(const float4*)(g_msgup + ((size_t)b * Cc + r) * 64 + c);
    }
    __syncthreads();

    const int r0 = (t / 16) * 4, c0 = (t % 16) * 4;
    float acc[4][4];
#pragma unroll
    for (int i = 0; i < 4; i++)
#pragma unroll
        for (int j = 0; j < 4; j++) acc[i][j] = 0.f;

#pragma unroll
    for (int k = 0; k < 100; k += 4) {
        float4 a4[4];
#pragma unroll
        for (int i = 0; i < 4; i++) a4[i] = *(float4*)(Ns + (r0 + i) * 104 + k);
#pragma unroll
        for (int kk = 0; kk < 4; kk++) {
            float4 b4 = *(float4*)(Ms + (k + kk) * 68 + c0);
#pragma unroll
            for (int i = 0; i < 4; i++) {
                float a = ((const float*)&a4[i])[kk];
                acc[i][0] += a * b4.x; acc[i][1] += a * b4.y;
                acc[i][2] += a * b4.z; acc[i][3] += a * b4.w;
            }
        }
    }

#pragma unroll
    for (int i = 0; i < 4; i++) {
        int gr = row0 + r0 + i;
        if (gr < NMAXx) {
            float4 o = make_float4(acc[i][0], acc[i][1], acc[i][2], acc[i][3]);
            *(float4*)(g_up + ((size_t)b * NMAXx + gr) * 64 + c0) = o;
        }
    }
}

// ---------------------------------------------------------------------------
// Kernel 4: f32x2 edge kernel over dst-sorted edges.
// Tile: 128 edges x 64 cols, 256 threads, per-thread 8 rows x 4 cols,
// packed as 4 rowpairs x 4 cols of f32x2 accumulators.
// A transposed in smem (k-major, pairs along rows), W duplicated pairs.
// Epilogue: run-coalesced atomics by sorted dst.
// ---------------------------------------------------------------------------
#define EST_S 130             // floats per k-row of EsT (even -> 8B-aligned pairs)
#define SM_EST 1024           // byte offset of EsT (64 * 130 floats)
#define SM_W2  34304          // byte offset of Ws2 (64 * 128 floats)
#define SM_EDGE_TOTAL (34304 + 64 * 128 * 4)   // 67072

__global__ __launch_bounds__(256) void k_edge_f2(const float* __restrict__ e)
{
    extern __shared__ char smraw[];
    int*   sd  = (int*)smraw;                 // [128]
    int*   ss  = (int*)(smraw + 512);         // [128]
    float* EsT = (float*)(smraw + SM_EST);    // [64][EST_S]
    float* Ws2 = (float*)(smraw + SM_W2);     // [64][128]

    const int t  = threadIdx.x;
    const int e0 = blockIdx.x * 128;

    if (t < 128) {
        sd[t] = g_dst_s[e0 + t];
        ss[t] = g_src_s[e0 + t];
    }

    // W duplicated pairs: linear copy 32KB
    {
        const float4* src = (const float4*)g_W2d;
        float4* dst = (float4*)Ws2;
#pragma unroll
        for (int i = t; i < 64 * 128 / 4; i += 256) dst[i] = src[i];
    }

    // Gather A rows in sorted order, store transposed (k-major).
    // i = r*16 + q: 16 lanes share a row -> coalesced 256B row reads.
#pragma unroll
    for (int i = t; i < 128 * 16; i += 256) {
        int r = i >> 4, q = i & 15;
        int eid = g_eid[e0 + r];
        float4 v = *(const float4*)(e + (size_t)eid * 64 + q * 4);
        int k = q * 4;
        EsT[(k + 0) * EST_S + r] = v.x;
        EsT[(k + 1) * EST_S + r] = v.y;
        EsT[(k + 2) * EST_S + r] = v.z;
        EsT[(k + 3) * EST_S + r] = v.w;
    }
    __syncthreads();

    const int r0 = (t / 16) * 8;      // 8 sorted rows
    const int c0 = (t % 16) * 4;      // 4 cols

    unsigned long long acc[4][4];     // [rowpair][col]
#pragma unroll
    for (int p = 0; p < 4; p++)
#pragma unroll
        for (int j = 0; j < 4; j++) acc[p][j] = 0ull;

#pragma unroll 8
    for (int k = 0; k < 64; k++) {
        const float* At = EsT + k * EST_S + r0;
        unsigned long long a0 = *(const unsigned long long*)(At + 0);
        unsigned long long a1 = *(const unsigned long long*)(At + 2);
        unsigned long long a2 = *(const unsigned long long*)(At + 4);
        unsigned long long a3 = *(const unsigned long long*)(At + 6);
        const float* Bt = Ws2 + k * 128 + 2 * c0;
        ulonglong2 bp0 = *(const ulonglong2*)(Bt);      // dup pairs cols c0, c0+1
        ulonglong2 bp1 = *(const ulonglong2*)(Bt + 4);  // dup pairs cols c0+2, c0+3
        fma2(acc[0][0], a0, bp0.x); fma2(acc[0][1], a0, bp0.y);
        fma2(acc[0][2], a0, bp1.x); fma2(acc[0][3], a0, bp1.y);
        fma2(acc[1][0], a1, bp0.x); fma2(acc[1][1], a1, bp0.y);
        fma2(acc[1][2], a1, bp1.x); fma2(acc[1][3], a1, bp1.y);
        fma2(acc[2][0], a2, bp0.x); fma2(acc[2][1], a2, bp0.y);
        fma2(acc[2][2], a2, bp1.x); fma2(acc[2][3], a2, bp1.y);
        fma2(acc[3][0], a3, bp0.x); fma2(acc[3][1], a3, bp0.y);
        fma2(acc[3][2], a3, bp1.x); fma2(acc[3][3], a3, bp1.y);
    }

    // Epilogue: walk the 8 sorted rows, coalesce atomics over equal-dst runs.
    {
        int cur_d = sd[r0];
        float s0 = 0.f, s1 = 0.f, s2 = 0.f, s3 = 0.f;
#pragma unroll
        for (int i = 0; i < 8; i++) {
            int row = r0 + i;
            int d = sd[row];
            int s = ss[row];
            float4 xa = *(const float4*)(g_xa + (size_t)s * 64 + c0);
            float2 p0 = unpack2(acc[i >> 1][0]);
            float2 p1 = unpack2(acc[i >> 1][1]);
            float2 p2 = unpack2(acc[i >> 1][2]);
            float2 p3 = unpack2(acc[i >> 1][3]);
            float v0 = (i & 1) ? p0.y : p0.x;
            float v1 = (i & 1) ? p1.y : p1.x;
            float v2 = (i & 1) ? p2.y : p2.x;
            float v3 = (i & 1) ? p3.y : p3.x;
            float m0 = fmaxf(v0 + xa.x, 0.f);
            float m1 = fmaxf(v1 + xa.y, 0.f);
            float m2 = fmaxf(v2 + xa.z, 0.f);
            float m3 = fmaxf(v3 + xa.w, 0.f);
            if (d != cur_d) {
                float* dp = g_acc + (size_t)cur_d * 64 + c0;
                atomicAdd(dp + 0, s0);
                atomicAdd(dp + 1, s1);
                atomicAdd(dp + 2, s2);
                atomicAdd(dp + 3, s3);
                s0 = s1 = s2 = s3 = 0.f;
                cur_d = d;
            }
            s0 += m0; s1 += m1; s2 += m2; s3 += m3;
        }
        float* dp = g_acc + (size_t)cur_d * 64 + c0;
        atomicAdd(dp + 0, s0);
        atomicAdd(dp + 1, s1);
        atomicAdd(dp + 2, s2);
        atomicAdd(dp + 3, s3);
    }
}

// ---------------------------------------------------------------------------
// Kernel 5 (fused tail): h1 = relu(g_acc @ W_ua + b_ua);
// h2 = relu((g_up[x_idx] + (1+eps2)*x) @ W_uu + b_uu);
// out = h1 @ W_c[0:64] + h2 @ W_c[64:128] + b_c
// ---------------------------------------------------------------------------
__global__ __launch_bounds__(256) void k_final(
    const float* __restrict__ x, const int* __restrict__ x_idx,
    const float* __restrict__ eps2,
    const float* __restrict__ W_ua, const float* __restrict__ b_ua,
    const float* __restrict__ W_uu, const float* __restrict__ b_uu,
    const float* __restrict__ W_c, const float* __restrict__ b_c,
    float* __restrict__ out)
{
    extern __shared__ float sm[];
    float* A1  = sm;
    float* A2  = A1 + 64 * 68;
    float* Wua = A2 + 64 * 68;
    float* Wuu = Wua + 64 * 68;
    float* Wc1 = Wuu + 64 * 68;
    float* Wc2 = Wc1 + 64 * 68;
    __shared__ float bua[64], buu[64], bcs[64];

    const int t = threadIdx.x;
    const int row0 = blockIdx.x * 64;
    const float e2 = 1.0f + eps2[0];

    for (int i = t; i < 64 * 16; i += 256) {
        int k = i / 16, c = (i % 16) * 4;
        *(float4*)(Wua + k * 68 + c) = *(const float4*)(W_ua + k * 64 + c);
        *(float4*)(Wuu + k * 68 + c) = *(const float4*)(W_uu + k * 64 + c);
        *(float4*)(Wc1 + k * 68 + c) = *(const float4*)(W_c + k * 64 + c);
        *(float4*)(Wc2 + k * 68 + c) = *(const float4*)(W_c + (64 + k) * 64 + c);
    }
    if (t < 64) { bua[t] = b_ua[t]; buu[t] = b_uu[t]; bcs[t] = b_c[t]; }

    for (int i = t; i < 64 * 16; i += 256) {
        int r = i / 16, c = (i % 16) * 4;
        int gr = row0 + r;
        float4 a1 = make_float4(0.f, 0.f, 0.f, 0.f);
        float4 a2 = make_float4(0.f, 0.f, 0.f, 0.f);
        if (gr < Nn) {
            a1 = *(const float4*)(g_acc + (size_t)gr * 64 + c);
            int xi = x_idx[gr];
            float4 u  = *(const float4*)(g_up + (size_t)xi * 64 + c);
            float4 xv = *(const float4*)(x + (size_t)gr * 64 + c);
            a2 = make_float4(u.x + e2 * xv.x, u.y + e2 * xv.y,
                             u.z + e2 * xv.z, u.w + e2 * xv.w);
        }
        *(float4*)(A1 + r * 68 + c) = a1;
        *(float4*)(A2 + r * 68 + c) = a2;
    }
    __syncthreads();

    const int r0 = (t / 16) * 4, c0 = (t % 16) * 4;
    float h1[4][4], h2[4][4];
#pragma unroll
    for (int i = 0; i < 4; i++)
#pragma unroll
        for (int j = 0; j < 4; j++) { h1[i][j] = 0.f; h2[i][j] = 0.f; }

#pragma unroll
    for (int k = 0; k < 64; k += 4) {
        float4 a14[4], a24[4];
#pragma unroll
        for (int i = 0; i < 4; i++) {
            a14[i] = *(float4*)(A1 + (r0 + i) * 68 + k);
            a24[i] = *(float4*)(A2 + (r0 + i) * 68 + k);
        }
#pragma unroll
        for (int kk = 0; kk < 4; kk++) {
            float4 b1 = *(float4*)(Wua + (k + kk) * 68 + c0);
            float4 b2 = *(float4*)(Wuu + (k + kk) * 68 + c0);
#pragma unroll
            for (int i = 0; i < 4; i++) {
                float a = ((const float*)&a14[i])[kk];
                float b = ((const float*)&a24[i])[kk];
                h1[i][0] += a * b1.x; h1[i][1] += a * b1.y;
                h1[i][2] += a * b1.z; h1[i][3] += a * b1.w;
                h2[i][0] += b * b2.x; h2[i][1] += b * b2.y;
                h2[i][2] += b * b2.z; h2[i][3] += b * b2.w;
            }
        }
    }
#pragma unroll
    for (int i = 0; i < 4; i++)
#pragma unroll
        for (int j = 0; j < 4; j++) {
            h1[i][j] = fmaxf(h1[i][j] + bua[c0 + j], 0.f);
            h2[i][j] = fmaxf(h2[i][j] + buu[c0 + j], 0.f);
        }
    __syncthreads();
#pragma unroll
    for (int i = 0; i < 4; i++)
#pragma unroll
        for (int j = 0; j < 4; j++) {
            A1[(r0 + i) * 68 + c0 + j] = h1[i][j];
            A2[(r0 + i) * 68 + c0 + j] = h2[i][j];
        }
    __syncthreads();

    float o[4][4];
#pragma unroll
    for (int i = 0; i < 4; i++)
#pragma unroll
        for (int j = 0; j < 4; j++) o[i][j] = 0.f;

#pragma unroll
    for (int k = 0; k < 64; k += 4) {
        float4 a14[4], a24[4];
#pragma unroll
        for (int i = 0; i < 4; i++) {
            a14[i] = *(float4*)(A1 + (r0 + i) * 68 + k);
            a24[i] = *(float4*)(A2 + (r0 + i) * 68 + k);
        }
#pragma unroll
        for (int kk = 0; kk < 4; kk++) {
            float4 b1 = *(float4*)(Wc1 + (k + kk) * 68 + c0);
            float4 b2 = *(float4*)(Wc2 + (k + kk) * 68 + c0);
#pragma unroll
            for (int i = 0; i < 4; i++) {
                float a = ((const float*)&a14[i])[kk];
                float b = ((const float*)&a24[i])[kk];
                o[i][0] += a * b1.x + b * b2.x;
                o[i][1] += a * b1.y + b * b2.y;
                o[i][2] += a * b1.z + b * b2.z;
                o[i][3] += a * b1.w + b * b2.w;
            }
        }
    }

#pragma unroll
    for (int i = 0; i < 4; i++) {
        int gr = row0 + r0 + i;
        if (gr < Nn) {
            float4 ov;
            ov.x = o[i][0] + bcs[c0 + 0];
            ov.y = o[i][1] + bcs[c0 + 1];
            ov.z = o[i][2] + bcs[c0 + 2];
            ov.w = o[i][3] + bcs[c0 + 3];
            *(float4*)(out + (size_t)gr * 64 + c0) = ov;
        }
    }
}

// ---------------------------------------------------------------------------
extern "C" void kernel_launch(void* const* d_in, const int* in_sizes, int n_in,
                              void* d_out, int out_size)
{
    const float* x     = (const float*)d_in[0];
    const float* e     = (const float*)d_in[1];
    const int*   ei    = (const int*)d_in[2];
    const float* attr1 = (const float*)d_in[3];
    const float* nc1   = (const float*)d_in[4];
    const int*   x_idx = (const int*)d_in[5];
    const float* eps1  = (const float*)d_in[6];
    const float* eps2  = (const float*)d_in[7];
    const float* W_ma  = (const float*)d_in[8];
    const float* b_ma  = (const float*)d_in[9];
    const float* W_mu  = (const float*)d_in[10];
    const float* b_mu  = (const float*)d_in[11];
    const float* W_ua  = (const float*)d_in[12];
    const float* b_ua  = (const float*)d_in[13];
    const float* W_uu  = (const float*)d_in[14];
    const float* b_uu  = (const float*)d_in[15];
    const float* W_c   = (const float*)d_in[16];
    const float* b_c   = (const float*)d_in[17];
    float* out = (float*)d_out;

    const int SMEM_UP  = (64 * 104 + 100 * 68) * 4;
    const int SMEM_FIN = (6 * 64 * 68) * 4;

    cudaFuncSetAttribute(k_upagg,   cudaFuncAttributeMaxDynamicSharedMemorySize, SMEM_UP);
    cudaFuncSetAttribute(k_edge_f2, cudaFuncAttributeMaxDynamicSharedMemorySize, SM_EDGE_TOTAL);
    cudaFuncSetAttribute(k_final,   cudaFuncAttributeMaxDynamicSharedMemorySize, SMEM_FIN);

    // counting sort of edges by dst
    k_zero_cnt<<<(Nn + 255) / 256, 256>>>();
    k_hist<<<(Ee + 255) / 256, 256>>>(ei);
    k_scan<<<1, 1024>>>();
    k_scatter<<<(Ee + 255) / 256, 256>>>(ei);

    // weight prep + node branches
    k_prep_w2<<<(64 * 64 + 255) / 256, 256>>>(W_ma);
    k_node_pre<<<(Nn + 63) / 64, 256>>>(x, W_ma, b_ma, eps1);
    k_mlp_up<<<(Bb * Cc + 63) / 64, 256>>>(attr1, W_mu, b_mu);
    k_upagg<<<dim3((NMAXx + 63) / 64, Bb), 256, SMEM_UP>>>(nc1);

    // f32x2 edge kernel over sorted edges
    k_edge_f2<<<Ee / 128, 256, SM_EDGE_TOTAL>>>(e);

    // fused tail
    k_final<<<(Nn + 63) / 64, 256, SMEM_FIN>>>(x, x_idx, eps2, W_ua, b_ua,
                                               W_uu, b_uu, W_c, b_c, out);
}

// round 5
// speedup vs baseline: 1.0874x; 1.0874x over previous
#include <cuda_runtime.h>
#include <cstdint>

// Problem constants
#define Nn     50000
#define Dd     64
#define Ee     800000
#define Bb     50
#define NMAXx  1000
#define Cc     100

// ---------------------------------------------------------------------------
// Device scratch (no allocations allowed)
// ---------------------------------------------------------------------------
__device__ float g_xa[Nn * Dd];          // x @ W_ma[:64] + b_ma
__device__ float g_acc[Nn * Dd];         // (1+eps1)*x + segment_sum(msg)
__device__ float g_up[Nn * Dd];          // einsum result (flat [B*NMAX, D])
__device__ float g_msgup[Bb * Cc * Dd];  // relu(attr1 @ W_mu + b_mu)

// W_ma[64:128] duplicated as pairs: g_W2d[k*128 + 2j(+1)] = W_ma[64+k][j]
__device__ float g_W2d[64 * 128];

// ---------------------------------------------------------------------------
// f32x2 packed helpers + vector red
// ---------------------------------------------------------------------------
__device__ __forceinline__ void fma2(unsigned long long& d,
                                     unsigned long long a,
                                     unsigned long long b) {
    asm("fma.rn.f32x2 %0, %1, %2, %0;" : "+l"(d) : "l"(a), "l"(b));
}
__device__ __forceinline__ float2 unpack2(unsigned long long v) {
    float2 r;
    asm("mov.b64 {%0, %1}, %2;" : "=f"(r.x), "=f"(r.y) : "l"(v));
    return r;
}
__device__ __forceinline__ void red_add_v4(float* p, float a, float b,
                                           float c, float d) {
    asm volatile("red.global.add.v4.f32 [%0], {%1, %2, %3, %4};"
                 :: "l"(p), "f"(a), "f"(b), "f"(c), "f"(d) : "memory");
}

// ---------------------------------------------------------------------------
// Precompute duplicated W2: g_W2d[k][2j] = g_W2d[k][2j+1] = W_ma[64+k][j]
// ---------------------------------------------------------------------------
__global__ void k_prep_w2(const float* __restrict__ W_ma) {
    int i = blockIdx.x * 256 + threadIdx.x;
    if (i >= 64 * 64) return;
    int k = i >> 6, j = i & 63;
    float w = W_ma[(64 + k) * 64 + j];
    g_W2d[k * 128 + 2 * j]     = w;
    g_W2d[k * 128 + 2 * j + 1] = w;
}

// ---------------------------------------------------------------------------
// Kernel 1: g_xa = x @ W_ma[0:64] + b_ma ;  g_acc = (1+eps1)*x
// ---------------------------------------------------------------------------
__global__ __launch_bounds__(256) void k_node_pre(
    const float* __restrict__ x, const float* __restrict__ W_ma,
    const float* __restrict__ b_ma, const float* __restrict__ eps1)
{
    __shared__ float Xs[64 * 68];
    __shared__ float Ws[64 * 68];
    __shared__ float bs[64];
    const int t = threadIdx.x;
    const int row0 = blockIdx.x * 64;

    for (int i = t; i < 64 * 16; i += 256) {
        int k = i / 16, c = (i % 16) * 4;
        *(float4*)(Ws + k * 68 + c) = *(const float4*)(W_ma + k * 64 + c);
    }
    if (t < 64) bs[t] = b_ma[t];
    for (int i = t; i < 64 * 16; i += 256) {
        int r = i / 16, c = (i % 16) * 4;
        int gr = row0 + r;
        float4 v = make_float4(0.f, 0.f, 0.f, 0.f);
        if (gr < Nn) v = *(const float4*)(x + gr * 64 + c);
        *(float4*)(Xs + r * 68 + c) = v;
    }
    __syncthreads();

    const int r0 = (t / 16) * 4, c0 = (t % 16) * 4;
    float acc[4][4];
#pragma unroll
    for (int i = 0; i < 4; i++)
#pragma unroll
        for (int j = 0; j < 4; j++) acc[i][j] = 0.f;

#pragma unroll
    for (int k = 0; k < 64; k += 4) {
        float4 a4[4];
#pragma unroll
        for (int i = 0; i < 4; i++) a4[i] = *(float4*)(Xs + (r0 + i) * 68 + k);
#pragma unroll
        for (int kk = 0; kk < 4; kk++) {
            float4 b4 = *(float4*)(Ws + (k + kk) * 68 + c0);
#pragma unroll
            for (int i = 0; i < 4; i++) {
                float a = ((const float*)&a4[i])[kk];
                acc[i][0] += a * b4.x; acc[i][1] += a * b4.y;
                acc[i][2] += a * b4.z; acc[i][3] += a * b4.w;
            }
        }
    }

    const float e1 = 1.0f + eps1[0];
#pragma unroll
    for (int i = 0; i < 4; i++) {
        int gr = row0 + r0 + i;
        if (gr < Nn) {
            float4 o;
            o.x = acc[i][0] + bs[c0 + 0];
            o.y = acc[i][1] + bs[c0 + 1];
            o.z = acc[i][2] + bs[c0 + 2];
            o.w = acc[i][3] + bs[c0 + 3];
            *(float4*)(g_xa + gr * 64 + c0) = o;
            float4 xv = *(float4*)(Xs + (r0 + i) * 68 + c0);
            float4 av = make_float4(e1 * xv.x, e1 * xv.y, e1 * xv.z, e1 * xv.w);
            *(float4*)(g_acc + gr * 64 + c0) = av;
        }
    }
}

// ---------------------------------------------------------------------------
// Kernel 2: g_msgup = relu(attr1 @ W_mu + b_mu)
// ---------------------------------------------------------------------------
__global__ __launch_bounds__(256) void k_mlp_up(
    const float* __restrict__ attr1, const float* __restrict__ W_mu,
    const float* __restrict__ b_mu)
{
    __shared__ float As[64 * 68];
    __shared__ float Ws[64 * 68];
    __shared__ float bs[64];
    const int t = threadIdx.x;
    const int row0 = blockIdx.x * 64;
    const int M = Bb * Cc;

    for (int i = t; i < 64 * 16; i += 256) {
        int k = i / 16, c = (i % 16) * 4;
        *(float4*)(Ws + k * 68 + c) = *(const float4*)(W_mu + k * 64 + c);
    }
    if (t < 64) bs[t] = b_mu[t];
    for (int i = t; i < 64 * 16; i += 256) {
        int r = i / 16, c = (i % 16) * 4;
        int gr = row0 + r;
        float4 v = make_float4(0.f, 0.f, 0.f, 0.f);
        if (gr < M) v = *(const float4*)(attr1 + gr * 64 + c);
        *(float4*)(As + r * 68 + c) = v;
    }
    __syncthreads();

    const int r0 = (t / 16) * 4, c0 = (t % 16) * 4;
    float acc[4][4];
#pragma unroll
    for (int i = 0; i < 4; i++)
#pragma unroll
        for (int j = 0; j < 4; j++) acc[i][j] = 0.f;

#pragma unroll
    for (int k = 0; k < 64; k += 4) {
        float4 a4[4];
#pragma unroll
        for (int i = 0; i < 4; i++) a4[i] = *(float4*)(As + (r0 + i) * 68 + k);
#pragma unroll
        for (int kk = 0; kk < 4; kk++) {
            float4 b4 = *(float4*)(Ws + (k + kk) * 68 + c0);
#pragma unroll
            for (int i = 0; i < 4; i++) {
                float a = ((const float*)&a4[i])[kk];
                acc[i][0] += a * b4.x; acc[i][1] += a * b4.y;
                acc[i][2] += a * b4.z; acc[i][3] += a * b4.w;
            }
        }
    }

#pragma unroll
    for (int i = 0; i < 4; i++) {
        int gr = row0 + r0 + i;
        if (gr < M) {
            float4 o;
            o.x = fmaxf(acc[i][0] + bs[c0 + 0], 0.f);
            o.y = fmaxf(acc[i][1] + bs[c0 + 1], 0.f);
            o.z = fmaxf(acc[i][2] + bs[c0 + 2], 0.f);
            o.w = fmaxf(acc[i][3] + bs[c0 + 3], 0.f);
            *(float4*)(g_msgup + gr * 64 + c0) = o;
        }
    }
}

// ---------------------------------------------------------------------------
// Kernel 3: g_up[b,n,:] = sum_c nc1[b,n,c] * g_msgup[b,c,:]
// ---------------------------------------------------------------------------
__global__ __launch_bounds__(256) void k_upagg(const float* __restrict__ nc1)
{
    extern __shared__ float sm[];
    float* Ns = sm;              // 64 x 104
    float* Ms = sm + 64 * 104;   // 100 x 68
    const int t = threadIdx.x;
    const int b = blockIdx.y;
    const int row0 = blockIdx.x * 64;

    for (int i = t; i < 64 * 25; i += 256) {
        int r = i / 25, c = (i % 25) * 4;
        int gr = row0 + r;
        float4 v = make_float4(0.f, 0.f, 0.f, 0.f);
        if (gr < NMAXx)
            v = *(const float4*)(nc1 + ((size_t)b * NMAXx + gr) * Cc + c);
        *(float4*)(Ns + r * 104 + c) = v;
    }
    for (int i = t; i < 100 * 16; i += 256) {
        int r = i / 16, c = (i % 16) * 4;
        *(float4*)(Ms + r * 68 + c) =
            *(const float4*)(g_msgup + ((size_t)b * Cc + r) * 64 + c);
    }
    __syncthreads();

    const int r0 = (t / 16) * 4, c0 = (t % 16) * 4;
    float acc[4][4];
#pragma unroll
    for (int i = 0; i < 4; i++)
#pragma unroll
        for (int j = 0; j < 4; j++) acc[i][j] = 0.f;

#pragma unroll
    for (int k = 0; k < 100; k += 4) {
        float4 a4[4];
#pragma unroll
        for (int i = 0; i < 4; i++) a4[i] = *(float4*)(Ns + (r0 + i) * 104 + k);
#pragma unroll
        for (int kk = 0; kk < 4; kk++) {
            float4 b4 = *(float4*)(Ms + (k + kk) * 68 + c0);
#pragma unroll
            for (int i = 0; i < 4; i++) {
                float a = ((const float*)&a4[i])[kk];
                acc[i][0] += a * b4.x; acc[i][1] += a * b4.y;
                acc[i][2] += a * b4.z; acc[i][3] += a * b4.w;
            }
        }
    }

#pragma unroll
    for (int i = 0; i < 4; i++) {
        int gr = row0 + r0 + i;
        if (gr < NMAXx) {
            float4 o = make_float4(acc[i][0], acc[i][1], acc[i][2], acc[i][3]);
            *(float4*)(g_up + ((size_t)b * NMAXx + gr) * 64 + c0) = o;
        }
    }
}

// ---------------------------------------------------------------------------
// Kernel 4: f32x2 edge kernel, ORIGINAL edge order (sequential e streaming).
// Tile: 128 edges x 64 cols, 256 threads; per-thread 4 row-pairs x 4 cols of
// f32x2 accumulators. A transposed k-major (stride 132 -> LDS.128 pairs),
// W duplicated pairs. Epilogue: relu(EW + xa[src]) then red.global.add.v4.
// ---------------------------------------------------------------------------
#define EST_S 132                         // floats per k-row (16B-aligned pairs)
#define SM_W2_OFF (64 * EST_S)            // float index of Ws2
#define SM_EDGE_TOTAL ((64 * EST_S + 64 * 128) * 4)   // 66560 bytes

__global__ __launch_bounds__(256) void k_edge_f2(
    const float* __restrict__ e, const int* __restrict__ ei)
{
    extern __shared__ float sm[];
    float* EsT = sm;                 // [64][EST_S]
    float* Ws2 = sm + SM_W2_OFF;     // [64][128]

    const int t  = threadIdx.x;
    const int e0 = blockIdx.x * 128;

    // W duplicated pairs: linear copy 32KB
    {
        const float4* src = (const float4*)g_W2d;
        float4* dst = (float4*)Ws2;
#pragma unroll
        for (int i = t; i < 64 * 128 / 4; i += 256) dst[i] = src[i];
    }

    // A tile: stream e rows sequentially, store transposed (k-major).
    // i = r*16 + q: 16 lanes share a row -> fully coalesced 256B row reads.
#pragma unroll
    for (int i = t; i < 128 * 16; i += 256) {
        int r = i >> 4, q = i & 15;
        float4 v = *(const float4*)(e + (size_t)(e0 + r) * 64 + q * 4);
        int k = q * 4;
        EsT[(k + 0) * EST_S + r] = v.x;
        EsT[(k + 1) * EST_S + r] = v.y;
        EsT[(k + 2) * EST_S + r] = v.z;
        EsT[(k + 3) * EST_S + r] = v.w;
    }
    __syncthreads();

    const int r0 = (t / 16) * 8;      // 8 rows (4 pairs)
    const int c0 = (t % 16) * 4;      // 4 cols

    unsigned long long acc[4][4];     // [rowpair][col]
#pragma unroll
    for (int p = 0; p < 4; p++)
#pragma unroll
        for (int j = 0; j < 4; j++) acc[p][j] = 0ull;

#pragma unroll 4
    for (int k = 0; k < 64; k++) {
        const float* At = EsT + k * EST_S + r0;
        ulonglong2 ap0 = *(const ulonglong2*)(At);        // rows r0..r0+3
        ulonglong2 ap1 = *(const ulonglong2*)(At + 4);    // rows r0+4..r0+7
        const float* Bt = Ws2 + k * 128 + 2 * c0;
        ulonglong2 bp0 = *(const ulonglong2*)(Bt);        // dup cols c0, c0+1
        ulonglong2 bp1 = *(const ulonglong2*)(Bt + 4);    // dup cols c0+2, c0+3
        fma2(acc[0][0], ap0.x, bp0.x); fma2(acc[0][1], ap0.x, bp0.y);
        fma2(acc[0][2], ap0.x, bp1.x); fma2(acc[0][3], ap0.x, bp1.y);
        fma2(acc[1][0], ap0.y, bp0.x); fma2(acc[1][1], ap0.y, bp0.y);
        fma2(acc[1][2], ap0.y, bp1.x); fma2(acc[1][3], ap0.y, bp1.y);
        fma2(acc[2][0], ap1.x, bp0.x); fma2(acc[2][1], ap1.x, bp0.y);
        fma2(acc[2][2], ap1.x, bp1.x); fma2(acc[2][3], ap1.x, bp1.y);
        fma2(acc[3][0], ap1.y, bp0.x); fma2(acc[3][1], ap1.y, bp0.y);
        fma2(acc[3][2], ap1.y, bp1.x); fma2(acc[3][3], ap1.y, bp1.y);
    }

    // Epilogue: msg = relu(EW + xa[src]); one red.v4 per (row, col-quad).
    {
        const int* __restrict__ srcp = ei;
        const int* __restrict__ dstp = ei + Ee;
#pragma unroll
        for (int i = 0; i < 8; i++) {
            int er = e0 + r0 + i;
            int s = srcp[er];
            int d = dstp[er];
            float4 xa = *(const float4*)(g_xa + (size_t)s * 64 + c0);
            float2 p0 = unpack2(acc[i >> 1][0]);
            float2 p1 = unpack2(acc[i >> 1][1]);
            float2 p2 = unpack2(acc[i >> 1][2]);
            float2 p3 = unpack2(acc[i >> 1][3]);
            float v0 = (i & 1) ? p0.y : p0.x;
            float v1 = (i & 1) ? p1.y : p1.x;
            float v2 = (i & 1) ? p2.y : p2.x;
            float v3 = (i & 1) ? p3.y : p3.x;
            float m0 = fmaxf(v0 + xa.x, 0.f);
            float m1 = fmaxf(v1 + xa.y, 0.f);
            float m2 = fmaxf(v2 + xa.z, 0.f);
            float m3 = fmaxf(v3 + xa.w, 0.f);
            red_add_v4(g_acc + (size_t)d * 64 + c0, m0, m1, m2, m3);
        }
    }
}

// ---------------------------------------------------------------------------
// Kernel 5 (fused tail): h1 = relu(g_acc @ W_ua + b_ua);
// h2 = relu((g_up[x_idx] + (1+eps2)*x) @ W_uu + b_uu);
// out = h1 @ W_c[0:64] + h2 @ W_c[64:128] + b_c
// ---------------------------------------------------------------------------
__global__ __launch_bounds__(256) void k_final(
    const float* __restrict__ x, const int* __restrict__ x_idx,
    const float* __restrict__ eps2,
    const float* __restrict__ W_ua, const float* __restrict__ b_ua,
    const float* __restrict__ W_uu, const float* __restrict__ b_uu,
    const float* __restrict__ W_c, const float* __restrict__ b_c,
    float* __restrict__ out)
{
    extern __shared__ float sm[];
    float* A1  = sm;
    float* A2  = A1 + 64 * 68;
    float* Wua = A2 + 64 * 68;
    float* Wuu = Wua + 64 * 68;
    float* Wc1 = Wuu + 64 * 68;
    float* Wc2 = Wc1 + 64 * 68;
    __shared__ float bua[64], buu[64], bcs[64];

    const int t = threadIdx.x;
    const int row0 = blockIdx.x * 64;
    const float e2 = 1.0f + eps2[0];

    for (int i = t; i < 64 * 16; i += 256) {
        int k = i / 16, c = (i % 16) * 4;
        *(float4*)(Wua + k * 68 + c) = *(const float4*)(W_ua + k * 64 + c);
        *(float4*)(Wuu + k * 68 + c) = *(const float4*)(W_uu + k * 64 + c);
        *(float4*)(Wc1 + k * 68 + c) = *(const float4*)(W_c + k * 64 + c);
        *(float4*)(Wc2 + k * 68 + c) = *(const float4*)(W_c + (64 + k) * 64 + c);
    }
    if (t < 64) { bua[t] = b_ua[t]; buu[t] = b_uu[t]; bcs[t] = b_c[t]; }

    for (int i = t; i < 64 * 16; i += 256) {
        int r = i / 16, c = (i % 16) * 4;
        int gr = row0 + r;
        float4 a1 = make_float4(0.f, 0.f, 0.f, 0.f);
        float4 a2 = make_float4(0.f, 0.f, 0.f, 0.f);
        if (gr < Nn) {
            a1 = *(const float4*)(g_acc + (size_t)gr * 64 + c);
            int xi = x_idx[gr];
            float4 u  = *(const float4*)(g_up + (size_t)xi * 64 + c);
            float4 xv = *(const float4*)(x + (size_t)gr * 64 + c);
            a2 = make_float4(u.x + e2 * xv.x, u.y + e2 * xv.y,
                             u.z + e2 * xv.z, u.w + e2 * xv.w);
        }
        *(float4*)(A1 + r * 68 + c) = a1;
        *(float4*)(A2 + r * 68 + c) = a2;
    }
    __syncthreads();

    const int r0 = (t / 16) * 4, c0 = (t % 16) * 4;
    float h1[4][4], h2[4][4];
#pragma unroll
    for (int i = 0; i < 4; i++)
#pragma unroll
        for (int j = 0; j < 4; j++) { h1[i][j] = 0.f; h2[i][j] = 0.f; }

#pragma unroll
    for (int k = 0; k < 64; k += 4) {
        float4 a14[4], a24[4];
#pragma unroll
        for (int i = 0; i < 4; i++) {
            a14[i] = *(float4*)(A1 + (r0 + i) * 68 + k);
            a24[i] = *(float4*)(A2 + (r0 + i) * 68 + k);
        }
#pragma unroll
        for (int kk = 0; kk < 4; kk++) {
            float4 b1 = *(float4*)(Wua + (k + kk) * 68 + c0);
            float4 b2 = *(float4*)(Wuu + (k + kk) * 68 + c0);
#pragma unroll
            for (int i = 0; i < 4; i++) {
                float a = ((const float*)&a14[i])[kk];
                float b = ((const float*)&a24[i])[kk];
                h1[i][0] += a * b1.x; h1[i][1] += a * b1.y;
                h1[i][2] += a * b1.z; h1[i][3] += a * b1.w;
                h2[i][0] += b * b2.x; h2[i][1] += b * b2.y;
                h2[i][2] += b * b2.z; h2[i][3] += b * b2.w;
            }
        }
    }
#pragma unroll
    for (int i = 0; i < 4; i++)
#pragma unroll
        for (int j = 0; j < 4; j++) {
            h1[i][j] = fmaxf(h1[i][j] + bua[c0 + j], 0.f);
            h2[i][j] = fmaxf(h2[i][j] + buu[c0 + j], 0.f);
        }
    __syncthreads();
#pragma unroll
    for (int i = 0; i < 4; i++)
#pragma unroll
        for (int j = 0; j < 4; j++) {
            A1[(r0 + i) * 68 + c0 + j] = h1[i][j];
            A2[(r0 + i) * 68 + c0 + j] = h2[i][j];
        }
    __syncthreads();

    float o[4][4];
#pragma unroll
    for (int i = 0; i < 4; i++)
#pragma unroll
        for (int j = 0; j < 4; j++) o[i][j] = 0.f;

#pragma unroll
    for (int k = 0; k < 64; k += 4) {
        float4 a14[4], a24[4];
#pragma unroll
        for (int i = 0; i < 4; i++) {
            a14[i] = *(float4*)(A1 + (r0 + i) * 68 + k);
            a24[i] = *(float4*)(A2 + (r0 + i) * 68 + k);
        }
#pragma unroll
        for (int kk = 0; kk < 4; kk++) {
            float4 b1 = *(float4*)(Wc1 + (k + kk) * 68 + c0);
            float4 b2 = *(float4*)(Wc2 + (k + kk) * 68 + c0);
#pragma unroll
            for (int i = 0; i < 4; i++) {
                float a = ((const float*)&a14[i])[kk];
                float b = ((const float*)&a24[i])[kk];
                o[i][0] += a * b1.x + b * b2.x;
                o[i][1] += a * b1.y + b * b2.y;
                o[i][2] += a * b1.z + b * b2.z;
                o[i][3] += a * b1.w + b * b2.w;
            }
        }
    }

#pragma unroll
    for (int i = 0; i < 4; i++) {
        int gr = row0 + r0 + i;
        if (gr < Nn) {
            float4 ov;
            ov.x = o[i][0] + bcs[c0 + 0];
            ov.y = o[i][1] + bcs[c0 + 1];
            ov.z = o[i][2] + bcs[c0 + 2];
            ov.w = o[i][3] + bcs[c0 + 3];
            *(float4*)(out + (size_t)gr * 64 + c0) = ov;
        }
    }
}

// ---------------------------------------------------------------------------
extern "C" void kernel_launch(void* const* d_in, const int* in_sizes, int n_in,
                              void* d_out, int out_size)
{
    const float* x     = (const float*)d_in[0];
    const float* e     = (const float*)d_in[1];
    const int*   ei    = (const int*)d_in[2];
    const float* attr1 = (const float*)d_in[3];
    const float* nc1   = (const float*)d_in[4];
    const int*   x_idx = (const int*)d_in[5];
    const float* eps1  = (const float*)d_in[6];
    const float* eps2  = (const float*)d_in[7];
    const float* W_ma  = (const float*)d_in[8];
    const float* b_ma  = (const float*)d_in[9];
    const float* W_mu  = (const float*)d_in[10];
    const float* b_mu  = (const float*)d_in[11];
    const float* W_ua  = (const float*)d_in[12];
    const float* b_ua  = (const float*)d_in[13];
    const float* W_uu  = (const float*)d_in[14];
    const float* b_uu  = (const float*)d_in[15];
    const float* W_c   = (const float*)d_in[16];
    const float* b_c   = (const float*)d_in[17];
    float* out = (float*)d_out;

    const int SMEM_UP  = (64 * 104 + 100 * 68) * 4;
    const int SMEM_FIN = (6 * 64 * 68) * 4;

    cudaFuncSetAttribute(k_upagg,   cudaFuncAttributeMaxDynamicSharedMemorySize, SMEM_UP);
    cudaFuncSetAttribute(k_edge_f2, cudaFuncAttributeMaxDynamicSharedMemorySize, SM_EDGE_TOTAL);
    cudaFuncSetAttribute(k_final,   cudaFuncAttributeMaxDynamicSharedMemorySize, SMEM_FIN);

    // weight prep + node branches
    k_prep_w2<<<(64 * 64 + 255) / 256, 256>>>(W_ma);
    k_node_pre<<<(Nn + 63) / 64, 256>>>(x, W_ma, b_ma, eps1);
    k_mlp_up<<<(Bb * Cc + 63) / 64, 256>>>(attr1, W_mu, b_mu);
    k_upagg<<<dim3((NMAXx + 63) / 64, Bb), 256, SMEM_UP>>>(nc1);

    // f32x2 edge kernel, original edge order, vector-red atomics
    k_edge_f2<<<Ee / 128, 256, SM_EDGE_TOTAL>>>(e, ei);

    // fused tail
    k_final<<<(Nn + 63) / 64, 256, SMEM_FIN>>>(x, x_idx, eps2, W_ua, b_ua,
                                               W_uu, b_uu, W_c, b_c, out);
}

// round 7
// speedup vs baseline: 1.6722x; 1.5378x over previous
#include <cuda_runtime.h>
#include <cuda_bf16.h>
#include <cstdint>

// Problem constants
#define Nn     50000
#define Dd     64
#define Ee     800000
#define Bb     50
#define NMAXx  1000
#define Cc     100

// ---------------------------------------------------------------------------
// Device scratch (no allocations allowed)
// ---------------------------------------------------------------------------
__device__ float g_xa[Nn * Dd];          // x @ W_ma[:64] + b_ma
__device__ float g_acc[Nn * Dd];         // (1+eps1)*x + segment_sum(msg)
__device__ float g_up[Nn * Dd];          // einsum result (flat [B*NMAX, D])
__device__ float g_msgup[Bb * Cc * Dd];  // relu(attr1 @ W_mu + b_mu)

// W_ma[64:128] split into bf16 hi/lo, n-major: g_Wbhi[n*64 + k]
__device__ unsigned short g_Wbhi[64 * 64];
__device__ unsigned short g_Wblo[64 * 64];

// ---------------------------------------------------------------------------
// mma.sync / ldmatrix helpers (base ISA, sm_80+)
// ---------------------------------------------------------------------------
__device__ __forceinline__ uint32_t smem_u32(const void* p) {
    uint32_t a;
    asm("{ .reg .u64 t; cvta.to.shared.u64 t, %1; cvt.u32.u64 %0, t; }"
        : "=r"(a) : "l"(p));
    return a;
}
__device__ __forceinline__ void ldsm_x4(uint32_t* r, uint32_t addr) {
    asm volatile("ldmatrix.sync.aligned.m8n8.x4.shared.b16 {%0,%1,%2,%3}, [%4];"
                 : "=r"(r[0]), "=r"(r[1]), "=r"(r[2]), "=r"(r[3]) : "r"(addr));
}
__device__ __forceinline__ void ldsm_x2(uint32_t* r, uint32_t addr) {
    asm volatile("ldmatrix.sync.aligned.m8n8.x2.shared.b16 {%0,%1}, [%2];"
                 : "=r"(r[0]), "=r"(r[1]) : "r"(addr));
}
__device__ __forceinline__ void mma_bf16(float* c, const uint32_t* a,
                                         const uint32_t* b) {
    asm volatile(
        "mma.sync.aligned.m16n8k16.row.col.f32.bf16.bf16.f32 "
        "{%0,%1,%2,%3}, {%4,%5,%6,%7}, {%8,%9}, {%0,%1,%2,%3};"
        : "+f"(c[0]), "+f"(c[1]), "+f"(c[2]), "+f"(c[3])
        : "r"(a[0]), "r"(a[1]), "r"(a[2]), "r"(a[3]), "r"(b[0]), "r"(b[1]));
}

// ---------------------------------------------------------------------------
// Prep: W_ma[64+k][n] -> bf16 hi (RZ truncate) + lo (RN residual), n-major
// ---------------------------------------------------------------------------
__global__ void k_prep_wb(const float* __restrict__ W_ma) {
    int i = blockIdx.x * 256 + threadIdx.x;
    if (i >= 64 * 64) return;
    int k = i >> 6, n = i & 63;
    float w = W_ma[(64 + k) * 64 + n];
    uint32_t u = __float_as_uint(w);
    unsigned short hi = (unsigned short)(u >> 16);
    float hif = __uint_as_float(u & 0xFFFF0000u);
    float lo = w - hif;
    g_Wbhi[n * 64 + k] = hi;
    g_Wblo[n * 64 + k] = __bfloat16_as_ushort(__float2bfloat16(lo));
}

// ---------------------------------------------------------------------------
// Kernel 1: g_xa = x @ W_ma[0:64] + b_ma ;  g_acc = (1+eps1)*x
// ---------------------------------------------------------------------------
__global__ __launch_bounds__(256) void k_node_pre(
    const float* __restrict__ x, const float* __restrict__ W_ma,
    const float* __restrict__ b_ma, const float* __restrict__ eps1)
{
    __shared__ float Xs[64 * 68];
    __shared__ float Ws[64 * 68];
    __shared__ float bs[64];
    const int t = threadIdx.x;
    const int row0 = blockIdx.x * 64;

    for (int i = t; i < 64 * 16; i += 256) {
        int k = i / 16, c = (i % 16) * 4;
        *(float4*)(Ws + k * 68 + c) = *(const float4*)(W_ma + k * 64 + c);
    }
    if (t < 64) bs[t] = b_ma[t];
    for (int i = t; i < 64 * 16; i += 256) {
        int r = i / 16, c = (i % 16) * 4;
        int gr = row0 + r;
        float4 v = make_float4(0.f, 0.f, 0.f, 0.f);
        if (gr < Nn) v = *(const float4*)(x + gr * 64 + c);
        *(float4*)(Xs + r * 68 + c) = v;
    }
    __syncthreads();

    const int r0 = (t / 16) * 4, c0 = (t % 16) * 4;
    float acc[4][4];
#pragma unroll
    for (int i = 0; i < 4; i++)
#pragma unroll
        for (int j = 0; j < 4; j++) acc[i][j] = 0.f;

#pragma unroll
    for (int k = 0; k < 64; k += 4) {
        float4 a4[4];
#pragma unroll
        for (int i = 0; i < 4; i++) a4[i] = *(float4*)(Xs + (r0 + i) * 68 + k);
#pragma unroll
        for (int kk = 0; kk < 4; kk++) {
            float4 b4 = *(float4*)(Ws + (k + kk) * 68 + c0);
#pragma unroll
            for (int i = 0; i < 4; i++) {
                float a = ((const float*)&a4[i])[kk];
                acc[i][0] += a * b4.x; acc[i][1] += a * b4.y;
                acc[i][2] += a * b4.z; acc[i][3] += a * b4.w;
            }
        }
    }

    const float e1 = 1.0f + eps1[0];
#pragma unroll
    for (int i = 0; i < 4; i++) {
        int gr = row0 + r0 + i;
        if (gr < Nn) {
            float4 o;
            o.x = acc[i][0] + bs[c0 + 0];
            o.y = acc[i][1] + bs[c0 + 1];
            o.z = acc[i][2] + bs[c0 + 2];
            o.w = acc[i][3] + bs[c0 + 3];
            *(float4*)(g_xa + gr * 64 + c0) = o;
            float4 xv = *(float4*)(Xs + (r0 + i) * 68 + c0);
            float4 av = make_float4(e1 * xv.x, e1 * xv.y, e1 * xv.z, e1 * xv.w);
            *(float4*)(g_acc + gr * 64 + c0) = av;
        }
    }
}

// ---------------------------------------------------------------------------
// Kernel 2: g_msgup = relu(attr1 @ W_mu + b_mu)
// ---------------------------------------------------------------------------
__global__ __launch_bounds__(256) void k_mlp_up(
    const float* __restrict__ attr1, const float* __restrict__ W_mu,
    const float* __restrict__ b_mu)
{
    __shared__ float As[64 * 68];
    __shared__ float Ws[64 * 68];
    __shared__ float bs[64];
    const int t = threadIdx.x;
    const int row0 = blockIdx.x * 64;
    const int M = Bb * Cc;

    for (int i = t; i < 64 * 16; i += 256) {
        int k = i / 16, c = (i % 16) * 4;
        *(float4*)(Ws + k * 68 + c) = *(const float4*)(W_mu + k * 64 + c);
    }
    if (t < 64) bs[t] = b_mu[t];
    for (int i = t; i < 64 * 16; i += 256) {
        int r = i / 16, c = (i % 16) * 4;
        int gr = row0 + r;
        float4 v = make_float4(0.f, 0.f, 0.f, 0.f);
        if (gr < M) v = *(const float4*)(attr1 + gr * 64 + c);
        *(float4*)(As + r * 68 + c) = v;
    }
    __syncthreads();

    const int r0 = (t / 16) * 4, c0 = (t % 16) * 4;
    float acc[4][4];
#pragma unroll
    for (int i = 0; i < 4; i++)
#pragma unroll
        for (int j = 0; j < 4; j++) acc[i][j] = 0.f;

#pragma unroll
    for (int k = 0; k < 64; k += 4) {
        float4 a4[4];
#pragma unroll
        for (int i = 0; i < 4; i++) a4[i] = *(float4*)(As + (r0 + i) * 68 + k);
#pragma unroll
        for (int kk = 0; kk < 4; kk++) {
            float4 b4 = *(float4*)(Ws + (k + kk) * 68 + c0);
#pragma unroll
            for (int i = 0; i < 4; i++) {
                float a = ((const float*)&a4[i])[kk];
                acc[i][0] += a * b4.x; acc[i][1] += a * b4.y;
                acc[i][2] += a * b4.z; acc[i][3] += a * b4.w;
            }
        }
    }

#pragma unroll
    for (int i = 0; i < 4; i++) {
        int gr = row0 + r0 + i;
        if (gr < M) {
            float4 o;
            o.x = fmaxf(acc[i][0] + bs[c0 + 0], 0.f);
            o.y = fmaxf(acc[i][1] + bs[c0 + 1], 0.f);
            o.z = fmaxf(acc[i][2] + bs[c0 + 2], 0.f);
            o.w = fmaxf(acc[i][3] + bs[c0 + 3], 0.f);
            *(float4*)(g_msgup + gr * 64 + c0) = o;
        }
    }
}

// ---------------------------------------------------------------------------
// Kernel 3: g_up[b,n,:] = sum_c nc1[b,n,c] * g_msgup[b,c,:]
// ---------------------------------------------------------------------------
__global__ __launch_bounds__(256) void k_upagg(const float* __restrict__ nc1)
{
    extern __shared__ float sm[];
    float* Ns = sm;              // 64 x 104
    float* Ms = sm + 64 * 104;   // 100 x 68
    const int t = threadIdx.x;
    const int b = blockIdx.y;
    const int row0 = blockIdx.x * 64;

    for (int i = t; i < 64 * 25; i += 256) {
        int r = i / 25, c = (i % 25) * 4;
        int gr = row0 + r;
        float4 v = make_float4(0.f, 0.f, 0.f, 0.f);
        if (gr < NMAXx)
            v = *(const float4*)(nc1 + ((size_t)b * NMAXx + gr) * Cc + c);
        *(float4*)(Ns + r * 104 + c) = v;
    }
    for (int i = t; i < 100 * 16; i += 256) {
        int r = i / 16, c = (i % 16) * 4;
        *(float4*)(Ms + r * 68 + c) =
            *(const float4*)(g_msgup + ((size_t)b * Cc + r) * 64 + c);
    }
    __syncthreads();

    const int r0 = (t / 16) * 4, c0 = (t % 16) * 4;
    float acc[4][4];
#pragma unroll
    for (int i = 0; i < 4; i++)
#pragma unroll
        for (int j = 0; j < 4; j++) acc[i][j] = 0.f;

#pragma unroll
    for (int k = 0; k < 100; k += 4) {
        float4 a4[4];
#pragma unroll
        for (int i = 0; i < 4; i++) a4[i] = *(float4*)(Ns + (r0 + i) * 104 + k);
#pragma unroll
        for (int kk = 0; kk < 4; kk++) {
            float4 b4 = *(float4*)(Ms + (k + kk) * 68 + c0);
#pragma unroll
            for (int i = 0; i < 4; i++) {
                float a = ((const float*)&a4[i])[kk];
                acc[i][0] += a * b4.x; acc[i][1] += a * b4.y;
                acc[i][2] += a * b4.z; acc[i][3] += a * b4.w;
            }
        }
    }

#pragma unroll
    for (int i = 0; i < 4; i++) {
        int gr = row0 + r0 + i;
        if (gr < NMAXx) {
            float4 o = make_float4(acc[i][0], acc[i][1], acc[i][2], acc[i][3]);
            *(float4*)(g_up + ((size_t)b * NMAXx + gr) * 64 + c0) = o;
        }
    }
}

// ---------------------------------------------------------------------------
// Kernel 4: split-bf16 HMMA edge kernel (mma.sync m16n8k16, base ISA).
// Tile: 128 edges x 64 cols x 64 K. 8 warps; warp w owns edge rows 16w..16w+15.
// EW = Ah@Bh + Ah@Bl + Al@Bh (fp32 accum). Stage C to smem, then R1 epilogue:
// msg = relu(EW + xa[src]); scalar atomicAdd x4 into g_acc[dst].
//
// smem (bytes): Ahi [128 x 72 bf16] @0 (18432), Alo @18432 (18432),
//               Bhi [64 x 72 bf16] @36864 (9216), Blo @46080 (9216). Tot 55296.
// Cstage [128 x 68 f32] overlays Ahi/Alo after A is consumed into fragments.
// ---------------------------------------------------------------------------
#define SMA_HI 0
#define SMA_LO 18432
#define SMB_HI 36864
#define SMB_LO 46080
#define SM_EDGE_TOT 55296

__global__ __launch_bounds__(256) void k_edge_hmma(
    const float* __restrict__ e, const int* __restrict__ ei)
{
    extern __shared__ char smc[];
    const uint32_t sbase = smem_u32(smc);
    const int t = threadIdx.x;
    const int w = t >> 5;
    const int lane = t & 31;
    const int e0 = blockIdx.x * 128;

    // B tiles: prepped bf16 n-major [n][64k], copy into stride-144B rows.
    {
        const uint4* srcH = (const uint4*)g_Wbhi;   // 512 uint4
        const uint4* srcL = (const uint4*)g_Wblo;
#pragma unroll
        for (int i = t; i < 512; i += 256) {
            int r = i >> 3, c = i & 7;
            *(uint4*)(smc + SMB_HI + r * 144 + c * 16) = srcH[i];
            *(uint4*)(smc + SMB_LO + r * 144 + c * 16) = srcL[i];
        }
    }

    // A tile: stream e rows, split fp32 -> bf16 hi (RZ) + lo (RN residual).
    // i = r*16 + q: 16 lanes share a row -> fully coalesced 256B row reads.
#pragma unroll
    for (int i = t; i < 2048; i += 256) {
        int r = i >> 4, q = i & 15;
        float4 v = *(const float4*)(e + (size_t)(e0 + r) * 64 + q * 4);
        uint32_t u0 = __float_as_uint(v.x), u1 = __float_as_uint(v.y);
        uint32_t u2 = __float_as_uint(v.z), u3 = __float_as_uint(v.w);
        uint32_t hi01 = (u0 >> 16) | (u1 & 0xFFFF0000u);
        uint32_t hi23 = (u2 >> 16) | (u3 & 0xFFFF0000u);
        float l0 = v.x - __uint_as_float(u0 & 0xFFFF0000u);
        float l1 = v.y - __uint_as_float(u1 & 0xFFFF0000u);
        float l2 = v.z - __uint_as_float(u2 & 0xFFFF0000u);
        float l3 = v.w - __uint_as_float(u3 & 0xFFFF0000u);
        __nv_bfloat162 p01 = __floats2bfloat162_rn(l0, l1);  // x=l0 (low half)
        __nv_bfloat162 p23 = __floats2bfloat162_rn(l2, l3);
        uint32_t lo01 = *(uint32_t*)&p01;
        uint32_t lo23 = *(uint32_t*)&p23;
        *(uint2*)(smc + SMA_HI + r * 144 + q * 8) = make_uint2(hi01, hi23);
        *(uint2*)(smc + SMA_LO + r * 144 + q * 8) = make_uint2(lo01, lo23);
    }
    __syncthreads();

    // Preload all A fragments (4 k-tiles, hi+lo): 32 regs.
    uint32_t ah[4][4], al[4][4];
    {
        int arow = 16 * w + (lane & 15);
        int acolB = ((lane >> 4) * 8) * 2;     // byte offset within k
#pragma unroll
        for (int kt = 0; kt < 4; kt++) {
            uint32_t off = (uint32_t)(arow * 144 + kt * 32 + acolB);
            ldsm_x4(ah[kt], sbase + SMA_HI + off);
            ldsm_x4(al[kt], sbase + SMA_LO + off);
        }
    }
    __syncthreads();   // all A consumed -> Cstage may overlay Ahi/Alo

    float* cst = (float*)smc;   // Cstage [128][68]

    // B ldmatrix addressing (x2): lanes 0-7 -> n rows 0-7 (k-off 0),
    // lanes 8-15 -> same n rows, k-off +8. Lanes 16-31: replicate (unused).
    const int bl = lane & 15;
    const int brow = bl & 7;
    const int bkB = ((bl >> 3) * 8) * 2;

    const int grp = lane >> 2, tig = lane & 3;

#pragma unroll
    for (int nt = 0; nt < 8; nt++) {
        uint32_t bh[4][2], blo[4][2];
#pragma unroll
        for (int kt = 0; kt < 4; kt++) {
            uint32_t ba = (uint32_t)((nt * 8 + brow) * 144 + kt * 32 + bkB);
            ldsm_x2(bh[kt], sbase + SMB_HI + ba);
            ldsm_x2(blo[kt], sbase + SMB_LO + ba);
        }
        float c[4] = {0.f, 0.f, 0.f, 0.f};
#pragma unroll
        for (int kt = 0; kt < 4; kt++) {
            mma_bf16(c, ah[kt], bh[kt]);
            mma_bf16(c, ah[kt], blo[kt]);
            mma_bf16(c, al[kt], bh[kt]);
        }
        int row = 16 * w + grp;
        int col = nt * 8 + 2 * tig;
        *(float2*)(cst + row * 68 + col)       = make_float2(c[0], c[1]);
        *(float2*)(cst + (row + 8) * 68 + col) = make_float2(c[2], c[3]);
    }
    __syncthreads();

    // Epilogue (R1 style): thread owns 8 rows x 4 cols.
    {
        const int r0 = (t / 16) * 8, c0 = (t % 16) * 4;
        const int* __restrict__ srcp = ei;
        const int* __restrict__ dstp = ei + Ee;
#pragma unroll
        for (int i = 0; i < 8; i++) {
            int er = e0 + r0 + i;
            int s = srcp[er];
            int d = dstp[er];
            float4 xa = *(const float4*)(g_xa + (size_t)s * 64 + c0);
            float4 cw = *(const float4*)(cst + (r0 + i) * 68 + c0);
            float m0 = fmaxf(cw.x + xa.x, 0.f);
            float m1 = fmaxf(cw.y + xa.y, 0.f);
            float m2 = fmaxf(cw.z + xa.z, 0.f);
            float m3 = fmaxf(cw.w + xa.w, 0.f);
            float* dp = g_acc + (size_t)d * 64 + c0;
            atomicAdd(dp + 0, m0);
            atomicAdd(dp + 1, m1);
            atomicAdd(dp + 2, m2);
            atomicAdd(dp + 3, m3);
        }
    }
}

// ---------------------------------------------------------------------------
// Kernel 5 (fused tail): h1 = relu(g_acc @ W_ua + b_ua);
// h2 = relu((g_up[x_idx] + (1+eps2)*x) @ W_uu + b_uu);
// out = h1 @ W_c[0:64] + h2 @ W_c[64:128] + b_c
// ---------------------------------------------------------------------------
__global__ __launch_bounds__(256) void k_final(
    const float* __restrict__ x, const int* __restrict__ x_idx,
    const float* __restrict__ eps2,
    const float* __restrict__ W_ua, const float* __restrict__ b_ua,
    const float* __restrict__ W_uu, const float* __restrict__ b_uu,
    const float* __restrict__ W_c, const float* __restrict__ b_c,
    float* __restrict__ out)
{
    extern __shared__ float sm[];
    float* A1  = sm;
    float* A2  = A1 + 64 * 68;
    float* Wua = A2 + 64 * 68;
    float* Wuu = Wua + 64 * 68;
    float* Wc1 = Wuu + 64 * 68;
    float* Wc2 = Wc1 + 64 * 68;
    __shared__ float bua[64], buu[64], bcs[64];

    const int t = threadIdx.x;
    const int row0 = blockIdx.x * 64;
    const float e2 = 1.0f + eps2[0];

    for (int i = t; i < 64 * 16; i += 256) {
        int k = i / 16, c = (i % 16) * 4;
        *(float4*)(Wua + k * 68 + c) = *(const float4*)(W_ua + k * 64 + c);
        *(float4*)(Wuu + k * 68 + c) = *(const float4*)(W_uu + k * 64 + c);
        *(float4*)(Wc1 + k * 68 + c) = *(const float4*)(W_c + k * 64 + c);
        *(float4*)(Wc2 + k * 68 + c) = *(const float4*)(W_c + (64 + k) * 64 + c);
    }
    if (t < 64) { bua[t] = b_ua[t]; buu[t] = b_uu[t]; bcs[t] = b_c[t]; }

    for (int i = t; i < 64 * 16; i += 256) {
        int r = i / 16, c = (i % 16) * 4;
        int gr = row0 + r;
        float4 a1 = make_float4(0.f, 0.f, 0.f, 0.f);
        float4 a2 = make_float4(0.f, 0.f, 0.f, 0.f);
        if (gr < Nn) {
            a1 = *(const float4*)(g_acc + (size_t)gr * 64 + c);
            int xi = x_idx[gr];
            float4 u  = *(const float4*)(g_up + (size_t)xi * 64 + c);
            float4 xv = *(const float4*)(x + (size_t)gr * 64 + c);
            a2 = make_float4(u.x + e2 * xv.x, u.y + e2 * xv.y,
                             u.z + e2 * xv.z, u.w + e2 * xv.w);
        }
        *(float4*)(A1 + r * 68 + c) = a1;
        *(float4*)(A2 + r * 68 + c) = a2;
    }
    __syncthreads();

    const int r0 = (t / 16) * 4, c0 = (t % 16) * 4;
    float h1[4][4], h2[4][4];
#pragma unroll
    for (int i = 0; i < 4; i++)
#pragma unroll
        for (int j = 0; j < 4; j++) { h1[i][j] = 0.f; h2[i][j] = 0.f; }

#pragma unroll
    for (int k = 0; k < 64; k += 4) {
        float4 a14[4], a24[4];
#pragma unroll
        for (int i = 0; i < 4; i++) {
            a14[i] = *(float4*)(A1 + (r0 + i) * 68 + k);
            a24[i] = *(float4*)(A2 + (r0 + i) * 68 + k);
        }
#pragma unroll
        for (int kk = 0; kk < 4; kk++) {
            float4 b1 = *(float4*)(Wua + (k + kk) * 68 + c0);
            float4 b2 = *(float4*)(Wuu + (k + kk) * 68 + c0);
#pragma unroll
            for (int i = 0; i < 4; i++) {
                float a = ((const float*)&a14[i])[kk];
                float b = ((const float*)&a24[i])[kk];
                h1[i][0] += a * b1.x; h1[i][1] += a * b1.y;
                h1[i][2] += a * b1.z; h1[i][3] += a * b1.w;
                h2[i][0] += b * b2.x; h2[i][1] += b * b2.y;
                h2[i][2] += b * b2.z; h2[i][3] += b * b2.w;
            }
        }
    }
#pragma unroll
    for (int i = 0; i < 4; i++)
#pragma unroll
        for (int j = 0; j < 4; j++) {
            h1[i][j] = fmaxf(h1[i][j] + bua[c0 + j], 0.f);
            h2[i][j] = fmaxf(h2[i][j] + buu[c0 + j], 0.f);
        }
    __syncthreads();
#pragma unroll
    for (int i = 0; i < 4; i++)
#pragma unroll
        for (int j = 0; j < 4; j++) {
            A1[(r0 + i) * 68 + c0 + j] = h1[i][j];
            A2[(r0 + i) * 68 + c0 + j] = h2[i][j];
        }
    __syncthreads();

    float o[4][4];
#pragma unroll
    for (int i = 0; i < 4; i++)
#pragma unroll
        for (int j = 0; j < 4; j++) o[i][j] = 0.f;

#pragma unroll
    for (int k = 0; k < 64; k += 4) {
        float4 a14[4], a24[4];
#pragma unroll
        for (int i = 0; i < 4; i++) {
            a14[i] = *(float4*)(A1 + (r0 + i) * 68 + k);
            a24[i] = *(float4*)(A2 + (r0 + i) * 68 + k);
        }
#pragma unroll
        for (int kk = 0; kk < 4; kk++) {
            float4 b1 = *(float4*)(Wc1 + (k + kk) * 68 + c0);
            float4 b2 = *(float4*)(Wc2 + (k + kk) * 68 + c0);
#pragma unroll
            for (int i = 0; i < 4; i++) {
                float a = ((const float*)&a14[i])[kk];
                float b = ((const float*)&a24[i])[kk];
                o[i][0] += a * b1.x + b * b2.x;
                o[i][1] += a * b1.y + b * b2.y;
                o[i][2] += a * b1.z + b * b2.z;
                o[i][3] += a * b1.w + b * b2.w;
            }
        }
    }

#pragma unroll
    for (int i = 0; i < 4; i++) {
        int gr = row0 + r0 + i;
        if (gr < Nn) {
            float4 ov;
            ov.x = o[i][0] + bcs[c0 + 0];
            ov.y = o[i][1] + bcs[c0 + 1];
            ov.z = o[i][2] + bcs[c0 + 2];
            ov.w = o[i][3] + bcs[c0 + 3];
            *(float4*)(out + (size_t)gr * 64 + c0) = ov;
        }
    }
}

// ---------------------------------------------------------------------------
extern "C" void kernel_launch(void* const* d_in, const int* in_sizes, int n_in,
                              void* d_out, int out_size)
{
    const float* x     = (const float*)d_in[0];
    const float* e     = (const float*)d_in[1];
    const int*   ei    = (const int*)d_in[2];
    const float* attr1 = (const float*)d_in[3];
    const float* nc1   = (const float*)d_in[4];
    const int*   x_idx = (const int*)d_in[5];
    const float* eps1  = (const float*)d_in[6];
    const float* eps2  = (const float*)d_in[7];
    const float* W_ma  = (const float*)d_in[8];
    const float* b_ma  = (const float*)d_in[9];
    const float* W_mu  = (const float*)d_in[10];
    const float* b_mu  = (const float*)d_in[11];
    const float* W_ua  = (const float*)d_in[12];
    const float* b_ua  = (const float*)d_in[13];
    const float* W_uu  = (const float*)d_in[14];
    const float* b_uu  = (const float*)d_in[15];
    const float* W_c   = (const float*)d_in[16];
    const float* b_c   = (const float*)d_in[17];
    float* out = (float*)d_out;

    const int SMEM_UP  = (64 * 104 + 100 * 68) * 4;
    const int SMEM_FIN = (6 * 64 * 68) * 4;

    cudaFuncSetAttribute(k_upagg,     cudaFuncAttributeMaxDynamicSharedMemorySize, SMEM_UP);
    cudaFuncSetAttribute(k_edge_hmma, cudaFuncAttributeMaxDynamicSharedMemorySize, SM_EDGE_TOT);
    cudaFuncSetAttribute(k_final,     cudaFuncAttributeMaxDynamicSharedMemorySize, SMEM_FIN);

    // weight split prep + node branches
    k_prep_wb<<<(64 * 64 + 255) / 256, 256>>>(W_ma);
    k_node_pre<<<(Nn + 63) / 64, 256>>>(x, W_ma, b_ma, eps1);
    k_mlp_up<<<(Bb * Cc + 63) / 64, 256>>>(attr1, W_mu, b_mu);
    k_upagg<<<dim3((NMAXx + 63) / 64, Bb), 256, SMEM_UP>>>(nc1);

    // split-bf16 HMMA edge kernel, original edge order
    k_edge_hmma<<<Ee / 128, 256, SM_EDGE_TOT>>>(e, ei);

    // fused tail
    k_final<<<(Nn + 63) / 64, 256, SMEM_FIN>>>(x, x_idx, eps2, W_ua, b_ua,
                                               W_uu, b_uu, W_c, b_c, out);
}

// round 11
// speedup vs baseline: 2.0847x; 1.2467x over previous
#include <cuda_runtime.h>
#include <cuda_bf16.h>
#include <cstdint>

// Problem constants
#define Nn     50000
#define Dd     64
#define Ee     800000
#define Bb     50
#define NMAXx  1000
#define Cc     100

// ---------------------------------------------------------------------------
// Device scratch (no allocations allowed)
// ---------------------------------------------------------------------------
__device__ float g_xa[Nn * Dd];          // x @ W_ma[:64] + b_ma
__device__ float g_acc[Nn * Dd];         // (1+eps1)*x + segment_sum(msg)
__device__ float g_up[Nn * Dd];          // einsum result (flat [B*NMAX, D])
__device__ float g_msgup[Bb * Cc * Dd];  // relu(attr1 @ W_mu + b_mu)

// W_ma[64:128] split into bf16 hi/lo, n-major: g_Wbhi[n*64 + k]
__device__ unsigned short g_Wbhi[64 * 64];
__device__ unsigned short g_Wblo[64 * 64];

// ---------------------------------------------------------------------------
// mma.sync / ldmatrix helpers (base ISA, sm_80+)
// ---------------------------------------------------------------------------
__device__ __forceinline__ uint32_t smem_u32(const void* p) {
    uint32_t a;
    asm("{ .reg .u64 t; cvta.to.shared.u64 t, %1; cvt.u32.u64 %0, t; }"
        : "=r"(a) : "l"(p));
    return a;
}
__device__ __forceinline__ void ldsm_x4(uint32_t* r, uint32_t addr) {
    asm volatile("ldmatrix.sync.aligned.m8n8.x4.shared.b16 {%0,%1,%2,%3}, [%4];"
                 : "=r"(r[0]), "=r"(r[1]), "=r"(r[2]), "=r"(r[3]) : "r"(addr));
}
__device__ __forceinline__ void ldsm_x2(uint32_t* r, uint32_t addr) {
    asm volatile("ldmatrix.sync.aligned.m8n8.x2.shared.b16 {%0,%1}, [%2];"
                 : "=r"(r[0]), "=r"(r[1]) : "r"(addr));
}
__device__ __forceinline__ void mma_bf16(float* c, const uint32_t* a,
                                         const uint32_t* b) {
    asm volatile(
        "mma.sync.aligned.m16n8k16.row.col.f32.bf16.bf16.f32 "
        "{%0,%1,%2,%3}, {%4,%5,%6,%7}, {%8,%9}, {%0,%1,%2,%3};"
        : "+f"(c[0]), "+f"(c[1]), "+f"(c[2]), "+f"(c[3])
        : "r"(a[0]), "r"(a[1]), "r"(a[2]), "r"(a[3]), "r"(b[0]), "r"(b[1]));
}
__device__ __forceinline__ void red_add_v4(float* p, float a, float b,
                                           float c, float d) {
    asm volatile("red.global.add.v4.f32 [%0], {%1, %2, %3, %4};"
                 :: "l"(p), "f"(a), "f"(b), "f"(c), "f"(d) : "memory");
}

// ---------------------------------------------------------------------------
// Prep: W_ma[64+k][n] -> bf16 hi (RZ truncate) + lo (RN residual), n-major
// ---------------------------------------------------------------------------
__global__ void k_prep_wb(const float* __restrict__ W_ma) {
    int i = blockIdx.x * 256 + threadIdx.x;
    if (i >= 64 * 64) return;
    int k = i >> 6, n = i & 63;
    float w = W_ma[(64 + k) * 64 + n];
    uint32_t u = __float_as_uint(w);
    unsigned short hi = (unsigned short)(u >> 16);
    float hif = __uint_as_float(u & 0xFFFF0000u);
    float lo = w - hif;
    g_Wbhi[n * 64 + k] = hi;
    g_Wblo[n * 64 + k] = __bfloat16_as_ushort(__float2bfloat16(lo));
}

// ---------------------------------------------------------------------------
// Kernel 1: g_xa = x @ W_ma[0:64] + b_ma ;  g_acc = (1+eps1)*x
// ---------------------------------------------------------------------------
__global__ __launch_bounds__(256) void k_node_pre(
    const float* __restrict__ x, const float* __restrict__ W_ma,
    const float* __restrict__ b_ma, const float* __restrict__ eps1)
{
    __shared__ float Xs[64 * 68];
    __shared__ float Ws[64 * 68];
    __shared__ float bs[64];
    const int t = threadIdx.x;
    const int row0 = blockIdx.x * 64;

    for (int i = t; i < 64 * 16; i += 256) {
        int k = i / 16, c = (i % 16) * 4;
        *(float4*)(Ws + k * 68 + c) = *(const float4*)(W_ma + k * 64 + c);
    }
    if (t < 64) bs[t] = b_ma[t];
    for (int i = t; i < 64 * 16; i += 256) {
        int r = i / 16, c = (i % 16) * 4;
        int gr = row0 + r;
        float4 v = make_float4(0.f, 0.f, 0.f, 0.f);
        if (gr < Nn) v = *(const float4*)(x + gr * 64 + c);
        *(float4*)(Xs + r * 68 + c) = v;
    }
    __syncthreads();

    const int r0 = (t / 16) * 4, c0 = (t % 16) * 4;
    float acc[4][4];
#pragma unroll
    for (int i = 0; i < 4; i++)
#pragma unroll
        for (int j = 0; j < 4; j++) acc[i][j] = 0.f;

#pragma unroll
    for (int k = 0; k < 64; k += 4) {
        float4 a4[4];
#pragma unroll
        for (int i = 0; i < 4; i++) a4[i] = *(float4*)(Xs + (r0 + i) * 68 + k);
#pragma unroll
        for (int kk = 0; kk < 4; kk++) {
            float4 b4 = *(float4*)(Ws + (k + kk) * 68 + c0);
#pragma unroll
            for (int i = 0; i < 4; i++) {
                float a = ((const float*)&a4[i])[kk];
                acc[i][0] += a * b4.x; acc[i][1] += a * b4.y;
                acc[i][2] += a * b4.z; acc[i][3] += a * b4.w;
            }
        }
    }

    const float e1 = 1.0f + eps1[0];
#pragma unroll
    for (int i = 0; i < 4; i++) {
        int gr = row0 + r0 + i;
        if (gr < Nn) {
            float4 o;
            o.x = acc[i][0] + bs[c0 + 0];
            o.y = acc[i][1] + bs[c0 + 1];
            o.z = acc[i][2] + bs[c0 + 2];
            o.w = acc[i][3] + bs[c0 + 3];
            *(float4*)(g_xa + gr * 64 + c0) = o;
            float4 xv = *(float4*)(Xs + (r0 + i) * 68 + c0);
            float4 av = make_float4(e1 * xv.x, e1 * xv.y, e1 * xv.z, e1 * xv.w);
            *(float4*)(g_acc + gr * 64 + c0) = av;
        }
    }
}

// ---------------------------------------------------------------------------
// Kernel 2: g_msgup = relu(attr1 @ W_mu + b_mu)
// ---------------------------------------------------------------------------
__global__ __launch_bounds__(256) void k_mlp_up(
    const float* __restrict__ attr1, const float* __restrict__ W_mu,
    const float* __restrict__ b_mu)
{
    __shared__ float As[64 * 68];
    __shared__ float Ws[64 * 68];
    __shared__ float bs[64];
    const int t = threadIdx.x;
    const int row0 = blockIdx.x * 64;
    const int M = Bb * Cc;

    for (int i = t; i < 64 * 16; i += 256) {
        int k = i / 16, c = (i % 16) * 4;
        *(float4*)(Ws + k * 68 + c) = *(const float4*)(W_mu + k * 64 + c);
    }
    if (t < 64) bs[t] = b_mu[t];
    for (int i = t; i < 64 * 16; i += 256) {
        int r = i / 16, c = (i % 16) * 4;
        int gr = row0 + r;
        float4 v = make_float4(0.f, 0.f, 0.f, 0.f);
        if (gr < M) v = *(const float4*)(attr1 + gr * 64 + c);
        *(float4*)(As + r * 68 + c) = v;
    }
    __syncthreads();

    const int r0 = (t / 16) * 4, c0 = (t % 16) * 4;
    float acc[4][4];
#pragma unroll
    for (int i = 0; i < 4; i++)
#pragma unroll
        for (int j = 0; j < 4; j++) acc[i][j] = 0.f;

#pragma unroll
    for (int k = 0; k < 64; k += 4) {
        float4 a4[4];
#pragma unroll
        for (int i = 0; i < 4; i++) a4[i] = *(float4*)(As + (r0 + i) * 68 + k);
#pragma unroll
        for (int kk = 0; kk < 4; kk++) {
            float4 b4 = *(float4*)(Ws + (k + kk) * 68 + c0);
#pragma unroll
            for (int i = 0; i < 4; i++) {
                float a = ((const float*)&a4[i])[kk];
                acc[i][0] += a * b4.x; acc[i][1] += a * b4.y;
                acc[i][2] += a * b4.z; acc[i][3] += a * b4.w;
            }
        }
    }

#pragma unroll
    for (int i = 0; i < 4; i++) {
        int gr = row0 + r0 + i;
        if (gr < M) {
            float4 o;
            o.x = fmaxf(acc[i][0] + bs[c0 + 0], 0.f);
            o.y = fmaxf(acc[i][1] + bs[c0 + 1], 0.f);
            o.z = fmaxf(acc[i][2] + bs[c0 + 2], 0.f);
            o.w = fmaxf(acc[i][3] + bs[c0 + 3], 0.f);
            *(float4*)(g_msgup + gr * 64 + c0) = o;
        }
    }
}

// ---------------------------------------------------------------------------
// Kernel 3: g_up[b,n,:] = sum_c nc1[b,n,c] * g_msgup[b,c,:]
// ---------------------------------------------------------------------------
__global__ __launch_bounds__(256) void k_upagg(const float* __restrict__ nc1)
{
    extern __shared__ float sm[];
    float* Ns = sm;              // 64 x 104
    float* Ms = sm + 64 * 104;   // 100 x 68
    const int t = threadIdx.x;
    const int b = blockIdx.y;
    const int row0 = blockIdx.x * 64;

    for (int i = t; i < 64 * 25; i += 256) {
        int r = i / 25, c = (i % 25) * 4;
        int gr = row0 + r;
        float4 v = make_float4(0.f, 0.f, 0.f, 0.f);
        if (gr < NMAXx)
            v = *(const float4*)(nc1 + ((size_t)b * NMAXx + gr) * Cc + c);
        *(float4*)(Ns + r * 104 + c) = v;
    }
    for (int i = t; i < 100 * 16; i += 256) {
        int r = i / 16, c = (i % 16) * 4;
        *(float4*)(Ms + r * 68 + c) =
            *(const float4*)(g_msgup + ((size_t)b * Cc + r) * 64 + c);
    }
    __syncthreads();

    const int r0 = (t / 16) * 4, c0 = (t % 16) * 4;
    float acc[4][4];
#pragma unroll
    for (int i = 0; i < 4; i++)
#pragma unroll
        for (int j = 0; j < 4; j++) acc[i][j] = 0.f;

#pragma unroll
    for (int k = 0; k < 100; k += 4) {
        float4 a4[4];
#pragma unroll
        for (int i = 0; i < 4; i++) a4[i] = *(float4*)(Ns + (r0 + i) * 104 + k);
#pragma unroll
        for (int kk = 0; kk < 4; kk++) {
            float4 b4 = *(float4*)(Ms + (k + kk) * 68 + c0);
#pragma unroll
            for (int i = 0; i < 4; i++) {
                float a = ((const float*)&a4[i])[kk];
                acc[i][0] += a * b4.x; acc[i][1] += a * b4.y;
                acc[i][2] += a * b4.z; acc[i][3] += a * b4.w;
            }
        }
    }

#pragma unroll
    for (int i = 0; i < 4; i++) {
        int gr = row0 + r0 + i;
        if (gr < NMAXx) {
            float4 o = make_float4(acc[i][0], acc[i][1], acc[i][2], acc[i][3]);
            *(float4*)(g_up + ((size_t)b * NMAXx + gr) * 64 + c0) = o;
        }
    }
}

// ---------------------------------------------------------------------------
// Kernel 4: split-bf16 HMMA edge kernel (mma.sync m16n8k16, base ISA).
// Identical to R6 except the epilogue scatter uses red.global.add.v4.f32.
// ---------------------------------------------------------------------------
#define SMA_HI 0
#define SMA_LO 18432
#define SMB_HI 36864
#define SMB_LO 46080
#define SM_EDGE_TOT 55296

__global__ __launch_bounds__(256) void k_edge_hmma(
    const float* __restrict__ e, const int* __restrict__ ei)
{
    extern __shared__ char smc[];
    const uint32_t sbase = smem_u32(smc);
    const int t = threadIdx.x;
    const int w = t >> 5;
    const int lane = t & 31;
    const int e0 = blockIdx.x * 128;

    // B tiles: prepped bf16 n-major [n][64k], copy into stride-144B rows.
    {
        const uint4* srcH = (const uint4*)g_Wbhi;   // 512 uint4
        const uint4* srcL = (const uint4*)g_Wblo;
#pragma unroll
        for (int i = t; i < 512; i += 256) {
            int r = i >> 3, c = i & 7;
            *(uint4*)(smc + SMB_HI + r * 144 + c * 16) = srcH[i];
            *(uint4*)(smc + SMB_LO + r * 144 + c * 16) = srcL[i];
        }
    }

    // A tile: stream e rows, split fp32 -> bf16 hi (RZ) + lo (RN residual).
#pragma unroll
    for (int i = t; i < 2048; i += 256) {
        int r = i >> 4, q = i & 15;
        float4 v = *(const float4*)(e + (size_t)(e0 + r) * 64 + q * 4);
        uint32_t u0 = __float_as_uint(v.x), u1 = __float_as_uint(v.y);
        uint32_t u2 = __float_as_uint(v.z), u3 = __float_as_uint(v.w);
        uint32_t hi01 = (u0 >> 16) | (u1 & 0xFFFF0000u);
        uint32_t hi23 = (u2 >> 16) | (u3 & 0xFFFF0000u);
        float l0 = v.x - __uint_as_float(u0 & 0xFFFF0000u);
        float l1 = v.y - __uint_as_float(u1 & 0xFFFF0000u);
        float l2 = v.z - __uint_as_float(u2 & 0xFFFF0000u);
        float l3 = v.w - __uint_as_float(u3 & 0xFFFF0000u);
        __nv_bfloat162 p01 = __floats2bfloat162_rn(l0, l1);
        __nv_bfloat162 p23 = __floats2bfloat162_rn(l2, l3);
        uint32_t lo01 = *(uint32_t*)&p01;
        uint32_t lo23 = *(uint32_t*)&p23;
        *(uint2*)(smc + SMA_HI + r * 144 + q * 8) = make_uint2(hi01, hi23);
        *(uint2*)(smc + SMA_LO + r * 144 + q * 8) = make_uint2(lo01, lo23);
    }
    __syncthreads();

    // Preload all A fragments (4 k-tiles, hi+lo): 32 regs.
    uint32_t ah[4][4], al[4][4];
    {
        int arow = 16 * w + (lane & 15);
        int acolB = ((lane >> 4) * 8) * 2;
#pragma unroll
        for (int kt = 0; kt < 4; kt++) {
            uint32_t off = (uint32_t)(arow * 144 + kt * 32 + acolB);
            ldsm_x4(ah[kt], sbase + SMA_HI + off);
            ldsm_x4(al[kt], sbase + SMA_LO + off);
        }
    }
    __syncthreads();   // all A consumed -> Cstage may overlay Ahi/Alo

    float* cst = (float*)smc;   // Cstage [128][68]

    const int bl = lane & 15;
    const int brow = bl & 7;
    const int bkB = ((bl >> 3) * 8) * 2;

    const int grp = lane >> 2, tig = lane & 3;

#pragma unroll
    for (int nt = 0; nt < 8; nt++) {
        uint32_t bh[4][2], blo[4][2];
#pragma unroll
        for (int kt = 0; kt < 4; kt++) {
            uint32_t ba = (uint32_t)((nt * 8 + brow) * 144 + kt * 32 + bkB);
            ldsm_x2(bh[kt], sbase + SMB_HI + ba);
            ldsm_x2(blo[kt], sbase + SMB_LO + ba);
        }
        float c[4] = {0.f, 0.f, 0.f, 0.f};
#pragma unroll
        for (int kt = 0; kt < 4; kt++) {
            mma_bf16(c, ah[kt], bh[kt]);
            mma_bf16(c, ah[kt], blo[kt]);
            mma_bf16(c, al[kt], bh[kt]);
        }
        int row = 16 * w + grp;
        int col = nt * 8 + 2 * tig;
        *(float2*)(cst + row * 68 + col)       = make_float2(c[0], c[1]);
        *(float2*)(cst + (row + 8) * 68 + col) = make_float2(c[2], c[3]);
    }
    __syncthreads();

    // Epilogue: thread owns 8 rows x 4 cols; one red.v4 per (row, col-quad).
    {
        const int r0 = (t / 16) * 8, c0 = (t % 16) * 4;
        const int* __restrict__ srcp = ei;
        const int* __restrict__ dstp = ei + Ee;
#pragma unroll
        for (int i = 0; i < 8; i++) {
            int er = e0 + r0 + i;
            int s = srcp[er];
            int d = dstp[er];
            float4 xa = *(const float4*)(g_xa + (size_t)s * 64 + c0);
            float4 cw = *(const float4*)(cst + (r0 + i) * 68 + c0);
            float m0 = fmaxf(cw.x + xa.x, 0.f);
            float m1 = fmaxf(cw.y + xa.y, 0.f);
            float m2 = fmaxf(cw.z + xa.z, 0.f);
            float m3 = fmaxf(cw.w + xa.w, 0.f);
            red_add_v4(g_acc + (size_t)d * 64 + c0, m0, m1, m2, m3);
        }
    }
}

// ---------------------------------------------------------------------------
// Kernel 5 (fused tail): h1 = relu(g_acc @ W_ua + b_ua);
// h2 = relu((g_up[x_idx] + (1+eps2)*x) @ W_uu + b_uu);
// out = h1 @ W_c[0:64] + h2 @ W_c[64:128] + b_c
// ---------------------------------------------------------------------------
__global__ __launch_bounds__(256) void k_final(
    const float* __restrict__ x, const int* __restrict__ x_idx,
    const float* __restrict__ eps2,
    const float* __restrict__ W_ua, const float* __restrict__ b_ua,
    const float* __restrict__ W_uu, const float* __restrict__ b_uu,
    const float* __restrict__ W_c, const float* __restrict__ b_c,
    float* __restrict__ out)
{
    extern __shared__ float sm[];
    float* A1  = sm;
    float* A2  = A1 + 64 * 68;
    float* Wua = A2 + 64 * 68;
    float* Wuu = Wua + 64 * 68;
    float* Wc1 = Wuu + 64 * 68;
    float* Wc2 = Wc1 + 64 * 68;
    __shared__ float bua[64], buu[64], bcs[64];

    const int t = threadIdx.x;
    const int row0 = blockIdx.x * 64;
    const float e2 = 1.0f + eps2[0];

    for (int i = t; i < 64 * 16; i += 256) {
        int k = i / 16, c = (i % 16) * 4;
        *(float4*)(Wua + k * 68 + c) = *(const float4*)(W_ua + k * 64 + c);
        *(float4*)(Wuu + k * 68 + c) = *(const float4*)(W_uu + k * 64 + c);
        *(float4*)(Wc1 + k * 68 + c) = *(const float4*)(W_c + k * 64 + c);
        *(float4*)(Wc2 + k * 68 + c) = *(const float4*)(W_c + (64 + k) * 64 + c);
    }
    if (t < 64) { bua[t] = b_ua[t]; buu[t] = b_uu[t]; bcs[t] = b_c[t]; }

    for (int i = t; i < 64 * 16; i += 256) {
        int r = i / 16, c = (i % 16) * 4;
        int gr = row0 + r;
        float4 a1 = make_float4(0.f, 0.f, 0.f, 0.f);
        float4 a2 = make_float4(0.f, 0.f, 0.f, 0.f);
        if (gr < Nn) {
            a1 = *(const float4*)(g_acc + (size_t)gr * 64 + c);
            int xi = x_idx[gr];
            float4 u  = *(const float4*)(g_up + (size_t)xi * 64 + c);
            float4 xv = *(const float4*)(x + (size_t)gr * 64 + c);
            a2 = make_float4(u.x + e2 * xv.x, u.y + e2 * xv.y,
                             u.z + e2 * xv.z, u.w + e2 * xv.w);
        }
        *(float4*)(A1 + r * 68 + c) = a1;
        *(float4*)(A2 + r * 68 + c) = a2;
    }
    __syncthreads();

    const int r0 = (t / 16) * 4, c0 = (t % 16) * 4;
    float h1[4][4], h2[4][4];
#pragma unroll
    for (int i = 0; i < 4; i++)
#pragma unroll
        for (int j = 0; j < 4; j++) { h1[i][j] = 0.f; h2[i][j] = 0.f; }

#pragma unroll
    for (int k = 0; k < 64; k += 4) {
        float4 a14[4], a24[4];
#pragma unroll
        for (int i = 0; i < 4; i++) {
            a14[i] = *(float4*)(A1 + (r0 + i) * 68 + k);
            a24[i] = *(float4*)(A2 + (r0 + i) * 68 + k);
        }
#pragma unroll
        for (int kk = 0; kk < 4; kk++) {
            float4 b1 = *(float4*)(Wua + (k + kk) * 68 + c0);
            float4 b2 = *(float4*)(Wuu + (k + kk) * 68 + c0);
#pragma unroll
            for (int i = 0; i < 4; i++) {
                float a = ((const float*)&a14[i])[kk];
                float b = ((const float*)&a24[i])[kk];
                h1[i][0] += a * b1.x; h1[i][1] += a * b1.y;
                h1[i][2] += a * b1.z; h1[i][3] += a * b1.w;
                h2[i][0] += b * b2.x; h2[i][1] += b * b2.y;
                h2[i][2] += b * b2.z; h2[i][3] += b * b2.w;
            }
        }
    }
#pragma unroll
    for (int i = 0; i < 4; i++)
#pragma unroll
        for (int j = 0; j < 4; j++) {
            h1[i][j] = fmaxf(h1[i][j] + bua[c0 + j], 0.f);
            h2[i][j] = fmaxf(h2[i][j] + buu[c0 + j], 0.f);
        }
    __syncthreads();
#pragma unroll
    for (int i = 0; i < 4; i++)
#pragma unroll
        for (int j = 0; j < 4; j++) {
            A1[(r0 + i) * 68 + c0 + j] = h1[i][j];
            A2[(r0 + i) * 68 + c0 + j] = h2[i][j];
        }
    __syncthreads();

    float o[4][4];
#pragma unroll
    for (int i = 0; i < 4; i++)
#pragma unroll
        for (int j = 0; j < 4; j++) o[i][j] = 0.f;

#pragma unroll
    for (int k = 0; k < 64; k += 4) {
        float4 a14[4], a24[4];
#pragma unroll
        for (int i = 0; i < 4; i++) {
            a14[i] = *(float4*)(A1 + (r0 + i) * 68 + k);
            a24[i] = *(float4*)(A2 + (r0 + i) * 68 + k);
        }
#pragma unroll
        for (int kk = 0; kk < 4; kk++) {
            float4 b1 = *(float4*)(Wc1 + (k + kk) * 68 + c0);
            float4 b2 = *(float4*)(Wc2 + (k + kk) * 68 + c0);
#pragma unroll
            for (int i = 0; i < 4; i++) {
                float a = ((const float*)&a14[i])[kk];
                float b = ((const float*)&a24[i])[kk];
                o[i][0] += a * b1.x + b * b2.x;
                o[i][1] += a * b1.y + b * b2.y;
                o[i][2] += a * b1.z + b * b2.z;
                o[i][3] += a * b1.w + b * b2.w;
            }
        }
    }

#pragma unroll
    for (int i = 0; i < 4; i++) {
        int gr = row0 + r0 + i;
        if (gr < Nn) {
            float4 ov;
            ov.x = o[i][0] + bcs[c0 + 0];
            ov.y = o[i][1] + bcs[c0 + 1];
            ov.z = o[i][2] + bcs[c0 + 2];
            ov.w = o[i][3] + bcs[c0 + 3];
            *(float4*)(out + (size_t)gr * 64 + c0) = ov;
        }
    }
}

// ---------------------------------------------------------------------------
extern "C" void kernel_launch(void* const* d_in, const int* in_sizes, int n_in,
                              void* d_out, int out_size)
{
    const float* x     = (const float*)d_in[0];
    const float* e     = (const float*)d_in[1];
    const int*   ei    = (const int*)d_in[2];
    const float* attr1 = (const float*)d_in[3];
    const float* nc1   = (const float*)d_in[4];
    const int*   x_idx = (const int*)d_in[5];
    const float* eps1  = (const float*)d_in[6];
    const float* eps2  = (const float*)d_in[7];
    const float* W_ma  = (const float*)d_in[8];
    const float* b_ma  = (const float*)d_in[9];
    const float* W_mu  = (const float*)d_in[10];
    const float* b_mu  = (const float*)d_in[11];
    const float* W_ua  = (const float*)d_in[12];
    const float* b_ua  = (const float*)d_in[13];
    const float* W_uu  = (const float*)d_in[14];
    const float* b_uu  = (const float*)d_in[15];
    const float* W_c   = (const float*)d_in[16];
    const float* b_c   = (const float*)d_in[17];
    float* out = (float*)d_out;

    const int SMEM_UP  = (64 * 104 + 100 * 68) * 4;
    const int SMEM_FIN = (6 * 64 * 68) * 4;

    cudaFuncSetAttribute(k_upagg,     cudaFuncAttributeMaxDynamicSharedMemorySize, SMEM_UP);
    cudaFuncSetAttribute(k_edge_hmma, cudaFuncAttributeMaxDynamicSharedMemorySize, SM_EDGE_TOT);
    cudaFuncSetAttribute(k_final,     cudaFuncAttributeMaxDynamicSharedMemorySize, SMEM_FIN);

    // weight split prep + node branches
    k_prep_wb<<<(64 * 64 + 255) / 256, 256>>>(W_ma);
    k_node_pre<<<(Nn + 63) / 64, 256>>>(x, W_ma, b_ma, eps1);
    k_mlp_up<<<(Bb * Cc + 63) / 64, 256>>>(attr1, W_mu, b_mu);
    k_upagg<<<dim3((NMAXx + 63) / 64, Bb), 256, SMEM_UP>>>(nc1);

    // split-bf16 HMMA edge kernel + vector-red scatter
    k_edge_hmma<<<Ee / 128, 256, SM_EDGE_TOT>>>(e, ei);

    // fused tail
    k_final<<<(Nn + 63) / 64, 256, SMEM_FIN>>>(x, x_idx, eps2, W_ua, b_ua,
                                               W_uu, b_uu, W_c, b_c, out);
}

// round 12
// speedup vs baseline: 2.4688x; 1.1842x over previous
#include <cuda_runtime.h>
#include <cuda_bf16.h>
#include <cstdint>

// Problem constants
#define Nn     50000
#define Dd     64
#define Ee     800000
#define Bb     50
#define NMAXx  1000
#define Cc     100

// ---------------------------------------------------------------------------
// Device scratch (no allocations allowed)
// ---------------------------------------------------------------------------
__device__ float g_xa[Nn * Dd];          // x @ W_ma[:64] + b_ma
__device__ float g_acc[Nn * Dd];         // (1+eps1)*x + segment_sum(msg)
__device__ float g_up[Nn * Dd];          // einsum result (flat [B*NMAX, D])
__device__ float g_msgup[Bb * Cc * Dd];  // relu(attr1 @ W_mu + b_mu)

// W_ma[64:128] split into bf16 hi/lo, n-major: g_Wbhi[n*64 + k]
__device__ unsigned short g_Wbhi[64 * 64];
__device__ unsigned short g_Wblo[64 * 64];

// k_final weights: 8 tiles n-major [Wua_h, Wua_l, Wuu_h, Wuu_l,
//                                   Wc1_h, Wc1_l, Wc2_h, Wc2_l]
__device__ unsigned short g_Wf[8 * 4096];

// ---------------------------------------------------------------------------
// mma.sync / ldmatrix helpers (base ISA, sm_80+)
// ---------------------------------------------------------------------------
__device__ __forceinline__ uint32_t smem_u32(const void* p) {
    uint32_t a;
    asm("{ .reg .u64 t; cvta.to.shared.u64 t, %1; cvt.u32.u64 %0, t; }"
        : "=r"(a) : "l"(p));
    return a;
}
__device__ __forceinline__ void ldsm_x4(uint32_t* r, uint32_t addr) {
    asm volatile("ldmatrix.sync.aligned.m8n8.x4.shared.b16 {%0,%1,%2,%3}, [%4];"
                 : "=r"(r[0]), "=r"(r[1]), "=r"(r[2]), "=r"(r[3]) : "r"(addr));
}
__device__ __forceinline__ void ldsm_x2(uint32_t* r, uint32_t addr) {
    asm volatile("ldmatrix.sync.aligned.m8n8.x2.shared.b16 {%0,%1}, [%2];"
                 : "=r"(r[0]), "=r"(r[1]) : "r"(addr));
}
__device__ __forceinline__ void mma_bf16(float* c, const uint32_t* a,
                                         const uint32_t* b) {
    asm volatile(
        "mma.sync.aligned.m16n8k16.row.col.f32.bf16.bf16.f32 "
        "{%0,%1,%2,%3}, {%4,%5,%6,%7}, {%8,%9}, {%0,%1,%2,%3};"
        : "+f"(c[0]), "+f"(c[1]), "+f"(c[2]), "+f"(c[3])
        : "r"(a[0]), "r"(a[1]), "r"(a[2]), "r"(a[3]), "r"(b[0]), "r"(b[1]));
}
__device__ __forceinline__ void red_add_v4(float* p, float a, float b,
                                           float c, float d) {
    asm volatile("red.global.add.v4.f32 [%0], {%1, %2, %3, %4};"
                 :: "l"(p), "f"(a), "f"(b), "f"(c), "f"(d) : "memory");
}
__device__ __forceinline__ void split_hl(float w, unsigned short& hi,
                                         unsigned short& lo) {
    uint32_t u = __float_as_uint(w);
    hi = (unsigned short)(u >> 16);
    float l = w - __uint_as_float(u & 0xFFFF0000u);
    lo = __bfloat16_as_ushort(__float2bfloat16(l));
}

// ---------------------------------------------------------------------------
// Prep: W_ma[64:128] -> hi/lo n-major (edge kernel B operand)
// ---------------------------------------------------------------------------
__global__ void k_prep_wb(const float* __restrict__ W_ma) {
    int i = blockIdx.x * 256 + threadIdx.x;
    if (i >= 64 * 64) return;
    int k = i >> 6, n = i & 63;
    unsigned short h, l;
    split_hl(W_ma[(64 + k) * 64 + n], h, l);
    g_Wbhi[n * 64 + k] = h;
    g_Wblo[n * 64 + k] = l;
}

// ---------------------------------------------------------------------------
// Prep: W_ua, W_uu, W_c -> 8 hi/lo n-major tiles for k_final_hmma
// ---------------------------------------------------------------------------
__global__ void k_prep_wf(const float* __restrict__ W_ua,
                          const float* __restrict__ W_uu,
                          const float* __restrict__ W_c) {
    int i = blockIdx.x * 256 + threadIdx.x;
    if (i >= 4096) return;
    int k = i >> 6, n = i & 63;
    unsigned short h, l;
    split_hl(W_ua[k * 64 + n], h, l);
    g_Wf[0 * 4096 + n * 64 + k] = h;
    g_Wf[1 * 4096 + n * 64 + k] = l;
    split_hl(W_uu[k * 64 + n], h, l);
    g_Wf[2 * 4096 + n * 64 + k] = h;
    g_Wf[3 * 4096 + n * 64 + k] = l;
    split_hl(W_c[k * 64 + n], h, l);
    g_Wf[4 * 4096 + n * 64 + k] = h;
    g_Wf[5 * 4096 + n * 64 + k] = l;
    split_hl(W_c[(64 + k) * 64 + n], h, l);
    g_Wf[6 * 4096 + n * 64 + k] = h;
    g_Wf[7 * 4096 + n * 64 + k] = l;
}

// ---------------------------------------------------------------------------
// Kernel 1: g_xa = x @ W_ma[0:64] + b_ma ;  g_acc = (1+eps1)*x
// ---------------------------------------------------------------------------
__global__ __launch_bounds__(256) void k_node_pre(
    const float* __restrict__ x, const float* __restrict__ W_ma,
    const float* __restrict__ b_ma, const float* __restrict__ eps1)
{
    __shared__ float Xs[64 * 68];
    __shared__ float Ws[64 * 68];
    __shared__ float bs[64];
    const int t = threadIdx.x;
    const int row0 = blockIdx.x * 64;

    for (int i = t; i < 64 * 16; i += 256) {
        int k = i / 16, c = (i % 16) * 4;
        *(float4*)(Ws + k * 68 + c) = *(const float4*)(W_ma + k * 64 + c);
    }
    if (t < 64) bs[t] = b_ma[t];
    for (int i = t; i < 64 * 16; i += 256) {
        int r = i / 16, c = (i % 16) * 4;
        int gr = row0 + r;
        float4 v = make_float4(0.f, 0.f, 0.f, 0.f);
        if (gr < Nn) v = *(const float4*)(x + gr * 64 + c);
        *(float4*)(Xs + r * 68 + c) = v;
    }
    __syncthreads();

    const int r0 = (t / 16) * 4, c0 = (t % 16) * 4;
    float acc[4][4];
#pragma unroll
    for (int i = 0; i < 4; i++)
#pragma unroll
        for (int j = 0; j < 4; j++) acc[i][j] = 0.f;

#pragma unroll
    for (int k = 0; k < 64; k += 4) {
        float4 a4[4];
#pragma unroll
        for (int i = 0; i < 4; i++) a4[i] = *(float4*)(Xs + (r0 + i) * 68 + k);
#pragma unroll
        for (int kk = 0; kk < 4; kk++) {
            float4 b4 = *(float4*)(Ws + (k + kk) * 68 + c0);
#pragma unroll
            for (int i = 0; i < 4; i++) {
                float a = ((const float*)&a4[i])[kk];
                acc[i][0] += a * b4.x; acc[i][1] += a * b4.y;
                acc[i][2] += a * b4.z; acc[i][3] += a * b4.w;
            }
        }
    }

    const float e1 = 1.0f + eps1[0];
#pragma unroll
    for (int i = 0; i < 4; i++) {
        int gr = row0 + r0 + i;
        if (gr < Nn) {
            float4 o;
            o.x = acc[i][0] + bs[c0 + 0];
            o.y = acc[i][1] + bs[c0 + 1];
            o.z = acc[i][2] + bs[c0 + 2];
            o.w = acc[i][3] + bs[c0 + 3];
            *(float4*)(g_xa + gr * 64 + c0) = o;
            float4 xv = *(float4*)(Xs + (r0 + i) * 68 + c0);
            float4 av = make_float4(e1 * xv.x, e1 * xv.y, e1 * xv.z, e1 * xv.w);
            *(float4*)(g_acc + gr * 64 + c0) = av;
        }
    }
}

// ---------------------------------------------------------------------------
// Kernel 2: g_msgup = relu(attr1 @ W_mu + b_mu)
// ---------------------------------------------------------------------------
__global__ __launch_bounds__(256) void k_mlp_up(
    const float* __restrict__ attr1, const float* __restrict__ W_mu,
    const float* __restrict__ b_mu)
{
    __shared__ float As[64 * 68];
    __shared__ float Ws[64 * 68];
    __shared__ float bs[64];
    const int t = threadIdx.x;
    const int row0 = blockIdx.x * 64;
    const int M = Bb * Cc;

    for (int i = t; i < 64 * 16; i += 256) {
        int k = i / 16, c = (i % 16) * 4;
        *(float4*)(Ws + k * 68 + c) = *(const float4*)(W_mu + k * 64 + c);
    }
    if (t < 64) bs[t] = b_mu[t];
    for (int i = t; i < 64 * 16; i += 256) {
        int r = i / 16, c = (i % 16) * 4;
        int gr = row0 + r;
        float4 v = make_float4(0.f, 0.f, 0.f, 0.f);
        if (gr < M) v = *(const float4*)(attr1 + gr * 64 + c);
        *(float4*)(As + r * 68 + c) = v;
    }
    __syncthreads();

    const int r0 = (t / 16) * 4, c0 = (t % 16) * 4;
    float acc[4][4];
#pragma unroll
    for (int i = 0; i < 4; i++)
#pragma unroll
        for (int j = 0; j < 4; j++) acc[i][j] = 0.f;

#pragma unroll
    for (int k = 0; k < 64; k += 4) {
        float4 a4[4];
#pragma unroll
        for (int i = 0; i < 4; i++) a4[i] = *(float4*)(As + (r0 + i) * 68 + k);
#pragma unroll
        for (int kk = 0; kk < 4; kk++) {
            float4 b4 = *(float4*)(Ws + (k + kk) * 68 + c0);
#pragma unroll
            for (int i = 0; i < 4; i++) {
                float a = ((const float*)&a4[i])[kk];
                acc[i][0] += a * b4.x; acc[i][1] += a * b4.y;
                acc[i][2] += a * b4.z; acc[i][3] += a * b4.w;
            }
        }
    }

#pragma unroll
    for (int i = 0; i < 4; i++) {
        int gr = row0 + r0 + i;
        if (gr < M) {
            float4 o;
            o.x = fmaxf(acc[i][0] + bs[c0 + 0], 0.f);
            o.y = fmaxf(acc[i][1] + bs[c0 + 1], 0.f);
            o.z = fmaxf(acc[i][2] + bs[c0 + 2], 0.f);
            o.w = fmaxf(acc[i][3] + bs[c0 + 3], 0.f);
            *(float4*)(g_msgup + gr * 64 + c0) = o;
        }
    }
}

// ---------------------------------------------------------------------------
// Kernel 3: g_up[b,n,:] = sum_c nc1[b,n,c] * g_msgup[b,c,:]
// ---------------------------------------------------------------------------
__global__ __launch_bounds__(256) void k_upagg(const float* __restrict__ nc1)
{
    extern __shared__ float sm[];
    float* Ns = sm;              // 64 x 104
    float* Ms = sm + 64 * 104;   // 100 x 68
    const int t = threadIdx.x;
    const int b = blockIdx.y;
    const int row0 = blockIdx.x * 64;

    for (int i = t; i < 64 * 25; i += 256) {
        int r = i / 25, c = (i % 25) * 4;
        int gr = row0 + r;
        float4 v = make_float4(0.f, 0.f, 0.f, 0.f);
        if (gr < NMAXx)
            v = *(const float4*)(nc1 + ((size_t)b * NMAXx + gr) * Cc + c);
        *(float4*)(Ns + r * 104 + c) = v;
    }
    for (int i = t; i < 100 * 16; i += 256) {
        int r = i / 16, c = (i % 16) * 4;
        *(float4*)(Ms + r * 68 + c) =
            *(const float4*)(g_msgup + ((size_t)b * Cc + r) * 64 + c);
    }
    __syncthreads();

    const int r0 = (t / 16) * 4, c0 = (t % 16) * 4;
    float acc[4][4];
#pragma unroll
    for (int i = 0; i < 4; i++)
#pragma unroll
        for (int j = 0; j < 4; j++) acc[i][j] = 0.f;

#pragma unroll
    for (int k = 0; k < 100; k += 4) {
        float4 a4[4];
#pragma unroll
        for (int i = 0; i < 4; i++) a4[i] = *(float4*)(Ns + (r0 + i) * 104 + k);
#pragma unroll
        for (int kk = 0; kk < 4; kk++) {
            float4 b4 = *(float4*)(Ms + (k + kk) * 68 + c0);
#pragma unroll
            for (int i = 0; i < 4; i++) {
                float a = ((const float*)&a4[i])[kk];
                acc[i][0] += a * b4.x; acc[i][1] += a * b4.y;
                acc[i][2] += a * b4.z; acc[i][3] += a * b4.w;
            }
        }
    }

#pragma unroll
    for (int i = 0; i < 4; i++) {
        int gr = row0 + r0 + i;
        if (gr < NMAXx) {
            float4 o = make_float4(acc[i][0], acc[i][1], acc[i][2], acc[i][3]);
            *(float4*)(g_up + ((size_t)b * NMAXx + gr) * 64 + c0) = o;
        }
    }
}

// ---------------------------------------------------------------------------
// Kernel 4: split-bf16 HMMA edge kernel + red.v4 scatter (R11, unchanged).
// ---------------------------------------------------------------------------
#define SMA_HI 0
#define SMA_LO 18432
#define SMB_HI 36864
#define SMB_LO 46080
#define SM_EDGE_TOT 55296

__global__ __launch_bounds__(256) void k_edge_hmma(
    const float* __restrict__ e, const int* __restrict__ ei)
{
    extern __shared__ char smc[];
    const uint32_t sbase = smem_u32(smc);
    const int t = threadIdx.x;
    const int w = t >> 5;
    const int lane = t & 31;
    const int e0 = blockIdx.x * 128;

    {
        const uint4* srcH = (const uint4*)g_Wbhi;
        const uint4* srcL = (const uint4*)g_Wblo;
#pragma unroll
        for (int i = t; i < 512; i += 256) {
            int r = i >> 3, c = i & 7;
            *(uint4*)(smc + SMB_HI + r * 144 + c * 16) = srcH[i];
            *(uint4*)(smc + SMB_LO + r * 144 + c * 16) = srcL[i];
        }
    }

#pragma unroll
    for (int i = t; i < 2048; i += 256) {
        int r = i >> 4, q = i & 15;
        float4 v = *(const float4*)(e + (size_t)(e0 + r) * 64 + q * 4);
        uint32_t u0 = __float_as_uint(v.x), u1 = __float_as_uint(v.y);
        uint32_t u2 = __float_as_uint(v.z), u3 = __float_as_uint(v.w);
        uint32_t hi01 = (u0 >> 16) | (u1 & 0xFFFF0000u);
        uint32_t hi23 = (u2 >> 16) | (u3 & 0xFFFF0000u);
        float l0 = v.x - __uint_as_float(u0 & 0xFFFF0000u);
        float l1 = v.y - __uint_as_float(u1 & 0xFFFF0000u);
        float l2 = v.z - __uint_as_float(u2 & 0xFFFF0000u);
        float l3 = v.w - __uint_as_float(u3 & 0xFFFF0000u);
        __nv_bfloat162 p01 = __floats2bfloat162_rn(l0, l1);
        __nv_bfloat162 p23 = __floats2bfloat162_rn(l2, l3);
        uint32_t lo01 = *(uint32_t*)&p01;
        uint32_t lo23 = *(uint32_t*)&p23;
        *(uint2*)(smc + SMA_HI + r * 144 + q * 8) = make_uint2(hi01, hi23);
        *(uint2*)(smc + SMA_LO + r * 144 + q * 8) = make_uint2(lo01, lo23);
    }
    __syncthreads();

    uint32_t ah[4][4], al[4][4];
    {
        int arow = 16 * w + (lane & 15);
        int acolB = ((lane >> 4) * 8) * 2;
#pragma unroll
        for (int kt = 0; kt < 4; kt++) {
            uint32_t off = (uint32_t)(arow * 144 + kt * 32 + acolB);
            ldsm_x4(ah[kt], sbase + SMA_HI + off);
            ldsm_x4(al[kt], sbase + SMA_LO + off);
        }
    }
    __syncthreads();

    float* cst = (float*)smc;   // Cstage [128][68]

    const int bl = lane & 15;
    const int brow = bl & 7;
    const int bkB = ((bl >> 3) * 8) * 2;
    const int grp = lane >> 2, tig = lane & 3;

#pragma unroll
    for (int nt = 0; nt < 8; nt++) {
        uint32_t bh[4][2], blo[4][2];
#pragma unroll
        for (int kt = 0; kt < 4; kt++) {
            uint32_t ba = (uint32_t)((nt * 8 + brow) * 144 + kt * 32 + bkB);
            ldsm_x2(bh[kt], sbase + SMB_HI + ba);
            ldsm_x2(blo[kt], sbase + SMB_LO + ba);
        }
        float c[4] = {0.f, 0.f, 0.f, 0.f};
#pragma unroll
        for (int kt = 0; kt < 4; kt++) {
            mma_bf16(c, ah[kt], bh[kt]);
            mma_bf16(c, ah[kt], blo[kt]);
            mma_bf16(c, al[kt], bh[kt]);
        }
        int row = 16 * w + grp;
        int col = nt * 8 + 2 * tig;
        *(float2*)(cst + row * 68 + col)       = make_float2(c[0], c[1]);
        *(float2*)(cst + (row + 8) * 68 + col) = make_float2(c[2], c[3]);
    }
    __syncthreads();

    {
        const int r0 = (t / 16) * 8, c0 = (t % 16) * 4;
        const int* __restrict__ srcp = ei;
        const int* __restrict__ dstp = ei + Ee;
#pragma unroll
        for (int i = 0; i < 8; i++) {
            int er = e0 + r0 + i;
            int s = srcp[er];
            int d = dstp[er];
            float4 xa = *(const float4*)(g_xa + (size_t)s * 64 + c0);
            float4 cw = *(const float4*)(cst + (r0 + i) * 68 + c0);
            float m0 = fmaxf(cw.x + xa.x, 0.f);
            float m1 = fmaxf(cw.y + xa.y, 0.f);
            float m2 = fmaxf(cw.z + xa.z, 0.f);
            float m3 = fmaxf(cw.w + xa.w, 0.f);
            red_add_v4(g_acc + (size_t)d * 64 + c0, m0, m1, m2, m3);
        }
    }
}

// ---------------------------------------------------------------------------
// Kernel 5: HMMA fused tail. Per 128-node CTA:
//   h1 = relu(g_acc @ Wua + bua), h2 = relu((g_up[x_idx]+e2*x) @ Wuu + buu)
//   out = h1 @ Wc1 + h2 @ Wc2 + bc
// All GEMMs split-bf16 (3 products). h1/h2 re-split before phase 2.
// smem: FA hi/lo (2 x 18432) + 8 weight tiles (8 x 9216) + biases (768).
// ---------------------------------------------------------------------------
#define FA_HI 0
#define FA_LO 18432
#define FB_BASE 36864
#define FBIAS 110592
#define SM_FIN_TOT 111360

__global__ __launch_bounds__(256) void k_final_hmma(
    const float* __restrict__ x, const int* __restrict__ x_idx,
    const float* __restrict__ eps2,
    const float* __restrict__ b_ua, const float* __restrict__ b_uu,
    const float* __restrict__ b_c, float* __restrict__ out)
{
    extern __shared__ char smc[];
    const uint32_t sbase = smem_u32(smc);
    float* bias = (float*)(smc + FBIAS);
    const int t = threadIdx.x;
    const int w = t >> 5;
    const int lane = t & 31;
    const int row0 = blockIdx.x * 128;
    const float e2v = 1.0f + eps2[0];

    // Weight tiles: 8 x (64 rows x 144B stride)
    {
        const uint4* srcW = (const uint4*)g_Wf;   // 4096 uint4
#pragma unroll
        for (int i = t; i < 4096; i += 256) {
            int tile = i >> 9;
            int j = i & 511;
            int r = j >> 3, c = j & 7;
            *(uint4*)(smc + FB_BASE + tile * 9216 + r * 144 + c * 16) = srcW[i];
        }
    }
    if (t < 64) {
        bias[t] = b_ua[t];
        bias[64 + t] = b_uu[t];
        bias[128 + t] = b_c[t];
    }

    // A1 = g_acc rows, split -> FA
#pragma unroll
    for (int i = t; i < 2048; i += 256) {
        int r = i >> 4, q = i & 15;
        int gr = min(row0 + r, Nn - 1);
        float4 v = *(const float4*)(g_acc + (size_t)gr * 64 + q * 4);
        uint32_t u0 = __float_as_uint(v.x), u1 = __float_as_uint(v.y);
        uint32_t u2 = __float_as_uint(v.z), u3 = __float_as_uint(v.w);
        uint32_t hi01 = (u0 >> 16) | (u1 & 0xFFFF0000u);
        uint32_t hi23 = (u2 >> 16) | (u3 & 0xFFFF0000u);
        float l0 = v.x - __uint_as_float(u0 & 0xFFFF0000u);
        float l1 = v.y - __uint_as_float(u1 & 0xFFFF0000u);
        float l2 = v.z - __uint_as_float(u2 & 0xFFFF0000u);
        float l3 = v.w - __uint_as_float(u3 & 0xFFFF0000u);
        __nv_bfloat162 p01 = __floats2bfloat162_rn(l0, l1);
        __nv_bfloat162 p23 = __floats2bfloat162_rn(l2, l3);
        *(uint2*)(smc + FA_HI + r * 144 + q * 8) = make_uint2(hi01, hi23);
        *(uint2*)(smc + FA_LO + r * 144 + q * 8) =
            make_uint2(*(uint32_t*)&p01, *(uint32_t*)&p23);
    }
    __syncthreads();

    const int arow = 16 * w + (lane & 15);
    const int acolB = ((lane >> 4) * 8) * 2;
    const int bl = lane & 15;
    const int brow = bl & 7;
    const int bkB = ((bl >> 3) * 8) * 2;
    const int grp = lane >> 2, tig = lane & 3;
    const int myrow = 16 * w + grp;

    uint32_t a1h[4][4], a1l[4][4];
#pragma unroll
    for (int kt = 0; kt < 4; kt++) {
        uint32_t off = (uint32_t)(arow * 144 + kt * 32 + acolB);
        ldsm_x4(a1h[kt], sbase + FA_HI + off);
        ldsm_x4(a1l[kt], sbase + FA_LO + off);
    }
    __syncthreads();

    // A2 = g_up[x_idx] + e2*x, split -> FA
#pragma unroll
    for (int i = t; i < 2048; i += 256) {
        int r = i >> 4, q = i & 15;
        int gr = min(row0 + r, Nn - 1);
        int xi = x_idx[gr];
        float4 u = *(const float4*)(g_up + (size_t)xi * 64 + q * 4);
        float4 xv = *(const float4*)(x + (size_t)gr * 64 + q * 4);
        float4 v = make_float4(u.x + e2v * xv.x, u.y + e2v * xv.y,
                               u.z + e2v * xv.z, u.w + e2v * xv.w);
        uint32_t u0 = __float_as_uint(v.x), u1 = __float_as_uint(v.y);
        uint32_t u2 = __float_as_uint(v.z), u3 = __float_as_uint(v.w);
        uint32_t hi01 = (u0 >> 16) | (u1 & 0xFFFF0000u);
        uint32_t hi23 = (u2 >> 16) | (u3 & 0xFFFF0000u);
        float l0 = v.x - __uint_as_float(u0 & 0xFFFF0000u);
        float l1 = v.y - __uint_as_float(u1 & 0xFFFF0000u);
        float l2 = v.z - __uint_as_float(u2 & 0xFFFF0000u);
        float l3 = v.w - __uint_as_float(u3 & 0xFFFF0000u);
        __nv_bfloat162 p01 = __floats2bfloat162_rn(l0, l1);
        __nv_bfloat162 p23 = __floats2bfloat162_rn(l2, l3);
        *(uint2*)(smc + FA_HI + r * 144 + q * 8) = make_uint2(hi01, hi23);
        *(uint2*)(smc + FA_LO + r * 144 + q * 8) =
            make_uint2(*(uint32_t*)&p01, *(uint32_t*)&p23);
    }
    __syncthreads();

    uint32_t a2h[4][4], a2l[4][4];
#pragma unroll
    for (int kt = 0; kt < 4; kt++) {
        uint32_t off = (uint32_t)(arow * 144 + kt * 32 + acolB);
        ldsm_x4(a2h[kt], sbase + FA_HI + off);
        ldsm_x4(a2l[kt], sbase + FA_LO + off);
    }
    __syncthreads();   // FA free: safe to overwrite with h1

    // Phase 1a: h1 = relu(A1@Wua + bua) -> split -> FA
#pragma unroll
    for (int nt = 0; nt < 8; nt++) {
        uint32_t bh[4][2], blv[4][2];
#pragma unroll
        for (int kt = 0; kt < 4; kt++) {
            uint32_t ba = (uint32_t)((nt * 8 + brow) * 144 + kt * 32 + bkB);
            ldsm_x2(bh[kt],  sbase + FB_BASE + 0 * 9216 + ba);
            ldsm_x2(blv[kt], sbase + FB_BASE + 1 * 9216 + ba);
        }
        float c[4] = {0.f, 0.f, 0.f, 0.f};
#pragma unroll
        for (int kt = 0; kt < 4; kt++) {
            mma_bf16(c, a1h[kt], bh[kt]);
            mma_bf16(c, a1h[kt], blv[kt]);
            mma_bf16(c, a1l[kt], bh[kt]);
        }
        int col = nt * 8 + 2 * tig;
        float h0 = fmaxf(c[0] + bias[col], 0.f);
        float h1v = fmaxf(c[1] + bias[col + 1], 0.f);
        float h2v = fmaxf(c[2] + bias[col], 0.f);
        float h3v = fmaxf(c[3] + bias[col + 1], 0.f);
        uint32_t u0 = __float_as_uint(h0), u1 = __float_as_uint(h1v);
        uint32_t u2 = __float_as_uint(h2v), u3 = __float_as_uint(h3v);
        float l0 = h0 - __uint_as_float(u0 & 0xFFFF0000u);
        float l1 = h1v - __uint_as_float(u1 & 0xFFFF0000u);
        float l2 = h2v - __uint_as_float(u2 & 0xFFFF0000u);
        float l3 = h3v - __uint_as_float(u3 & 0xFFFF0000u);
        __nv_bfloat162 p01 = __floats2bfloat162_rn(l0, l1);
        __nv_bfloat162 p23 = __floats2bfloat162_rn(l2, l3);
        *(uint32_t*)(smc + FA_HI + myrow * 144 + col * 2) =
            (u0 >> 16) | (u1 & 0xFFFF0000u);
        *(uint32_t*)(smc + FA_LO + myrow * 144 + col * 2) = *(uint32_t*)&p01;
        *(uint32_t*)(smc + FA_HI + (myrow + 8) * 144 + col * 2) =
            (u2 >> 16) | (u3 & 0xFFFF0000u);
        *(uint32_t*)(smc + FA_LO + (myrow + 8) * 144 + col * 2) = *(uint32_t*)&p23;
    }
    __syncthreads();

    // Reload h1 fragments (reuse a1h/a1l)
#pragma unroll
    for (int kt = 0; kt < 4; kt++) {
        uint32_t off = (uint32_t)(arow * 144 + kt * 32 + acolB);
        ldsm_x4(a1h[kt], sbase + FA_HI + off);
        ldsm_x4(a1l[kt], sbase + FA_LO + off);
    }
    __syncthreads();

    // Phase 1b: h2 = relu(A2@Wuu + buu) -> split -> FA
#pragma unroll
    for (int nt = 0; nt < 8; nt++) {
        uint32_t bh[4][2], blv[4][2];
#pragma unroll
        for (int kt = 0; kt < 4; kt++) {
            uint32_t ba = (uint32_t)((nt * 8 + brow) * 144 + kt * 32 + bkB);
            ldsm_x2(bh[kt],  sbase + FB_BASE + 2 * 9216 + ba);
            ldsm_x2(blv[kt], sbase + FB_BASE + 3 * 9216 + ba);
        }
        float c[4] = {0.f, 0.f, 0.f, 0.f};
#pragma unroll
        for (int kt = 0; kt < 4; kt++) {
            mma_bf16(c, a2h[kt], bh[kt]);
            mma_bf16(c, a2h[kt], blv[kt]);
            mma_bf16(c, a2l[kt], bh[kt]);
        }
        int col = nt * 8 + 2 * tig;
        float h0 = fmaxf(c[0] + bias[64 + col], 0.f);
        float h1v = fmaxf(c[1] + bias[64 + col + 1], 0.f);
        float h2v = fmaxf(c[2] + bias[64 + col], 0.f);
        float h3v = fmaxf(c[3] + bias[64 + col + 1], 0.f);
        uint32_t u0 = __float_as_uint(h0), u1 = __float_as_uint(h1v);
        uint32_t u2 = __float_as_uint(h2v), u3 = __float_as_uint(h3v);
        float l0 = h0 - __uint_as_float(u0 & 0xFFFF0000u);
        float l1 = h1v - __uint_as_float(u1 & 0xFFFF0000u);
        float l2 = h2v - __uint_as_float(u2 & 0xFFFF0000u);
        float l3 = h3v - __uint_as_float(u3 & 0xFFFF0000u);
        __nv_bfloat162 p01 = __floats2bfloat162_rn(l0, l1);
        __nv_bfloat162 p23 = __floats2bfloat162_rn(l2, l3);
        *(uint32_t*)(smc + FA_HI + myrow * 144 + col * 2) =
            (u0 >> 16) | (u1 & 0xFFFF0000u);
        *(uint32_t*)(smc + FA_LO + myrow * 144 + col * 2) = *(uint32_t*)&p01;
        *(uint32_t*)(smc + FA_HI + (myrow + 8) * 144 + col * 2) =
            (u2 >> 16) | (u3 & 0xFFFF0000u);
        *(uint32_t*)(smc + FA_LO + (myrow + 8) * 144 + col * 2) = *(uint32_t*)&p23;
    }
    __syncthreads();

    // Reload h2 fragments (reuse a2h/a2l)
#pragma unroll
    for (int kt = 0; kt < 4; kt++) {
        uint32_t off = (uint32_t)(arow * 144 + kt * 32 + acolB);
        ldsm_x4(a2h[kt], sbase + FA_HI + off);
        ldsm_x4(a2l[kt], sbase + FA_LO + off);
    }

    // Phase 2: out = h1@Wc1 + h2@Wc2 + bc, direct global write
#pragma unroll
    for (int nt = 0; nt < 8; nt++) {
        uint32_t b1h[4][2], b1l[4][2], b2h[4][2], b2l[4][2];
#pragma unroll
        for (int kt = 0; kt < 4; kt++) {
            uint32_t ba = (uint32_t)((nt * 8 + brow) * 144 + kt * 32 + bkB);
            ldsm_x2(b1h[kt], sbase + FB_BASE + 4 * 9216 + ba);
            ldsm_x2(b1l[kt], sbase + FB_BASE + 5 * 9216 + ba);
            ldsm_x2(b2h[kt], sbase + FB_BASE + 6 * 9216 + ba);
            ldsm_x2(b2l[kt], sbase + FB_BASE + 7 * 9216 + ba);
        }
        float c[4] = {0.f, 0.f, 0.f, 0.f};
#pragma unroll
        for (int kt = 0; kt < 4; kt++) {
            mma_bf16(c, a1h[kt], b1h[kt]);
            mma_bf16(c, a1h[kt], b1l[kt]);
            mma_bf16(c, a1l[kt], b1h[kt]);
            mma_bf16(c, a2h[kt], b2h[kt]);
            mma_bf16(c, a2h[kt], b2l[kt]);
            mma_bf16(c, a2l[kt], b2h[kt]);
        }
        int col = nt * 8 + 2 * tig;
        int gr1 = row0 + myrow;
        int gr2 = gr1 + 8;
        if (gr1 < Nn)
            *(float2*)(out + (size_t)gr1 * 64 + col) =
                make_float2(c[0] + bias[128 + col], c[1] + bias[128 + col + 1]);
        if (gr2 < Nn)
            *(float2*)(out + (size_t)gr2 * 64 + col) =
                make_float2(c[2] + bias[128 + col], c[3] + bias[128 + col + 1]);
    }
}

// ---------------------------------------------------------------------------
extern "C" void kernel_launch(void* const* d_in, const int* in_sizes, int n_in,
                              void* d_out, int out_size)
{
    const float* x     = (const float*)d_in[0];
    const float* e     = (const float*)d_in[1];
    const int*   ei    = (const int*)d_in[2];
    const float* attr1 = (const float*)d_in[3];
    const float* nc1   = (const float*)d_in[4];
    const int*   x_idx = (const int*)d_in[5];
    const float* eps1  = (const float*)d_in[6];
    const float* eps2  = (const float*)d_in[7];
    const float* W_ma  = (const float*)d_in[8];
    const float* b_ma  = (const float*)d_in[9];
    const float* W_mu  = (const float*)d_in[10];
    const float* b_mu  = (const float*)d_in[11];
    const float* W_ua  = (const float*)d_in[12];
    const float* b_ua  = (const float*)d_in[13];
    const float* W_uu  = (const float*)d_in[14];
    const float* b_uu  = (const float*)d_in[15];
    const float* W_c   = (const float*)d_in[16];
    const float* b_c   = (const float*)d_in[17];
    float* out = (float*)d_out;

    const int SMEM_UP = (64 * 104 + 100 * 68) * 4;

    cudaFuncSetAttribute(k_upagg,      cudaFuncAttributeMaxDynamicSharedMemorySize, SMEM_UP);
    cudaFuncSetAttribute(k_edge_hmma,  cudaFuncAttributeMaxDynamicSharedMemorySize, SM_EDGE_TOT);
    cudaFuncSetAttribute(k_final_hmma, cudaFuncAttributeMaxDynamicSharedMemorySize, SM_FIN_TOT);

    // weight split prep + node branches
    k_prep_wb<<<(64 * 64 + 255) / 256, 256>>>(W_ma);
    k_prep_wf<<<(4096 + 255) / 256, 256>>>(W_ua, W_uu, W_c);
    k_node_pre<<<(Nn + 63) / 64, 256>>>(x, W_ma, b_ma, eps1);
    k_mlp_up<<<(Bb * Cc + 63) / 64, 256>>>(attr1, W_mu, b_mu);
    k_upagg<<<dim3((NMAXx + 63) / 64, Bb), 256, SMEM_UP>>>(nc1);

    // split-bf16 HMMA edge kernel + vector-red scatter
    k_edge_hmma<<<Ee / 128, 256, SM_EDGE_TOT>>>(e, ei);

    // HMMA fused tail
    k_final_hmma<<<(Nn + 127) / 128, 256, SM_FIN_TOT>>>(x, x_idx, eps2,
                                                        b_ua, b_uu, b_c, out);
}

// round 13
// speedup vs baseline: 2.7353x; 1.1080x over previous
#include <cuda_runtime.h>
#include <cuda_bf16.h>
#include <cstdint>

// Problem constants
#define Nn     50000
#define Dd     64
#define Ee     800000
#define Bb     50
#define NMAXx  1000
#define Cc     100

// ---------------------------------------------------------------------------
// Device scratch (no allocations allowed)
// ---------------------------------------------------------------------------
__device__ float g_xa[Nn * Dd];          // x @ W_ma[:64] + b_ma
__device__ float g_acc[Nn * Dd];         // (1+eps1)*x + segment_sum(msg)
__device__ float g_up[Nn * Dd];          // einsum result (flat [B*NMAX, D])
__device__ float g_msgup[Bb * Cc * Dd];  // relu(attr1 @ W_mu + b_mu)

// W_ma split n-major: first-half (node branch) and second-half (edge branch)
__device__ unsigned short g_Wn[2 * 4096];    // [W1_h, W1_l]
__device__ unsigned short g_Wbhi[64 * 64];
__device__ unsigned short g_Wblo[64 * 64];

// k_final weights: 8 tiles n-major
__device__ unsigned short g_Wf[8 * 4096];

// msgup split for upagg B operand: [b][n][112] (k zero-padded 100->112)
__device__ unsigned short g_msgupBh[Bb * 64 * 112];
__device__ unsigned short g_msgupBl[Bb * 64 * 112];

// ---------------------------------------------------------------------------
// mma.sync / ldmatrix helpers (base ISA, sm_80+)
// ---------------------------------------------------------------------------
__device__ __forceinline__ uint32_t smem_u32(const void* p) {
    uint32_t a;
    asm("{ .reg .u64 t; cvta.to.shared.u64 t, %1; cvt.u32.u64 %0, t; }"
        : "=r"(a) : "l"(p));
    return a;
}
__device__ __forceinline__ void ldsm_x4(uint32_t* r, uint32_t addr) {
    asm volatile("ldmatrix.sync.aligned.m8n8.x4.shared.b16 {%0,%1,%2,%3}, [%4];"
                 : "=r"(r[0]), "=r"(r[1]), "=r"(r[2]), "=r"(r[3]) : "r"(addr));
}
__device__ __forceinline__ void ldsm_x2(uint32_t* r, uint32_t addr) {
    asm volatile("ldmatrix.sync.aligned.m8n8.x2.shared.b16 {%0,%1}, [%2];"
                 : "=r"(r[0]), "=r"(r[1]) : "r"(addr));
}
__device__ __forceinline__ void mma_bf16(float* c, const uint32_t* a,
                                         const uint32_t* b) {
    asm volatile(
        "mma.sync.aligned.m16n8k16.row.col.f32.bf16.bf16.f32 "
        "{%0,%1,%2,%3}, {%4,%5,%6,%7}, {%8,%9}, {%0,%1,%2,%3};"
        : "+f"(c[0]), "+f"(c[1]), "+f"(c[2]), "+f"(c[3])
        : "r"(a[0]), "r"(a[1]), "r"(a[2]), "r"(a[3]), "r"(b[0]), "r"(b[1]));
}
__device__ __forceinline__ void red_add_v4(float* p, float a, float b,
                                           float c, float d) {
    asm volatile("red.global.add.v4.f32 [%0], {%1, %2, %3, %4};"
                 :: "l"(p), "f"(a), "f"(b), "f"(c), "f"(d) : "memory");
}
__device__ __forceinline__ void split_hl(float w, unsigned short& hi,
                                         unsigned short& lo) {
    uint32_t u = __float_as_uint(w);
    hi = (unsigned short)(u >> 16);
    float l = w - __uint_as_float(u & 0xFFFF0000u);
    lo = __bfloat16_as_ushort(__float2bfloat16(l));
}
// split float4 -> hi-pair / lo-pair words
__device__ __forceinline__ void split4(float4 v, uint2& hi, uint2& lo) {
    uint32_t u0 = __float_as_uint(v.x), u1 = __float_as_uint(v.y);
    uint32_t u2 = __float_as_uint(v.z), u3 = __float_as_uint(v.w);
    hi.x = (u0 >> 16) | (u1 & 0xFFFF0000u);
    hi.y = (u2 >> 16) | (u3 & 0xFFFF0000u);
    float l0 = v.x - __uint_as_float(u0 & 0xFFFF0000u);
    float l1 = v.y - __uint_as_float(u1 & 0xFFFF0000u);
    float l2 = v.z - __uint_as_float(u2 & 0xFFFF0000u);
    float l3 = v.w - __uint_as_float(u3 & 0xFFFF0000u);
    __nv_bfloat162 p01 = __floats2bfloat162_rn(l0, l1);
    __nv_bfloat162 p23 = __floats2bfloat162_rn(l2, l3);
    lo.x = *(uint32_t*)&p01;
    lo.y = *(uint32_t*)&p23;
}

// ---------------------------------------------------------------------------
// Prep: W_ma (both halves) -> hi/lo n-major
// ---------------------------------------------------------------------------
__global__ void k_prep_w(const float* __restrict__ W_ma) {
    int i = blockIdx.x * 256 + threadIdx.x;
    if (i >= 128 * 64) return;
    int k = i >> 6, n = i & 63;
    unsigned short h, l;
    split_hl(W_ma[k * 64 + n], h, l);
    if (k < 64) {
        g_Wn[0 * 4096 + n * 64 + k] = h;
        g_Wn[1 * 4096 + n * 64 + k] = l;
    } else {
        g_Wbhi[n * 64 + (k - 64)] = h;
        g_Wblo[n * 64 + (k - 64)] = l;
    }
}

// ---------------------------------------------------------------------------
// Prep: W_ua, W_uu, W_c -> 8 hi/lo n-major tiles for k_final_hmma
// ---------------------------------------------------------------------------
__global__ void k_prep_wf(const float* __restrict__ W_ua,
                          const float* __restrict__ W_uu,
                          const float* __restrict__ W_c) {
    int i = blockIdx.x * 256 + threadIdx.x;
    if (i >= 4096) return;
    int k = i >> 6, n = i & 63;
    unsigned short h, l;
    split_hl(W_ua[k * 64 + n], h, l);
    g_Wf[0 * 4096 + n * 64 + k] = h;
    g_Wf[1 * 4096 + n * 64 + k] = l;
    split_hl(W_uu[k * 64 + n], h, l);
    g_Wf[2 * 4096 + n * 64 + k] = h;
    g_Wf[3 * 4096 + n * 64 + k] = l;
    split_hl(W_c[k * 64 + n], h, l);
    g_Wf[4 * 4096 + n * 64 + k] = h;
    g_Wf[5 * 4096 + n * 64 + k] = l;
    split_hl(W_c[(64 + k) * 64 + n], h, l);
    g_Wf[6 * 4096 + n * 64 + k] = h;
    g_Wf[7 * 4096 + n * 64 + k] = l;
}

// ---------------------------------------------------------------------------
// Prep: g_msgup -> n-major hi/lo, k padded 100->112 (zeros)
// ---------------------------------------------------------------------------
__global__ void k_split_msgup() {
    int i = blockIdx.x * 256 + threadIdx.x;
    if (i >= Bb * 64 * 112) return;
    int c = i % 112;
    int tmp = i / 112;
    int n = tmp & 63;
    int b = tmp >> 6;
    float v = (c < Cc) ? g_msgup[((size_t)b * Cc + c) * 64 + n] : 0.f;
    unsigned short h, l;
    split_hl(v, h, l);
    g_msgupBh[i] = h;
    g_msgupBl[i] = l;
}

// ---------------------------------------------------------------------------
// Kernel 1 (HMMA): g_xa = x @ W_ma[0:64] + b_ma ; g_acc = (1+eps1)*x
// 128-row tiles, 256 threads, same fragment template as k_final.
// ---------------------------------------------------------------------------
#define NP_HI 0
#define NP_LO 18432
#define NP_B  36864
#define NP_BIAS 55296
#define SM_NP_TOT 55552

__global__ __launch_bounds__(256) void k_node_pre_hmma(
    const float* __restrict__ x, const float* __restrict__ eps1,
    const float* __restrict__ b_ma)
{
    extern __shared__ char smc[];
    const uint32_t sbase = smem_u32(smc);
    float* bias = (float*)(smc + NP_BIAS);
    const int t = threadIdx.x;
    const int w = t >> 5;
    const int lane = t & 31;
    const int row0 = blockIdx.x * 128;

    {
        const uint4* srcW = (const uint4*)g_Wn;   // 1024 uint4
#pragma unroll
        for (int i = t; i < 1024; i += 256) {
            int tile = i >> 9;
            int j = i & 511;
            int r = j >> 3, c = j & 7;
            *(uint4*)(smc + NP_B + tile * 9216 + r * 144 + c * 16) = srcW[i];
        }
    }
    if (t < 64) bias[t] = b_ma[t];
    const float e1 = 1.0f + eps1[0];

#pragma unroll
    for (int i = t; i < 2048; i += 256) {
        int r = i >> 4, q = i & 15;
        int gr0 = row0 + r;
        int gr = min(gr0, Nn - 1);
        float4 v = *(const float4*)(x + (size_t)gr * 64 + q * 4);
        if (gr0 < Nn) {
            float4 av = make_float4(e1 * v.x, e1 * v.y, e1 * v.z, e1 * v.w);
            *(float4*)(g_acc + (size_t)gr0 * 64 + q * 4) = av;
        }
        uint2 hi, lo;
        split4(v, hi, lo);
        *(uint2*)(smc + NP_HI + r * 144 + q * 8) = hi;
        *(uint2*)(smc + NP_LO + r * 144 + q * 8) = lo;
    }
    __syncthreads();

    const int arow = 16 * w + (lane & 15);
    const int acolB = ((lane >> 4) * 8) * 2;
    const int bl = lane & 15;
    const int brow = bl & 7;
    const int bkB = ((bl >> 3) * 8) * 2;
    const int grp = lane >> 2, tig = lane & 3;
    const int myrow = 16 * w + grp;

    uint32_t ah[4][4], al[4][4];
#pragma unroll
    for (int kt = 0; kt < 4; kt++) {
        uint32_t off = (uint32_t)(arow * 144 + kt * 32 + acolB);
        ldsm_x4(ah[kt], sbase + NP_HI + off);
        ldsm_x4(al[kt], sbase + NP_LO + off);
    }

#pragma unroll
    for (int nt = 0; nt < 8; nt++) {
        uint32_t bh[4][2], blv[4][2];
#pragma unroll
        for (int kt = 0; kt < 4; kt++) {
            uint32_t ba = (uint32_t)((nt * 8 + brow) * 144 + kt * 32 + bkB);
            ldsm_x2(bh[kt],  sbase + NP_B + 0 * 9216 + ba);
            ldsm_x2(blv[kt], sbase + NP_B + 1 * 9216 + ba);
        }
        float c[4] = {0.f, 0.f, 0.f, 0.f};
#pragma unroll
        for (int kt = 0; kt < 4; kt++) {
            mma_bf16(c, ah[kt], bh[kt]);
            mma_bf16(c, ah[kt], blv[kt]);
            mma_bf16(c, al[kt], bh[kt]);
        }
        int col = nt * 8 + 2 * tig;
        int gr1 = row0 + myrow;
        int gr2 = gr1 + 8;
        if (gr1 < Nn)
            *(float2*)(g_xa + (size_t)gr1 * 64 + col) =
                make_float2(c[0] + bias[col], c[1] + bias[col + 1]);
        if (gr2 < Nn)
            *(float2*)(g_xa + (size_t)gr2 * 64 + col) =
                make_float2(c[2] + bias[col], c[3] + bias[col + 1]);
    }
}

// ---------------------------------------------------------------------------
// Kernel 2: g_msgup = relu(attr1 @ W_mu + b_mu)  (scalar, unchanged)
// ---------------------------------------------------------------------------
__global__ __launch_bounds__(256) void k_mlp_up(
    const float* __restrict__ attr1, const float* __restrict__ W_mu,
    const float* __restrict__ b_mu)
{
    __shared__ float As[64 * 68];
    __shared__ float Ws[64 * 68];
    __shared__ float bs[64];
    const int t = threadIdx.x;
    const int row0 = blockIdx.x * 64;
    const int M = Bb * Cc;

    for (int i = t; i < 64 * 16; i += 256) {
        int k = i / 16, c = (i % 16) * 4;
        *(float4*)(Ws + k * 68 + c) = *(const float4*)(W_mu + k * 64 + c);
    }
    if (t < 64) bs[t] = b_mu[t];
    for (int i = t; i < 64 * 16; i += 256) {
        int r = i / 16, c = (i % 16) * 4;
        int gr = row0 + r;
        float4 v = make_float4(0.f, 0.f, 0.f, 0.f);
        if (gr < M) v = *(const float4*)(attr1 + gr * 64 + c);
        *(float4*)(As + r * 68 + c) = v;
    }
    __syncthreads();

    const int r0 = (t / 16) * 4, c0 = (t % 16) * 4;
    float acc[4][4];
#pragma unroll
    for (int i = 0; i < 4; i++)
#pragma unroll
        for (int j = 0; j < 4; j++) acc[i][j] = 0.f;

#pragma unroll
    for (int k = 0; k < 64; k += 4) {
        float4 a4[4];
#pragma unroll
        for (int i = 0; i < 4; i++) a4[i] = *(float4*)(As + (r0 + i) * 68 + k);
#pragma unroll
        for (int kk = 0; kk < 4; kk++) {
            float4 b4 = *(float4*)(Ws + (k + kk) * 68 + c0);
#pragma unroll
            for (int i = 0; i < 4; i++) {
                float a = ((const float*)&a4[i])[kk];
                acc[i][0] += a * b4.x; acc[i][1] += a * b4.y;
                acc[i][2] += a * b4.z; acc[i][3] += a * b4.w;
            }
        }
    }

#pragma unroll
    for (int i = 0; i < 4; i++) {
        int gr = row0 + r0 + i;
        if (gr < M) {
            float4 o;
            o.x = fmaxf(acc[i][0] + bs[c0 + 0], 0.f);
            o.y = fmaxf(acc[i][1] + bs[c0 + 1], 0.f);
            o.z = fmaxf(acc[i][2] + bs[c0 + 2], 0.f);
            o.w = fmaxf(acc[i][3] + bs[c0 + 3], 0.f);
            *(float4*)(g_msgup + gr * 64 + c0) = o;
        }
    }
}

// ---------------------------------------------------------------------------
// Kernel 3 (HMMA): g_up[b,n,:] = sum_c nc1[b,n,c] * msgup[b,c,:]
// K = 100 padded to 112 (7 k-tiles). A rows stride 240B. grid (8, 50).
// ---------------------------------------------------------------------------
#define UP_AHI 0
#define UP_ALO 30720
#define UP_BHI 61440
#define UP_BLO 76800
#define SM_UPG_TOT 92160

__global__ __launch_bounds__(256) void k_upagg_hmma(const float* __restrict__ nc1)
{
    extern __shared__ char smc[];
    const uint32_t sbase = smem_u32(smc);
    const int t = threadIdx.x;
    const int w = t >> 5;
    const int lane = t & 31;
    const int b = blockIdx.y;
    const int row0 = blockIdx.x * 128;

    // B: 64 rows x 112 bf16 (224B) at stride 240
#pragma unroll
    for (int i = t; i < 896; i += 256) {
        int r = i / 14, c = i % 14;
        size_t src = ((size_t)b * 64 + r) * 112 + c * 8;
        *(uint4*)(smc + UP_BHI + r * 240 + c * 16) = *(const uint4*)(g_msgupBh + src);
        *(uint4*)(smc + UP_BLO + r * 240 + c * 16) = *(const uint4*)(g_msgupBl + src);
    }

    // A: 128 rows x 100 f32 -> split, k 0..99
#pragma unroll
    for (int i = t; i < 3200; i += 256) {
        int r = i / 25, j = i % 25;
        int gr = min(row0 + r, NMAXx - 1);
        float4 v = *(const float4*)(nc1 + ((size_t)b * NMAXx + gr) * Cc + j * 4);
        uint2 hi, lo;
        split4(v, hi, lo);
        *(uint2*)(smc + UP_AHI + r * 240 + j * 8) = hi;
        *(uint2*)(smc + UP_ALO + r * 240 + j * 8) = lo;
    }
    // zero pad k 100..111 (bytes 200..224)
#pragma unroll
    for (int i = t; i < 384; i += 256) {
        int r = i / 3, j = i % 3;
        *(uint2*)(smc + UP_AHI + r * 240 + 200 + j * 8) = make_uint2(0u, 0u);
        *(uint2*)(smc + UP_ALO + r * 240 + 200 + j * 8) = make_uint2(0u, 0u);
    }
    __syncthreads();

    const int arow = 16 * w + (lane & 15);
    const int acolB = ((lane >> 4) * 8) * 2;
    const int bl = lane & 15;
    const int brow = bl & 7;
    const int bkB = ((bl >> 3) * 8) * 2;
    const int grp = lane >> 2, tig = lane & 3;
    const int myrow = 16 * w + grp;

    uint32_t ah[7][4], al[7][4];
#pragma unroll
    for (int kt = 0; kt < 7; kt++) {
        uint32_t off = (uint32_t)(arow * 240 + kt * 32 + acolB);
        ldsm_x4(ah[kt], sbase + UP_AHI + off);
        ldsm_x4(al[kt], sbase + UP_ALO + off);
    }

#pragma unroll
    for (int nt = 0; nt < 8; nt++) {
        float c[4] = {0.f, 0.f, 0.f, 0.f};
#pragma unroll
        for (int kt = 0; kt < 7; kt++) {
            uint32_t ba = (uint32_t)((nt * 8 + brow) * 240 + kt * 32 + bkB);
            uint32_t bh[2], blv[2];
            ldsm_x2(bh,  sbase + UP_BHI + ba);
            ldsm_x2(blv, sbase + UP_BLO + ba);
            mma_bf16(c, ah[kt], bh);
            mma_bf16(c, ah[kt], blv);
            mma_bf16(c, al[kt], bh);
        }
        int col = nt * 8 + 2 * tig;
        int gr1 = row0 + myrow;
        int gr2 = gr1 + 8;
        if (gr1 < NMAXx)
            *(float2*)(g_up + ((size_t)b * NMAXx + gr1) * 64 + col) =
                make_float2(c[0], c[1]);
        if (gr2 < NMAXx)
            *(float2*)(g_up + ((size_t)b * NMAXx + gr2) * 64 + col) =
                make_float2(c[2], c[3]);
    }
}

// ---------------------------------------------------------------------------
// Kernel 4: split-bf16 HMMA edge kernel + red.v4 scatter (unchanged).
// ---------------------------------------------------------------------------
#define SMA_HI 0
#define SMA_LO 18432
#define SMB_HI 36864
#define SMB_LO 46080
#define SM_EDGE_TOT 55296

__global__ __launch_bounds__(256) void k_edge_hmma(
    const float* __restrict__ e, const int* __restrict__ ei)
{
    extern __shared__ char smc[];
    const uint32_t sbase = smem_u32(smc);
    const int t = threadIdx.x;
    const int w = t >> 5;
    const int lane = t & 31;
    const int e0 = blockIdx.x * 128;

    {
        const uint4* srcH = (const uint4*)g_Wbhi;
        const uint4* srcL = (const uint4*)g_Wblo;
#pragma unroll
        for (int i = t; i < 512; i += 256) {
            int r = i >> 3, c = i & 7;
            *(uint4*)(smc + SMB_HI + r * 144 + c * 16) = srcH[i];
            *(uint4*)(smc + SMB_LO + r * 144 + c * 16) = srcL[i];
        }
    }

#pragma unroll
    for (int i = t; i < 2048; i += 256) {
        int r = i >> 4, q = i & 15;
        float4 v = *(const float4*)(e + (size_t)(e0 + r) * 64 + q * 4);
        uint2 hi, lo;
        split4(v, hi, lo);
        *(uint2*)(smc + SMA_HI + r * 144 + q * 8) = hi;
        *(uint2*)(smc + SMA_LO + r * 144 + q * 8) = lo;
    }
    __syncthreads();

    uint32_t ah[4][4], al[4][4];
    {
        int arow = 16 * w + (lane & 15);
        int acolB = ((lane >> 4) * 8) * 2;
#pragma unroll
        for (int kt = 0; kt < 4; kt++) {
            uint32_t off = (uint32_t)(arow * 144 + kt * 32 + acolB);
            ldsm_x4(ah[kt], sbase + SMA_HI + off);
            ldsm_x4(al[kt], sbase + SMA_LO + off);
        }
    }
    __syncthreads();

    float* cst = (float*)smc;   // Cstage [128][68]

    const int bl = lane & 15;
    const int brow = bl & 7;
    const int bkB = ((bl >> 3) * 8) * 2;
    const int grp = lane >> 2, tig = lane & 3;

#pragma unroll
    for (int nt = 0; nt < 8; nt++) {
        uint32_t bh[4][2], blo[4][2];
#pragma unroll
        for (int kt = 0; kt < 4; kt++) {
            uint32_t ba = (uint32_t)((nt * 8 + brow) * 144 + kt * 32 + bkB);
            ldsm_x2(bh[kt], sbase + SMB_HI + ba);
            ldsm_x2(blo[kt], sbase + SMB_LO + ba);
        }
        float c[4] = {0.f, 0.f, 0.f, 0.f};
#pragma unroll
        for (int kt = 0; kt < 4; kt++) {
            mma_bf16(c, ah[kt], bh[kt]);
            mma_bf16(c, ah[kt], blo[kt]);
            mma_bf16(c, al[kt], bh[kt]);
        }
        int row = 16 * w + grp;
        int col = nt * 8 + 2 * tig;
        *(float2*)(cst + row * 68 + col)       = make_float2(c[0], c[1]);
        *(float2*)(cst + (row + 8) * 68 + col) = make_float2(c[2], c[3]);
    }
    __syncthreads();

    {
        const int r0 = (t / 16) * 8, c0 = (t % 16) * 4;
        const int* __restrict__ srcp = ei;
        const int* __restrict__ dstp = ei + Ee;
#pragma unroll
        for (int i = 0; i < 8; i++) {
            int er = e0 + r0 + i;
            int s = srcp[er];
            int d = dstp[er];
            float4 xa = *(const float4*)(g_xa + (size_t)s * 64 + c0);
            float4 cw = *(const float4*)(cst + (r0 + i) * 68 + c0);
            float m0 = fmaxf(cw.x + xa.x, 0.f);
            float m1 = fmaxf(cw.y + xa.y, 0.f);
            float m2 = fmaxf(cw.z + xa.z, 0.f);
            float m3 = fmaxf(cw.w + xa.w, 0.f);
            red_add_v4(g_acc + (size_t)d * 64 + c0, m0, m1, m2, m3);
        }
    }
}

// ---------------------------------------------------------------------------
// Kernel 5: HMMA fused tail (unchanged from R12).
// ---------------------------------------------------------------------------
#define FA_HI 0
#define FA_LO 18432
#define FB_BASE 36864
#define FBIAS 110592
#define SM_FIN_TOT 111360

__global__ __launch_bounds__(256) void k_final_hmma(
    const float* __restrict__ x, const int* __restrict__ x_idx,
    const float* __restrict__ eps2,
    const float* __restrict__ b_ua, const float* __restrict__ b_uu,
    const float* __restrict__ b_c, float* __restrict__ out)
{
    extern __shared__ char smc[];
    const uint32_t sbase = smem_u32(smc);
    float* bias = (float*)(smc + FBIAS);
    const int t = threadIdx.x;
    const int w = t >> 5;
    const int lane = t & 31;
    const int row0 = blockIdx.x * 128;
    const float e2v = 1.0f + eps2[0];

    {
        const uint4* srcW = (const uint4*)g_Wf;
#pragma unroll
        for (int i = t; i < 4096; i += 256) {
            int tile = i >> 9;
            int j = i & 511;
            int r = j >> 3, c = j & 7;
            *(uint4*)(smc + FB_BASE + tile * 9216 + r * 144 + c * 16) = srcW[i];
        }
    }
    if (t < 64) {
        bias[t] = b_ua[t];
        bias[64 + t] = b_uu[t];
        bias[128 + t] = b_c[t];
    }

#pragma unroll
    for (int i = t; i < 2048; i += 256) {
        int r = i >> 4, q = i & 15;
        int gr = min(row0 + r, Nn - 1);
        float4 v = *(const float4*)(g_acc + (size_t)gr * 64 + q * 4);
        uint2 hi, lo;
        split4(v, hi, lo);
        *(uint2*)(smc + FA_HI + r * 144 + q * 8) = hi;
        *(uint2*)(smc + FA_LO + r * 144 + q * 8) = lo;
    }
    __syncthreads();

    const int arow = 16 * w + (lane & 15);
    const int acolB = ((lane >> 4) * 8) * 2;
    const int bl = lane & 15;
    const int brow = bl & 7;
    const int bkB = ((bl >> 3) * 8) * 2;
    const int grp = lane >> 2, tig = lane & 3;
    const int myrow = 16 * w + grp;

    uint32_t a1h[4][4], a1l[4][4];
#pragma unroll
    for (int kt = 0; kt < 4; kt++) {
        uint32_t off = (uint32_t)(arow * 144 + kt * 32 + acolB);
        ldsm_x4(a1h[kt], sbase + FA_HI + off);
        ldsm_x4(a1l[kt], sbase + FA_LO + off);
    }
    __syncthreads();

#pragma unroll
    for (int i = t; i < 2048; i += 256) {
        int r = i >> 4, q = i & 15;
        int gr = min(row0 + r, Nn - 1);
        int xi = x_idx[gr];
        float4 u = *(const float4*)(g_up + (size_t)xi * 64 + q * 4);
        float4 xv = *(const float4*)(x + (size_t)gr * 64 + q * 4);
        float4 v = make_float4(u.x + e2v * xv.x, u.y + e2v * xv.y,
                               u.z + e2v * xv.z, u.w + e2v * xv.w);
        uint2 hi, lo;
        split4(v, hi, lo);
        *(uint2*)(smc + FA_HI + r * 144 + q * 8) = hi;
        *(uint2*)(smc + FA_LO + r * 144 + q * 8) = lo;
    }
    __syncthreads();

    uint32_t a2h[4][4], a2l[4][4];
#pragma unroll
    for (int kt = 0; kt < 4; kt++) {
        uint32_t off = (uint32_t)(arow * 144 + kt * 32 + acolB);
        ldsm_x4(a2h[kt], sbase + FA_HI + off);
        ldsm_x4(a2l[kt], sbase + FA_LO + off);
    }
    __syncthreads();

    // Phase 1a: h1 = relu(A1@Wua + bua) -> split -> FA
#pragma unroll
    for (int nt = 0; nt < 8; nt++) {
        uint32_t bh[4][2], blv[4][2];
#pragma unroll
        for (int kt = 0; kt < 4; kt++) {
            uint32_t ba = (uint32_t)((nt * 8 + brow) * 144 + kt * 32 + bkB);
            ldsm_x2(bh[kt],  sbase + FB_BASE + 0 * 9216 + ba);
            ldsm_x2(blv[kt], sbase + FB_BASE + 1 * 9216 + ba);
        }
        float c[4] = {0.f, 0.f, 0.f, 0.f};
#pragma unroll
        for (int kt = 0; kt < 4; kt++) {
            mma_bf16(c, a1h[kt], bh[kt]);
            mma_bf16(c, a1h[kt], blv[kt]);
            mma_bf16(c, a1l[kt], bh[kt]);
        }
        int col = nt * 8 + 2 * tig;
        float h0 = fmaxf(c[0] + bias[col], 0.f);
        float h1v = fmaxf(c[1] + bias[col + 1], 0.f);
        float h2v = fmaxf(c[2] + bias[col], 0.f);
        float h3v = fmaxf(c[3] + bias[col + 1], 0.f);
        uint2 hiA, loA;
        split4(make_float4(h0, h1v, h2v, h3v), hiA, loA);
        *(uint32_t*)(smc + FA_HI + myrow * 144 + col * 2) = hiA.x;
        *(uint32_t*)(smc + FA_LO + myrow * 144 + col * 2) = loA.x;
        *(uint32_t*)(smc + FA_HI + (myrow + 8) * 144 + col * 2) = hiA.y;
        *(uint32_t*)(smc + FA_LO + (myrow + 8) * 144 + col * 2) = loA.y;
    }
    __syncthreads();

#pragma unroll
    for (int kt = 0; kt < 4; kt++) {
        uint32_t off = (uint32_t)(arow * 144 + kt * 32 + acolB);
        ldsm_x4(a1h[kt], sbase + FA_HI + off);
        ldsm_x4(a1l[kt], sbase + FA_LO + off);
    }
    __syncthreads();

    // Phase 1b: h2 = relu(A2@Wuu + buu) -> split -> FA
#pragma unroll
    for (int nt = 0; nt < 8; nt++) {
        uint32_t bh[4][2], blv[4][2];
#pragma unroll
        for (int kt = 0; kt < 4; kt++) {
            uint32_t ba = (uint32_t)((nt * 8 + brow) * 144 + kt * 32 + bkB);
            ldsm_x2(bh[kt],  sbase + FB_BASE + 2 * 9216 + ba);
            ldsm_x2(blv[kt], sbase + FB_BASE + 3 * 9216 + ba);
        }
        float c[4] = {0.f, 0.f, 0.f, 0.f};
#pragma unroll
        for (int kt = 0; kt < 4; kt++) {
            mma_bf16(c, a2h[kt], bh[kt]);
            mma_bf16(c, a2h[kt], blv[kt]);
            mma_bf16(c, a2l[kt], bh[kt]);
        }
        int col = nt * 8 + 2 * tig;
        float h0 = fmaxf(c[0] + bias[64 + col], 0.f);
        float h1v = fmaxf(c[1] + bias[64 + col + 1], 0.f);
        float h2v = fmaxf(c[2] + bias[64 + col], 0.f);
        float h3v = fmaxf(c[3] + bias[64 + col + 1], 0.f);
        uint2 hiA, loA;
        split4(make_float4(h0, h1v, h2v, h3v), hiA, loA);
        *(uint32_t*)(smc + FA_HI + myrow * 144 + col * 2) = hiA.x;
        *(uint32_t*)(smc + FA_LO + myrow * 144 + col * 2) = loA.x;
        *(uint32_t*)(smc + FA_HI + (myrow + 8) * 144 + col * 2) = hiA.y;
        *(uint32_t*)(smc + FA_LO + (myrow + 8) * 144 + col * 2) = loA.y;
    }
    __syncthreads();

#pragma unroll
    for (int kt = 0; kt < 4; kt++) {
        uint32_t off = (uint32_t)(arow * 144 + kt * 32 + acolB);
        ldsm_x4(a2h[kt], sbase + FA_HI + off);
        ldsm_x4(a2l[kt], sbase + FA_LO + off);
    }

    // Phase 2: out = h1@Wc1 + h2@Wc2 + bc
#pragma unroll
    for (int nt = 0; nt < 8; nt++) {
        uint32_t b1h[4][2], b1l[4][2], b2h[4][2], b2l[4][2];
#pragma unroll
        for (int kt = 0; kt < 4; kt++) {
            uint32_t ba = (uint32_t)((nt * 8 + brow) * 144 + kt * 32 + bkB);
            ldsm_x2(b1h[kt], sbase + FB_BASE + 4 * 9216 + ba);
            ldsm_x2(b1l[kt], sbase + FB_BASE + 5 * 9216 + ba);
            ldsm_x2(b2h[kt], sbase + FB_BASE + 6 * 9216 + ba);
            ldsm_x2(b2l[kt], sbase + FB_BASE + 7 * 9216 + ba);
        }
        float c[4] = {0.f, 0.f, 0.f, 0.f};
#pragma unroll
        for (int kt = 0; kt < 4; kt++) {
            mma_bf16(c, a1h[kt], b1h[kt]);
            mma_bf16(c, a1h[kt], b1l[kt]);
            mma_bf16(c, a1l[kt], b1h[kt]);
            mma_bf16(c, a2h[kt], b2h[kt]);
            mma_bf16(c, a2h[kt], b2l[kt]);
            mma_bf16(c, a2l[kt], b2h[kt]);
        }
        int col = nt * 8 + 2 * tig;
        int gr1 = row0 + myrow;
        int gr2 = gr1 + 8;
        if (gr1 < Nn)
            *(float2*)(out + (size_t)gr1 * 64 + col) =
                make_float2(c[0] + bias[128 + col], c[1] + bias[128 + col + 1]);
        if (gr2 < Nn)
            *(float2*)(out + (size_t)gr2 * 64 + col) =
                make_float2(c[2] + bias[128 + col], c[3] + bias[128 + col + 1]);
    }
}

// ---------------------------------------------------------------------------
extern "C" void kernel_launch(void* const* d_in, const int* in_sizes, int n_in,
                              void* d_out, int out_size)
{
    const float* x     = (const float*)d_in[0];
    const float* e     = (const float*)d_in[1];
    const int*   ei    = (const int*)d_in[2];
    const float* attr1 = (const float*)d_in[3];
    const float* nc1   = (const float*)d_in[4];
    const int*   x_idx = (const int*)d_in[5];
    const float* eps1  = (const float*)d_in[6];
    const float* eps2  = (const float*)d_in[7];
    const float* W_ma  = (const float*)d_in[8];
    const float* b_ma  = (const float*)d_in[9];
    const float* W_mu  = (const float*)d_in[10];
    const float* b_mu  = (const float*)d_in[11];
    const float* W_ua  = (const float*)d_in[12];
    const float* b_ua  = (const float*)d_in[13];
    const float* W_uu  = (const float*)d_in[14];
    const float* b_uu  = (const float*)d_in[15];
    const float* W_c   = (const float*)d_in[16];
    const float* b_c   = (const float*)d_in[17];
    float* out = (float*)d_out;

    cudaFuncSetAttribute(k_node_pre_hmma, cudaFuncAttributeMaxDynamicSharedMemorySize, SM_NP_TOT);
    cudaFuncSetAttribute(k_upagg_hmma,    cudaFuncAttributeMaxDynamicSharedMemorySize, SM_UPG_TOT);
    cudaFuncSetAttribute(k_edge_hmma,     cudaFuncAttributeMaxDynamicSharedMemorySize, SM_EDGE_TOT);
    cudaFuncSetAttribute(k_final_hmma,    cudaFuncAttributeMaxDynamicSharedMemorySize, SM_FIN_TOT);

    // weight prep
    k_prep_w<<<(128 * 64 + 255) / 256, 256>>>(W_ma);
    k_prep_wf<<<(4096 + 255) / 256, 256>>>(W_ua, W_uu, W_c);

    // node branch (HMMA) + cluster branch
    k_node_pre_hmma<<<(Nn + 127) / 128, 256, SM_NP_TOT>>>(x, eps1, b_ma);
    k_mlp_up<<<(Bb * Cc + 63) / 64, 256>>>(attr1, W_mu, b_mu);
    k_split_msgup<<<(Bb * 64 * 112 + 255) / 256, 256>>>();
    k_upagg_hmma<<<dim3(8, Bb), 256, SM_UPG_TOT>>>(nc1);

    // edge kernel (HMMA + red.v4)
    k_edge_hmma<<<Ee / 128, 256, SM_EDGE_TOT>>>(e, ei);

    // fused tail (HMMA)
    k_final_hmma<<<(Nn + 127) / 128, 256, SM_FIN_TOT>>>(x, x_idx, eps2,
                                                        b_ua, b_uu, b_c, out);
}

// round 14
// speedup vs baseline: 2.8738x; 1.0506x over previous
#include <cuda_runtime.h>
#include <cuda_bf16.h>
#include <cstdint>

// Problem constants
#define Nn     50000
#define Dd     64
#define Ee     800000
#define Bb     50
#define NMAXx  1000
#define Cc     100

// ---------------------------------------------------------------------------
// Device scratch (no allocations allowed)
// ---------------------------------------------------------------------------
__device__ float g_xa[Nn * Dd];          // x @ W_ma[:64] + b_ma
__device__ float g_acc[Nn * Dd];         // (1+eps1)*x + segment_sum(msg)
__device__ float g_up[Nn * Dd];          // einsum result (flat [B*NMAX, D])

// W_ma split n-major: first-half (node branch) and second-half (edge branch)
__device__ unsigned short g_Wn[2 * 4096];    // [W1_h, W1_l]
__device__ unsigned short g_Wbhi[64 * 64];
__device__ unsigned short g_Wblo[64 * 64];

// W_mu split n-major (mlp branch)
__device__ unsigned short g_Wmu[2 * 4096];

// k_final weights: 8 tiles n-major
__device__ unsigned short g_Wf[8 * 4096];

// msgup split for upagg B operand: [b][n][112] (k zero-padded 100->112)
__device__ unsigned short g_msgupBh[Bb * 64 * 112];
__device__ unsigned short g_msgupBl[Bb * 64 * 112];

// ---------------------------------------------------------------------------
// mma.sync / ldmatrix helpers (base ISA, sm_80+)
// ---------------------------------------------------------------------------
__device__ __forceinline__ uint32_t smem_u32(const void* p) {
    uint32_t a;
    asm("{ .reg .u64 t; cvta.to.shared.u64 t, %1; cvt.u32.u64 %0, t; }"
        : "=r"(a) : "l"(p));
    return a;
}
__device__ __forceinline__ void ldsm_x4(uint32_t* r, uint32_t addr) {
    asm volatile("ldmatrix.sync.aligned.m8n8.x4.shared.b16 {%0,%1,%2,%3}, [%4];"
                 : "=r"(r[0]), "=r"(r[1]), "=r"(r[2]), "=r"(r[3]) : "r"(addr));
}
__device__ __forceinline__ void ldsm_x2(uint32_t* r, uint32_t addr) {
    asm volatile("ldmatrix.sync.aligned.m8n8.x2.shared.b16 {%0,%1}, [%2];"
                 : "=r"(r[0]), "=r"(r[1]) : "r"(addr));
}
__device__ __forceinline__ void mma_bf16(float* c, const uint32_t* a,
                                         const uint32_t* b) {
    asm volatile(
        "mma.sync.aligned.m16n8k16.row.col.f32.bf16.bf16.f32 "
        "{%0,%1,%2,%3}, {%4,%5,%6,%7}, {%8,%9}, {%0,%1,%2,%3};"
        : "+f"(c[0]), "+f"(c[1]), "+f"(c[2]), "+f"(c[3])
        : "r"(a[0]), "r"(a[1]), "r"(a[2]), "r"(a[3]), "r"(b[0]), "r"(b[1]));
}
__device__ __forceinline__ void red_add_v4(float* p, float a, float b,
                                           float c, float d) {
    asm volatile("red.global.add.v4.f32 [%0], {%1, %2, %3, %4};"
                 :: "l"(p), "f"(a), "f"(b), "f"(c), "f"(d) : "memory");
}
__device__ __forceinline__ void split_hl(float w, unsigned short& hi,
                                         unsigned short& lo) {
    uint32_t u = __float_as_uint(w);
    hi = (unsigned short)(u >> 16);
    float l = w - __uint_as_float(u & 0xFFFF0000u);
    lo = __bfloat16_as_ushort(__float2bfloat16(l));
}
// split float4 -> hi-pair / lo-pair words
__device__ __forceinline__ void split4(float4 v, uint2& hi, uint2& lo) {
    uint32_t u0 = __float_as_uint(v.x), u1 = __float_as_uint(v.y);
    uint32_t u2 = __float_as_uint(v.z), u3 = __float_as_uint(v.w);
    hi.x = (u0 >> 16) | (u1 & 0xFFFF0000u);
    hi.y = (u2 >> 16) | (u3 & 0xFFFF0000u);
    float l0 = v.x - __uint_as_float(u0 & 0xFFFF0000u);
    float l1 = v.y - __uint_as_float(u1 & 0xFFFF0000u);
    float l2 = v.z - __uint_as_float(u2 & 0xFFFF0000u);
    float l3 = v.w - __uint_as_float(u3 & 0xFFFF0000u);
    __nv_bfloat162 p01 = __floats2bfloat162_rn(l0, l1);
    __nv_bfloat162 p23 = __floats2bfloat162_rn(l2, l3);
    lo.x = *(uint32_t*)&p01;
    lo.y = *(uint32_t*)&p23;
}

// ---------------------------------------------------------------------------
// Merged prep: all weight splits + zero msgupB k-padding.
// grid covers max task = Bb*64*12 = 38400 items.
// ---------------------------------------------------------------------------
__global__ void k_prep_all(const float* __restrict__ W_ma,
                           const float* __restrict__ W_ua,
                           const float* __restrict__ W_uu,
                           const float* __restrict__ W_c,
                           const float* __restrict__ W_mu) {
    int i = blockIdx.x * 256 + threadIdx.x;
    unsigned short h, l;
    if (i < 128 * 64) {
        int k = i >> 6, n = i & 63;
        split_hl(W_ma[k * 64 + n], h, l);
        if (k < 64) {
            g_Wn[0 * 4096 + n * 64 + k] = h;
            g_Wn[1 * 4096 + n * 64 + k] = l;
        } else {
            g_Wbhi[n * 64 + (k - 64)] = h;
            g_Wblo[n * 64 + (k - 64)] = l;
        }
    }
    if (i < 4096) {
        int k = i >> 6, n = i & 63;
        split_hl(W_ua[k * 64 + n], h, l);
        g_Wf[0 * 4096 + n * 64 + k] = h;
        g_Wf[1 * 4096 + n * 64 + k] = l;
        split_hl(W_uu[k * 64 + n], h, l);
        g_Wf[2 * 4096 + n * 64 + k] = h;
        g_Wf[3 * 4096 + n * 64 + k] = l;
        split_hl(W_c[k * 64 + n], h, l);
        g_Wf[4 * 4096 + n * 64 + k] = h;
        g_Wf[5 * 4096 + n * 64 + k] = l;
        split_hl(W_c[(64 + k) * 64 + n], h, l);
        g_Wf[6 * 4096 + n * 64 + k] = h;
        g_Wf[7 * 4096 + n * 64 + k] = l;
        split_hl(W_mu[k * 64 + n], h, l);
        g_Wmu[0 * 4096 + n * 64 + k] = h;
        g_Wmu[1 * 4096 + n * 64 + k] = l;
    }
    if (i < Bb * 64 * 12) {
        int b = i / (64 * 12);
        int rem = i % (64 * 12);
        int n = rem / 12;
        int c = 100 + rem % 12;
        size_t idx = ((size_t)b * 64 + n) * 112 + c;
        g_msgupBh[idx] = 0;
        g_msgupBl[idx] = 0;
    }
}

// ---------------------------------------------------------------------------
// Fat kernel 1: blocks [0, NODE_BLKS) = node_pre path
//   g_xa = x @ W_ma[0:64] + b_ma ; g_acc = (1+eps1)*x
// blocks [NODE_BLKS, NODE_BLKS+MLP_BLKS) = mlp path
//   msgup = relu(attr1 @ W_mu + b_mu) -> split hi/lo -> g_msgupB (n-major)
// Both paths use identical smem layout (55552 B) and fragment template.
// ---------------------------------------------------------------------------
#define NODE_BLKS 391
#define MLP_BLKS  40
#define NP_HI 0
#define NP_LO 18432
#define NP_B  36864
#define NP_BIAS 55296
#define SM_NP_TOT 55552

__global__ __launch_bounds__(256) void k_pre_fused(
    const float* __restrict__ x, const float* __restrict__ eps1,
    const float* __restrict__ b_ma,
    const float* __restrict__ attr1, const float* __restrict__ b_mu)
{
    extern __shared__ char smc[];
    const uint32_t sbase = smem_u32(smc);
    float* bias = (float*)(smc + NP_BIAS);
    const int t = threadIdx.x;
    const int w = t >> 5;
    const int lane = t & 31;

    const bool is_node = (blockIdx.x < NODE_BLKS);

    const int arow = 16 * w + (lane & 15);
    const int acolB = ((lane >> 4) * 8) * 2;
    const int bl = lane & 15;
    const int brow = bl & 7;
    const int bkB = ((bl >> 3) * 8) * 2;
    const int grp = lane >> 2, tig = lane & 3;
    const int myrow = 16 * w + grp;

    if (is_node) {
        const int row0 = blockIdx.x * 128;
        {
            const uint4* srcW = (const uint4*)g_Wn;
#pragma unroll
            for (int i = t; i < 1024; i += 256) {
                int tile = i >> 9;
                int j = i & 511;
                int r = j >> 3, c = j & 7;
                *(uint4*)(smc + NP_B + tile * 9216 + r * 144 + c * 16) = srcW[i];
            }
        }
        if (t < 64) bias[t] = b_ma[t];
        const float e1 = 1.0f + eps1[0];

#pragma unroll
        for (int i = t; i < 2048; i += 256) {
            int r = i >> 4, q = i & 15;
            int gr0 = row0 + r;
            int gr = min(gr0, Nn - 1);
            float4 v = *(const float4*)(x + (size_t)gr * 64 + q * 4);
            if (gr0 < Nn) {
                float4 av = make_float4(e1 * v.x, e1 * v.y, e1 * v.z, e1 * v.w);
                *(float4*)(g_acc + (size_t)gr0 * 64 + q * 4) = av;
            }
            uint2 hi, lo;
            split4(v, hi, lo);
            *(uint2*)(smc + NP_HI + r * 144 + q * 8) = hi;
            *(uint2*)(smc + NP_LO + r * 144 + q * 8) = lo;
        }
        __syncthreads();

        uint32_t ah[4][4], al[4][4];
#pragma unroll
        for (int kt = 0; kt < 4; kt++) {
            uint32_t off = (uint32_t)(arow * 144 + kt * 32 + acolB);
            ldsm_x4(ah[kt], sbase + NP_HI + off);
            ldsm_x4(al[kt], sbase + NP_LO + off);
        }

#pragma unroll
        for (int nt = 0; nt < 8; nt++) {
            uint32_t bh[4][2], blv[4][2];
#pragma unroll
            for (int kt = 0; kt < 4; kt++) {
                uint32_t ba = (uint32_t)((nt * 8 + brow) * 144 + kt * 32 + bkB);
                ldsm_x2(bh[kt],  sbase + NP_B + 0 * 9216 + ba);
                ldsm_x2(blv[kt], sbase + NP_B + 1 * 9216 + ba);
            }
            float c[4] = {0.f, 0.f, 0.f, 0.f};
#pragma unroll
            for (int kt = 0; kt < 4; kt++) {
                mma_bf16(c, ah[kt], bh[kt]);
                mma_bf16(c, ah[kt], blv[kt]);
                mma_bf16(c, al[kt], bh[kt]);
            }
            int col = nt * 8 + 2 * tig;
            int gr1 = row0 + myrow;
            int gr2 = gr1 + 8;
            if (gr1 < Nn)
                *(float2*)(g_xa + (size_t)gr1 * 64 + col) =
                    make_float2(c[0] + bias[col], c[1] + bias[col + 1]);
            if (gr2 < Nn)
                *(float2*)(g_xa + (size_t)gr2 * 64 + col) =
                    make_float2(c[2] + bias[col], c[3] + bias[col + 1]);
        }
    } else {
        const int row0 = (blockIdx.x - NODE_BLKS) * 128;
        const int M = Bb * Cc;   // 5000
        {
            const uint4* srcW = (const uint4*)g_Wmu;
#pragma unroll
            for (int i = t; i < 1024; i += 256) {
                int tile = i >> 9;
                int j = i & 511;
                int r = j >> 3, c = j & 7;
                *(uint4*)(smc + NP_B + tile * 9216 + r * 144 + c * 16) = srcW[i];
            }
        }
        if (t < 64) bias[t] = b_mu[t];

#pragma unroll
        for (int i = t; i < 2048; i += 256) {
            int r = i >> 4, q = i & 15;
            int m = min(row0 + r, M - 1);
            float4 v = *(const float4*)(attr1 + (size_t)m * 64 + q * 4);
            uint2 hi, lo;
            split4(v, hi, lo);
            *(uint2*)(smc + NP_HI + r * 144 + q * 8) = hi;
            *(uint2*)(smc + NP_LO + r * 144 + q * 8) = lo;
        }
        __syncthreads();

        uint32_t ah[4][4], al[4][4];
#pragma unroll
        for (int kt = 0; kt < 4; kt++) {
            uint32_t off = (uint32_t)(arow * 144 + kt * 32 + acolB);
            ldsm_x4(ah[kt], sbase + NP_HI + off);
            ldsm_x4(al[kt], sbase + NP_LO + off);
        }

#pragma unroll
        for (int nt = 0; nt < 8; nt++) {
            uint32_t bh[4][2], blv[4][2];
#pragma unroll
            for (int kt = 0; kt < 4; kt++) {
                uint32_t ba = (uint32_t)((nt * 8 + brow) * 144 + kt * 32 + bkB);
                ldsm_x2(bh[kt],  sbase + NP_B + 0 * 9216 + ba);
                ldsm_x2(blv[kt], sbase + NP_B + 1 * 9216 + ba);
            }
            float c[4] = {0.f, 0.f, 0.f, 0.f};
#pragma unroll
            for (int kt = 0; kt < 4; kt++) {
                mma_bf16(c, ah[kt], bh[kt]);
                mma_bf16(c, ah[kt], blv[kt]);
                mma_bf16(c, al[kt], bh[kt]);
            }
            int col = nt * 8 + 2 * tig;
            // rows m1, m2 of msgup [5000, 64]; write split n-major padded
            int m1 = row0 + myrow;
            int m2 = m1 + 8;
            if (m1 < M) {
                int b = m1 / Cc, cc = m1 % Cc;
                unsigned short h, l;
                split_hl(fmaxf(c[0] + bias[col], 0.f), h, l);
                size_t i0 = ((size_t)b * 64 + col) * 112 + cc;
                g_msgupBh[i0] = h; g_msgupBl[i0] = l;
                split_hl(fmaxf(c[1] + bias[col + 1], 0.f), h, l);
                size_t i1 = ((size_t)b * 64 + col + 1) * 112 + cc;
                g_msgupBh[i1] = h; g_msgupBl[i1] = l;
            }
            if (m2 < M) {
                int b = m2 / Cc, cc = m2 % Cc;
                unsigned short h, l;
                split_hl(fmaxf(c[2] + bias[col], 0.f), h, l);
                size_t i0 = ((size_t)b * 64 + col) * 112 + cc;
                g_msgupBh[i0] = h; g_msgupBl[i0] = l;
                split_hl(fmaxf(c[3] + bias[col + 1], 0.f), h, l);
                size_t i1 = ((size_t)b * 64 + col + 1) * 112 + cc;
                g_msgupBh[i1] = h; g_msgupBl[i1] = l;
            }
        }
    }
}

// ---------------------------------------------------------------------------
// Kernel 3 (HMMA): g_up[b,n,:] = sum_c nc1[b,n,c] * msgup[b,c,:]
// K = 100 padded to 112 (7 k-tiles). A rows stride 240B. grid (8, 50).
// ---------------------------------------------------------------------------
#define UP_AHI 0
#define UP_ALO 30720
#define UP_BHI 61440
#define UP_BLO 76800
#define SM_UPG_TOT 92160

__global__ __launch_bounds__(256) void k_upagg_hmma(const float* __restrict__ nc1)
{
    extern __shared__ char smc[];
    const uint32_t sbase = smem_u32(smc);
    const int t = threadIdx.x;
    const int w = t >> 5;
    const int lane = t & 31;
    const int b = blockIdx.y;
    const int row0 = blockIdx.x * 128;

    // B: 64 rows x 112 bf16 (224B) at stride 240
#pragma unroll
    for (int i = t; i < 896; i += 256) {
        int r = i / 14, c = i % 14;
        size_t src = ((size_t)b * 64 + r) * 112 + c * 8;
        *(uint4*)(smc + UP_BHI + r * 240 + c * 16) = *(const uint4*)(g_msgupBh + src);
        *(uint4*)(smc + UP_BLO + r * 240 + c * 16) = *(const uint4*)(g_msgupBl + src);
    }

    // A: 128 rows x 100 f32 -> split, k 0..99
#pragma unroll
    for (int i = t; i < 3200; i += 256) {
        int r = i / 25, j = i % 25;
        int gr = min(row0 + r, NMAXx - 1);
        float4 v = *(const float4*)(nc1 + ((size_t)b * NMAXx + gr) * Cc + j * 4);
        uint2 hi, lo;
        split4(v, hi, lo);
        *(uint2*)(smc + UP_AHI + r * 240 + j * 8) = hi;
        *(uint2*)(smc + UP_ALO + r * 240 + j * 8) = lo;
    }
    // zero pad k 100..111 (bytes 200..224)
#pragma unroll
    for (int i = t; i < 384; i += 256) {
        int r = i / 3, j = i % 3;
        *(uint2*)(smc + UP_AHI + r * 240 + 200 + j * 8) = make_uint2(0u, 0u);
        *(uint2*)(smc + UP_ALO + r * 240 + 200 + j * 8) = make_uint2(0u, 0u);
    }
    __syncthreads();

    const int arow = 16 * w + (lane & 15);
    const int acolB = ((lane >> 4) * 8) * 2;
    const int bl = lane & 15;
    const int brow = bl & 7;
    const int bkB = ((bl >> 3) * 8) * 2;
    const int grp = lane >> 2, tig = lane & 3;
    const int myrow = 16 * w + grp;

    uint32_t ah[7][4], al[7][4];
#pragma unroll
    for (int kt = 0; kt < 7; kt++) {
        uint32_t off = (uint32_t)(arow * 240 + kt * 32 + acolB);
        ldsm_x4(ah[kt], sbase + UP_AHI + off);
        ldsm_x4(al[kt], sbase + UP_ALO + off);
    }

#pragma unroll
    for (int nt = 0; nt < 8; nt++) {
        float c[4] = {0.f, 0.f, 0.f, 0.f};
#pragma unroll
        for (int kt = 0; kt < 7; kt++) {
            uint32_t ba = (uint32_t)((nt * 8 + brow) * 240 + kt * 32 + bkB);
            uint32_t bh[2], blv[2];
            ldsm_x2(bh,  sbase + UP_BHI + ba);
            ldsm_x2(blv, sbase + UP_BLO + ba);
            mma_bf16(c, ah[kt], bh);
            mma_bf16(c, ah[kt], blv);
            mma_bf16(c, al[kt], bh);
        }
        int col = nt * 8 + 2 * tig;
        int gr1 = row0 + myrow;
        int gr2 = gr1 + 8;
        if (gr1 < NMAXx)
            *(float2*)(g_up + ((size_t)b * NMAXx + gr1) * 64 + col) =
                make_float2(c[0], c[1]);
        if (gr2 < NMAXx)
            *(float2*)(g_up + ((size_t)b * NMAXx + gr2) * 64 + col) =
                make_float2(c[2], c[3]);
    }
}

// ---------------------------------------------------------------------------
// Kernel 4: split-bf16 HMMA edge kernel + red.v4 scatter (unchanged).
// ---------------------------------------------------------------------------
#define SMA_HI 0
#define SMA_LO 18432
#define SMB_HI 36864
#define SMB_LO 46080
#define SM_EDGE_TOT 55296

__global__ __launch_bounds__(256) void k_edge_hmma(
    const float* __restrict__ e, const int* __restrict__ ei)
{
    extern __shared__ char smc[];
    const uint32_t sbase = smem_u32(smc);
    const int t = threadIdx.x;
    const int w = t >> 5;
    const int lane = t & 31;
    const int e0 = blockIdx.x * 128;

    {
        const uint4* srcH = (const uint4*)g_Wbhi;
        const uint4* srcL = (const uint4*)g_Wblo;
#pragma unroll
        for (int i = t; i < 512; i += 256) {
            int r = i >> 3, c = i & 7;
            *(uint4*)(smc + SMB_HI + r * 144 + c * 16) = srcH[i];
            *(uint4*)(smc + SMB_LO + r * 144 + c * 16) = srcL[i];
        }
    }

#pragma unroll
    for (int i = t; i < 2048; i += 256) {
        int r = i >> 4, q = i & 15;
        float4 v = *(const float4*)(e + (size_t)(e0 + r) * 64 + q * 4);
        uint2 hi, lo;
        split4(v, hi, lo);
        *(uint2*)(smc + SMA_HI + r * 144 + q * 8) = hi;
        *(uint2*)(smc + SMA_LO + r * 144 + q * 8) = lo;
    }
    __syncthreads();

    uint32_t ah[4][4], al[4][4];
    {
        int arow = 16 * w + (lane & 15);
        int acolB = ((lane >> 4) * 8) * 2;
#pragma unroll
        for (int kt = 0; kt < 4; kt++) {
            uint32_t off = (uint32_t)(arow * 144 + kt * 32 + acolB);
            ldsm_x4(ah[kt], sbase + SMA_HI + off);
            ldsm_x4(al[kt], sbase + SMA_LO + off);
        }
    }
    __syncthreads();

    float* cst = (float*)smc;   // Cstage [128][68]

    const int bl = lane & 15;
    const int brow = bl & 7;
    const int bkB = ((bl >> 3) * 8) * 2;
    const int grp = lane >> 2, tig = lane & 3;

#pragma unroll
    for (int nt = 0; nt < 8; nt++) {
        uint32_t bh[4][2], blo[4][2];
#pragma unroll
        for (int kt = 0; kt < 4; kt++) {
            uint32_t ba = (uint32_t)((nt * 8 + brow) * 144 + kt * 32 + bkB);
            ldsm_x2(bh[kt], sbase + SMB_HI + ba);
            ldsm_x2(blo[kt], sbase + SMB_LO + ba);
        }
        float c[4] = {0.f, 0.f, 0.f, 0.f};
#pragma unroll
        for (int kt = 0; kt < 4; kt++) {
            mma_bf16(c, ah[kt], bh[kt]);
            mma_bf16(c, ah[kt], blo[kt]);
            mma_bf16(c, al[kt], bh[kt]);
        }
        int row = 16 * w + grp;
        int col = nt * 8 + 2 * tig;
        *(float2*)(cst + row * 68 + col)       = make_float2(c[0], c[1]);
        *(float2*)(cst + (row + 8) * 68 + col) = make_float2(c[2], c[3]);
    }
    __syncthreads();

    {
        const int r0 = (t / 16) * 8, c0 = (t % 16) * 4;
        const int* __restrict__ srcp = ei;
        const int* __restrict__ dstp = ei + Ee;
#pragma unroll
        for (int i = 0; i < 8; i++) {
            int er = e0 + r0 + i;
            int s = srcp[er];
            int d = dstp[er];
            float4 xa = *(const float4*)(g_xa + (size_t)s * 64 + c0);
            float4 cw = *(const float4*)(cst + (r0 + i) * 68 + c0);
            float m0 = fmaxf(cw.x + xa.x, 0.f);
            float m1 = fmaxf(cw.y + xa.y, 0.f);
            float m2 = fmaxf(cw.z + xa.z, 0.f);
            float m3 = fmaxf(cw.w + xa.w, 0.f);
            red_add_v4(g_acc + (size_t)d * 64 + c0, m0, m1, m2, m3);
        }
    }
}

// ---------------------------------------------------------------------------
// Kernel 5: HMMA fused tail (unchanged).
// ---------------------------------------------------------------------------
#define FA_HI 0
#define FA_LO 18432
#define FB_BASE 36864
#define FBIAS 110592
#define SM_FIN_TOT 111360

__global__ __launch_bounds__(256) void k_final_hmma(
    const float* __restrict__ x, const int* __restrict__ x_idx,
    const float* __restrict__ eps2,
    const float* __restrict__ b_ua, const float* __restrict__ b_uu,
    const float* __restrict__ b_c, float* __restrict__ out)
{
    extern __shared__ char smc[];
    const uint32_t sbase = smem_u32(smc);
    float* bias = (float*)(smc + FBIAS);
    const int t = threadIdx.x;
    const int w = t >> 5;
    const int lane = t & 31;
    const int row0 = blockIdx.x * 128;
    const float e2v = 1.0f + eps2[0];

    {
        const uint4* srcW = (const uint4*)g_Wf;
#pragma unroll
        for (int i = t; i < 4096; i += 256) {
            int tile = i >> 9;
            int j = i & 511;
            int r = j >> 3, c = j & 7;
            *(uint4*)(smc + FB_BASE + tile * 9216 + r * 144 + c * 16) = srcW[i];
        }
    }
    if (t < 64) {
        bias[t] = b_ua[t];
        bias[64 + t] = b_uu[t];
        bias[128 + t] = b_c[t];
    }

#pragma unroll
    for (int i = t; i < 2048; i += 256) {
        int r = i >> 4, q = i & 15;
        int gr = min(row0 + r, Nn - 1);
        float4 v = *(const float4*)(g_acc + (size_t)gr * 64 + q * 4);
        uint2 hi, lo;
        split4(v, hi, lo);
        *(uint2*)(smc + FA_HI + r * 144 + q * 8) = hi;
        *(uint2*)(smc + FA_LO + r * 144 + q * 8) = lo;
    }
    __syncthreads();

    const int arow = 16 * w + (lane & 15);
    const int acolB = ((lane >> 4) * 8) * 2;
    const int bl = lane & 15;
    const int brow = bl & 7;
    const int bkB = ((bl >> 3) * 8) * 2;
    const int grp = lane >> 2, tig = lane & 3;
    const int myrow = 16 * w + grp;

    uint32_t a1h[4][4], a1l[4][4];
#pragma unroll
    for (int kt = 0; kt < 4; kt++) {
        uint32_t off = (uint32_t)(arow * 144 + kt * 32 + acolB);
        ldsm_x4(a1h[kt], sbase + FA_HI + off);
        ldsm_x4(a1l[kt], sbase + FA_LO + off);
    }
    __syncthreads();

#pragma unroll
    for (int i = t; i < 2048; i += 256) {
        int r = i >> 4, q = i & 15;
        int gr = min(row0 + r, Nn - 1);
        int xi = x_idx[gr];
        float4 u = *(const float4*)(g_up + (size_t)xi * 64 + q * 4);
        float4 xv = *(const float4*)(x + (size_t)gr * 64 + q * 4);
        float4 v = make_float4(u.x + e2v * xv.x, u.y + e2v * xv.y,
                               u.z + e2v * xv.z, u.w + e2v * xv.w);
        uint2 hi, lo;
        split4(v, hi, lo);
        *(uint2*)(smc + FA_HI + r * 144 + q * 8) = hi;
        *(uint2*)(smc + FA_LO + r * 144 + q * 8) = lo;
    }
    __syncthreads();

    uint32_t a2h[4][4], a2l[4][4];
#pragma unroll
    for (int kt = 0; kt < 4; kt++) {
        uint32_t off = (uint32_t)(arow * 144 + kt * 32 + acolB);
        ldsm_x4(a2h[kt], sbase + FA_HI + off);
        ldsm_x4(a2l[kt], sbase + FA_LO + off);
    }
    __syncthreads();

    // Phase 1a: h1 = relu(A1@Wua + bua) -> split -> FA
#pragma unroll
    for (int nt = 0; nt < 8; nt++) {
        uint32_t bh[4][2], blv[4][2];
#pragma unroll
        for (int kt = 0; kt < 4; kt++) {
            uint32_t ba = (uint32_t)((nt * 8 + brow) * 144 + kt * 32 + bkB);
            ldsm_x2(bh[kt],  sbase + FB_BASE + 0 * 9216 + ba);
            ldsm_x2(blv[kt], sbase + FB_BASE + 1 * 9216 + ba);
        }
        float c[4] = {0.f, 0.f, 0.f, 0.f};
#pragma unroll
        for (int kt = 0; kt < 4; kt++) {
            mma_bf16(c, a1h[kt], bh[kt]);
            mma_bf16(c, a1h[kt], blv[kt]);
            mma_bf16(c, a1l[kt], bh[kt]);
        }
        int col = nt * 8 + 2 * tig;
        float h0 = fmaxf(c[0] + bias[col], 0.f);
        float h1v = fmaxf(c[1] + bias[col + 1], 0.f);
        float h2v = fmaxf(c[2] + bias[col], 0.f);
        float h3v = fmaxf(c[3] + bias[col + 1], 0.f);
        uint2 hiA, loA;
        split4(make_float4(h0, h1v, h2v, h3v), hiA, loA);
        *(uint32_t*)(smc + FA_HI + myrow * 144 + col * 2) = hiA.x;
        *(uint32_t*)(smc + FA_LO + myrow * 144 + col * 2) = loA.x;
        *(uint32_t*)(smc + FA_HI + (myrow + 8) * 144 + col * 2) = hiA.y;
        *(uint32_t*)(smc + FA_LO + (myrow + 8) * 144 + col * 2) = loA.y;
    }
    __syncthreads();

#pragma unroll
    for (int kt = 0; kt < 4; kt++) {
        uint32_t off = (uint32_t)(arow * 144 + kt * 32 + acolB);
        ldsm_x4(a1h[kt], sbase + FA_HI + off);
        ldsm_x4(a1l[kt], sbase + FA_LO + off);
    }
    __syncthreads();

    // Phase 1b: h2 = relu(A2@Wuu + buu) -> split -> FA
#pragma unroll
    for (int nt = 0; nt < 8; nt++) {
        uint32_t bh[4][2], blv[4][2];
#pragma unroll
        for (int kt = 0; kt < 4; kt++) {
            uint32_t ba = (uint32_t)((nt * 8 + brow) * 144 + kt * 32 + bkB);
            ldsm_x2(bh[kt],  sbase + FB_BASE + 2 * 9216 + ba);
            ldsm_x2(blv[kt], sbase + FB_BASE + 3 * 9216 + ba);
        }
        float c[4] = {0.f, 0.f, 0.f, 0.f};
#pragma unroll
        for (int kt = 0; kt < 4; kt++) {
            mma_bf16(c, a2h[kt], bh[kt]);
            mma_bf16(c, a2h[kt], blv[kt]);
            mma_bf16(c, a2l[kt], bh[kt]);
        }
        int col = nt * 8 + 2 * tig;
        float h0 = fmaxf(c[0] + bias[64 + col], 0.f);
        float h1v = fmaxf(c[1] + bias[64 + col + 1], 0.f);
        float h2v = fmaxf(c[2] + bias[64 + col], 0.f);
        float h3v = fmaxf(c[3] + bias[64 + col + 1], 0.f);
        uint2 hiA, loA;
        split4(make_float4(h0, h1v, h2v, h3v), hiA, loA);
        *(uint32_t*)(smc + FA_HI + myrow * 144 + col * 2) = hiA.x;
        *(uint32_t*)(smc + FA_LO + myrow * 144 + col * 2) = loA.x;
        *(uint32_t*)(smc + FA_HI + (myrow + 8) * 144 + col * 2) = hiA.y;
        *(uint32_t*)(smc + FA_LO + (myrow + 8) * 144 + col * 2) = loA.y;
    }
    __syncthreads();

#pragma unroll
    for (int kt = 0; kt < 4; kt++) {
        uint32_t off = (uint32_t)(arow * 144 + kt * 32 + acolB);
        ldsm_x4(a2h[kt], sbase + FA_HI + off);
        ldsm_x4(a2l[kt], sbase + FA_LO + off);
    }

    // Phase 2: out = h1@Wc1 + h2@Wc2 + bc
#pragma unroll
    for (int nt = 0; nt < 8; nt++) {
        uint32_t b1h[4][2], b1l[4][2], b2h[4][2], b2l[4][2];
#pragma unroll
        for (int kt = 0; kt < 4; kt++) {
            uint32_t ba = (uint32_t)((nt * 8 + brow) * 144 + kt * 32 + bkB);
            ldsm_x2(b1h[kt], sbase + FB_BASE + 4 * 9216 + ba);
            ldsm_x2(b1l[kt], sbase + FB_BASE + 5 * 9216 + ba);
            ldsm_x2(b2h[kt], sbase + FB_BASE + 6 * 9216 + ba);
            ldsm_x2(b2l[kt], sbase + FB_BASE + 7 * 9216 + ba);
        }
        float c[4] = {0.f, 0.f, 0.f, 0.f};
#pragma unroll
        for (int kt = 0; kt < 4; kt++) {
            mma_bf16(c, a1h[kt], b1h[kt]);
            mma_bf16(c, a1h[kt], b1l[kt]);
            mma_bf16(c, a1l[kt], b1h[kt]);
            mma_bf16(c, a2h[kt], b2h[kt]);
            mma_bf16(c, a2h[kt], b2l[kt]);
            mma_bf16(c, a2l[kt], b2h[kt]);
        }
        int col = nt * 8 + 2 * tig;
        int gr1 = row0 + myrow;
        int gr2 = gr1 + 8;
        if (gr1 < Nn)
            *(float2*)(out + (size_t)gr1 * 64 + col) =
                make_float2(c[0] + bias[128 + col], c[1] + bias[128 + col + 1]);
        if (gr2 < Nn)
            *(float2*)(out + (size_t)gr2 * 64 + col) =
                make_float2(c[2] + bias[128 + col], c[3] + bias[128 + col + 1]);
    }
}

// ---------------------------------------------------------------------------
extern "C" void kernel_launch(void* const* d_in, const int* in_sizes, int n_in,
                              void* d_out, int out_size)
{
    const float* x     = (const float*)d_in[0];
    const float* e     = (const float*)d_in[1];
    const int*   ei    = (const int*)d_in[2];
    const float* attr1 = (const float*)d_in[3];
    const float* nc1   = (const float*)d_in[4];
    const int*   x_idx = (const int*)d_in[5];
    const float* eps1  = (const float*)d_in[6];
    const float* eps2  = (const float*)d_in[7];
    const float* W_ma  = (const float*)d_in[8];
    const float* b_ma  = (const float*)d_in[9];
    const float* W_mu  = (const float*)d_in[10];
    const float* b_mu  = (const float*)d_in[11];
    const float* W_ua  = (const float*)d_in[12];
    const float* b_ua  = (const float*)d_in[13];
    const float* W_uu  = (const float*)d_in[14];
    const float* b_uu  = (const float*)d_in[15];
    const float* W_c   = (const float*)d_in[16];
    const float* b_c   = (const float*)d_in[17];
    float* out = (float*)d_out;

    cudaFuncSetAttribute(k_pre_fused,  cudaFuncAttributeMaxDynamicSharedMemorySize, SM_NP_TOT);
    cudaFuncSetAttribute(k_upagg_hmma, cudaFuncAttributeMaxDynamicSharedMemorySize, SM_UPG_TOT);
    cudaFuncSetAttribute(k_edge_hmma,  cudaFuncAttributeMaxDynamicSharedMemorySize, SM_EDGE_TOT);
    cudaFuncSetAttribute(k_final_hmma, cudaFuncAttributeMaxDynamicSharedMemorySize, SM_FIN_TOT);

    // merged weight prep (+ msgupB padding zeros)
    k_prep_all<<<(Bb * 64 * 12 + 255) / 256, 256>>>(W_ma, W_ua, W_uu, W_c, W_mu);

    // fat kernel: node_pre (blocks 0..390) + mlp->split (blocks 391..430)
    k_pre_fused<<<NODE_BLKS + MLP_BLKS, 256, SM_NP_TOT>>>(x, eps1, b_ma,
                                                          attr1, b_mu);

    // cluster aggregation (HMMA)
    k_upagg_hmma<<<dim3(8, Bb), 256, SM_UPG_TOT>>>(nc1);

    // edge kernel (HMMA + red.v4)
    k_edge_hmma<<<Ee / 128, 256, SM_EDGE_TOT>>>(e, ei);

    // fused tail (HMMA)
    k_final_hmma<<<(Nn + 127) / 128, 256, SM_FIN_TOT>>>(x, x_idx, eps2,
                                                        b_ua, b_uu, b_c, out);
}